// round 1
// baseline (speedup 1.0000x reference)
#include <cuda_runtime.h>
#include <cuda_bf16.h>
#include <math.h>

// ---------------- problem constants ----------------
#define BATCH 4
#define PP    196
#define FF    8
#define CC    768
#define NN    1569          // 1 + F*P
#define SS    1568          // F*P
#define HH    12
#define DD    64
#define SCALE 0.125f        // d^-0.5

#define M_QKV   (BATCH*NN)          // 6276
#define N_QKV   (3*CC)              // 2304
#define M_S     (BATCH*SS)          // 6272
#define OUT_ELEMS ((size_t)BATCH*NN*CC)   // 4,819,968

// ---------------- scratch ----------------
__device__ float g_qkv[(size_t)M_QKV * N_QKV];        // (B,N,3C)
__device__ float g_xt [(size_t)M_S * FF * CC];        // (B,S,F,C)
__device__ float g_xd [(size_t)M_S * CC];             // x_diag (B,S,C)
__device__ float g_q2 [(size_t)M_S * CC];             // (B,S,C) scaled
__device__ float g_G  [(size_t)M_S * HH * CC];        // (B,S,h,C)
__device__ float g_pre[(size_t)M_QKV * CC];           // pre-proj (B,N,C)

// =============================================================
// Generic SGEMM: C = alpha * A(MxK) @ B(KxN) (+bias), row-major.
// 128x128 tile, BK=8, 256 threads, 8x8 per thread. N%128==0, K%8==0.
// =============================================================
template<bool HAS_BIAS>
__global__ __launch_bounds__(256)
void sgemm128(const float* __restrict__ A, const float* __restrict__ Bm,
              float* __restrict__ Cm, const float* __restrict__ bias,
              int M, int N, int K, int lda, int ldb, int ldc, float alpha)
{
    __shared__ float As[8][128];
    __shared__ float Bs[8][128];

    const int tid = threadIdx.x;
    const int tx  = tid & 15;
    const int ty  = tid >> 4;
    const int m0  = blockIdx.y * 128;
    const int n0  = blockIdx.x * 128;

    const int arow = tid >> 1;          // 0..127
    const int ak   = (tid & 1) * 4;     // 0 or 4
    const int brow = tid >> 5;          // 0..7
    const int bcol = (tid & 31) * 4;

    const bool arow_ok = (m0 + arow) < M;

    float acc[8][8];
#pragma unroll
    for (int i = 0; i < 8; i++)
#pragma unroll
        for (int j = 0; j < 8; j++) acc[i][j] = 0.f;

    for (int k0 = 0; k0 < K; k0 += 8) {
        float4 av = make_float4(0.f,0.f,0.f,0.f);
        if (arow_ok)
            av = *reinterpret_cast<const float4*>(A + (size_t)(m0 + arow) * lda + k0 + ak);
        float4 bv = *reinterpret_cast<const float4*>(Bm + (size_t)(k0 + brow) * ldb + n0 + bcol);

        __syncthreads();
        As[ak + 0][arow] = av.x;
        As[ak + 1][arow] = av.y;
        As[ak + 2][arow] = av.z;
        As[ak + 3][arow] = av.w;
        *reinterpret_cast<float4*>(&Bs[brow][bcol]) = bv;
        __syncthreads();

#pragma unroll
        for (int kk = 0; kk < 8; kk++) {
            float a[8], b[8];
            float4 t;
            t = *reinterpret_cast<const float4*>(&As[kk][ty * 4]);      a[0]=t.x; a[1]=t.y; a[2]=t.z; a[3]=t.w;
            t = *reinterpret_cast<const float4*>(&As[kk][64 + ty * 4]); a[4]=t.x; a[5]=t.y; a[6]=t.z; a[7]=t.w;
            t = *reinterpret_cast<const float4*>(&Bs[kk][tx * 4]);      b[0]=t.x; b[1]=t.y; b[2]=t.z; b[3]=t.w;
            t = *reinterpret_cast<const float4*>(&Bs[kk][64 + tx * 4]); b[4]=t.x; b[5]=t.y; b[6]=t.z; b[7]=t.w;
#pragma unroll
            for (int i = 0; i < 8; i++)
#pragma unroll
                for (int j = 0; j < 8; j++) acc[i][j] += a[i] * b[j];
        }
    }

#pragma unroll
    for (int ih = 0; ih < 2; ih++) {
#pragma unroll
        for (int i = 0; i < 4; i++) {
            int m = m0 + ih * 64 + ty * 4 + i;
            if (m < M) {
                float* crow = Cm + (size_t)m * ldc + n0;
#pragma unroll
                for (int jh = 0; jh < 2; jh++) {
                    float4 r;
                    r.x = acc[ih*4+i][jh*4+0] * alpha;
                    r.y = acc[ih*4+i][jh*4+1] * alpha;
                    r.z = acc[ih*4+i][jh*4+2] * alpha;
                    r.w = acc[ih*4+i][jh*4+3] * alpha;
                    if (HAS_BIAS) {
                        float4 bb = *reinterpret_cast<const float4*>(bias + n0 + jh*64 + tx*4);
                        r.x += bb.x; r.y += bb.y; r.z += bb.z; r.w += bb.w;
                    }
                    *reinterpret_cast<float4*>(crow + jh*64 + tx*4) = r;
                }
            }
        }
    }
}

// =============================================================
// CLS attention: 48 blocks (b,h). Attends over all N tokens.
// =============================================================
__global__ __launch_bounds__(256)
void cls_attn_kernel(const float* __restrict__ qkv, float* __restrict__ preout)
{
    __shared__ float sim[NN];
    __shared__ float qv[DD];
    __shared__ float red[256];
    __shared__ float accred[4 * DD];

    const int b = blockIdx.x / HH;
    const int h = blockIdx.x % HH;
    const int tid = threadIdx.x;

    if (tid < DD)
        qv[tid] = qkv[(size_t)(b * NN) * N_QKV + h * DD + tid] * SCALE;
    __syncthreads();

    for (int n = tid; n < NN; n += 256) {
        const float* kp = qkv + (size_t)(b * NN + n) * N_QKV + CC + h * DD;
        float d = 0.f;
#pragma unroll
        for (int c4 = 0; c4 < DD / 4; c4++) {
            float4 k4 = *reinterpret_cast<const float4*>(kp + c4 * 4);
            d += qv[c4*4+0]*k4.x + qv[c4*4+1]*k4.y + qv[c4*4+2]*k4.z + qv[c4*4+3]*k4.w;
        }
        sim[n] = d;
    }
    __syncthreads();

    float m = -1e30f;
    for (int n = tid; n < NN; n += 256) m = fmaxf(m, sim[n]);
    red[tid] = m; __syncthreads();
    for (int o = 128; o > 0; o >>= 1) { if (tid < o) red[tid] = fmaxf(red[tid], red[tid+o]); __syncthreads(); }
    const float mx = red[0];
    __syncthreads();

    float s = 0.f;
    for (int n = tid; n < NN; n += 256) { float e = __expf(sim[n] - mx); sim[n] = e; s += e; }
    red[tid] = s; __syncthreads();
    for (int o = 128; o > 0; o >>= 1) { if (tid < o) red[tid] += red[tid+o]; __syncthreads(); }
    const float inv = 1.f / red[0];
    __syncthreads();

    const int g = tid >> 6, dd = tid & 63;
    float a = 0.f;
    for (int n = g; n < NN; n += 4)
        a += sim[n] * qkv[(size_t)(b * NN + n) * N_QKV + 2 * CC + h * DD + dd];
    accred[g * DD + dd] = a;
    __syncthreads();
    if (tid < DD)
        preout[(size_t)(b * NN) * CC + h * DD + tid] =
            (accred[tid] + accred[DD + tid] + accred[2*DD + tid] + accred[3*DD + tid]) * inv;
}

// =============================================================
// Space attention: block = (qtile 0..24, f 0..7, bh 0..47).
// Q tile 64xD, K/V frame tiles 196xD in smem; softmax over P.
// =============================================================
#define SA_PAD 68
#define SA_SCLD 200
#define SA_SMEM ((2*196*SA_PAD + 64*SA_PAD + 64*SA_SCLD) * 4)

__global__ __launch_bounds__(256)
void space_attn_kernel(const float* __restrict__ qkv, float* __restrict__ xt)
{
    extern __shared__ float sm[];
    float* Ksm = sm;                       // 196 x 68
    float* Vsm = Ksm + 196 * SA_PAD;       // 196 x 68
    float* Qsm = Vsm + 196 * SA_PAD;       // 64 x 68
    float* Sc  = Qsm + 64 * SA_PAD;        // 64 x 200

    const int bh = blockIdx.z;
    const int b = bh / HH, h = bh % HH;
    const int f = blockIdx.y;
    const int q0 = blockIdx.x * 64;
    const int tid = threadIdx.x;

    // load K,V (frame f) : 196 rows x 16 float4
    for (int i = tid; i < 196 * 16; i += 256) {
        int r = i >> 4, c4 = i & 15;
        size_t base = (size_t)(b * NN + 1 + f * PP + r) * N_QKV + h * DD + c4 * 4;
        *reinterpret_cast<float4*>(Ksm + r * SA_PAD + c4 * 4) =
            *reinterpret_cast<const float4*>(qkv + base + CC);
        *reinterpret_cast<float4*>(Vsm + r * SA_PAD + c4 * 4) =
            *reinterpret_cast<const float4*>(qkv + base + 2 * CC);
    }
    // load Q tile
    for (int i = tid; i < 64 * 16; i += 256) {
        int r = i >> 4, c4 = i & 15;
        int sq = q0 + r;
        float4 qv = make_float4(0.f,0.f,0.f,0.f);
        if (sq < SS)
            qv = *reinterpret_cast<const float4*>(qkv + (size_t)(b * NN + 1 + sq) * N_QKV + h * DD + c4 * 4);
        *reinterpret_cast<float4*>(Qsm + r * SA_PAD + c4 * 4) = qv;
    }
    __syncthreads();

    // phase 1: scores. warp w -> q rows 8w..8w+7, lane l -> p = l+32j
    const int w = tid >> 5, l = tid & 31;
    float acc[8][7];
#pragma unroll
    for (int qi = 0; qi < 8; qi++)
#pragma unroll
        for (int j = 0; j < 7; j++) acc[qi][j] = 0.f;

#pragma unroll 4
    for (int k4 = 0; k4 < 16; k4++) {
        float4 kreg[7];
#pragma unroll
        for (int j = 0; j < 7; j++) {
            int p = l + 32 * j;
            kreg[j] = (p < 196) ? *reinterpret_cast<const float4*>(Ksm + p * SA_PAD + 4 * k4)
                                : make_float4(0.f,0.f,0.f,0.f);
        }
#pragma unroll
        for (int qi = 0; qi < 8; qi++) {
            float4 qv = *reinterpret_cast<const float4*>(Qsm + (8 * w + qi) * SA_PAD + 4 * k4);
#pragma unroll
            for (int j = 0; j < 7; j++)
                acc[qi][j] += qv.x*kreg[j].x + qv.y*kreg[j].y + qv.z*kreg[j].z + qv.w*kreg[j].w;
        }
    }

    // softmax over p (196) per q row
#pragma unroll
    for (int qi = 0; qi < 8; qi++) {
        float mx = -1e30f;
#pragma unroll
        for (int j = 0; j < 7; j++) {
            float v = acc[qi][j] * SCALE;
            acc[qi][j] = v;
            if (l + 32 * j < 196) mx = fmaxf(mx, v);
        }
#pragma unroll
        for (int o = 16; o > 0; o >>= 1) mx = fmaxf(mx, __shfl_xor_sync(0xffffffffu, mx, o));
        float sum = 0.f;
#pragma unroll
        for (int j = 0; j < 7; j++) {
            float e = (l + 32 * j < 196) ? __expf(acc[qi][j] - mx) : 0.f;
            acc[qi][j] = e; sum += e;
        }
#pragma unroll
        for (int o = 16; o > 0; o >>= 1) sum += __shfl_xor_sync(0xffffffffu, sum, o);
        float inv = 1.f / sum;
        int q = 8 * w + qi;
#pragma unroll
        for (int j = 0; j < 7; j++) {
            int p = l + 32 * j;
            if (p < 196) Sc[q * SA_SCLD + p] = acc[qi][j] * inv;
        }
    }
    __syncthreads();

    // phase 3: out(64x64) = Sc(64x196) @ V(196x64)
    const int ty = tid >> 4, tx = tid & 15;
    float o2[4][4];
#pragma unroll
    for (int i = 0; i < 4; i++)
#pragma unroll
        for (int j = 0; j < 4; j++) o2[i][j] = 0.f;

#pragma unroll 4
    for (int p = 0; p < 196; p++) {
        float4 vv = *reinterpret_cast<const float4*>(Vsm + p * SA_PAD + 4 * tx);
#pragma unroll
        for (int i = 0; i < 4; i++) {
            float s = Sc[(ty * 4 + i) * SA_SCLD + p];
            o2[i][0] += s * vv.x; o2[i][1] += s * vv.y;
            o2[i][2] += s * vv.z; o2[i][3] += s * vv.w;
        }
    }

#pragma unroll
    for (int i = 0; i < 4; i++) {
        int sq = q0 + ty * 4 + i;
        if (sq < SS) {
            float4 r = make_float4(o2[i][0], o2[i][1], o2[i][2], o2[i][3]);
            *reinterpret_cast<float4*>(xt + ((size_t)(b * SS + sq) * FF + f) * CC + h * DD + 4 * tx) = r;
        }
    }
}

// =============================================================
// Gather x_diag[b,s,:] = xt[b,s,s/P,:]
// =============================================================
__global__ __launch_bounds__(256)
void gather_xdiag_kernel(const float* __restrict__ xt, float* __restrict__ xd)
{
    size_t idx = (size_t)blockIdx.x * 256 + threadIdx.x;     // float4 index
    const size_t total = (size_t)M_S * (CC / 4);
    if (idx < total) {
        size_t m = idx / (CC / 4);
        int c4 = (int)(idx % (CC / 4));
        int s = (int)(m % SS);
        int f = s / PP;
        reinterpret_cast<float4*>(xd)[idx] =
            reinterpret_cast<const float4*>(xt)[(m * FF + f) * (CC / 4) + c4];
    }
}

// =============================================================
// G[b,s,h,c] = sum_dd q2[b,s,h*64+dd] * w_kv[c, h*64+dd]   (NT, K=64)
// grid: (98, 12, 12) = (mtile, ctile, head)
// =============================================================
__global__ __launch_bounds__(256)
void gemm_G_kernel(const float* __restrict__ q2, const float* __restrict__ wkv,
                   float* __restrict__ G)
{
    __shared__ float As[64][68];
    __shared__ float Bs[64][68];
    const int mt = blockIdx.x, ct = blockIdx.y, h = blockIdx.z;
    const int tid = threadIdx.x;

    for (int i = tid; i < 64 * 16; i += 256) {
        int r = i >> 4, c4 = i & 15;
        *reinterpret_cast<float4*>(&As[r][4 * c4]) =
            *reinterpret_cast<const float4*>(q2 + (size_t)(mt * 64 + r) * CC + h * DD + 4 * c4);
        *reinterpret_cast<float4*>(&Bs[r][4 * c4]) =
            *reinterpret_cast<const float4*>(wkv + (size_t)(ct * 64 + r) * (2 * CC) + h * DD + 4 * c4);
    }
    __syncthreads();

    const int tx = tid & 15, ty = tid >> 4;
    float acc[4][4];
#pragma unroll
    for (int i = 0; i < 4; i++)
#pragma unroll
        for (int j = 0; j < 4; j++) acc[i][j] = 0.f;

#pragma unroll 4
    for (int k4 = 0; k4 < 16; k4++) {
        float4 a[4], b[4];
#pragma unroll
        for (int jm = 0; jm < 4; jm++) a[jm] = *reinterpret_cast<const float4*>(&As[ty + 16 * jm][4 * k4]);
#pragma unroll
        for (int jc = 0; jc < 4; jc++) b[jc] = *reinterpret_cast<const float4*>(&Bs[tx + 16 * jc][4 * k4]);
#pragma unroll
        for (int jm = 0; jm < 4; jm++)
#pragma unroll
            for (int jc = 0; jc < 4; jc++)
                acc[jm][jc] += a[jm].x*b[jc].x + a[jm].y*b[jc].y + a[jm].z*b[jc].z + a[jm].w*b[jc].w;
    }

#pragma unroll
    for (int jm = 0; jm < 4; jm++) {
        size_t m = (size_t)mt * 64 + ty + 16 * jm;
#pragma unroll
        for (int jc = 0; jc < 4; jc++)
            G[(m * HH + h) * CC + ct * 64 + tx + 16 * jc] = acc[jm][jc];
    }
}

// =============================================================
// Per (b,s): scores(12x8) = G . xt, softmax over f -> attn2 out,
// out row = sum_f attn2 * xt  -> preout (row 1+s)
// =============================================================
#define SO_SMEM ((FF*CC + HH*CC + 96 + 96) * 4)

__global__ __launch_bounds__(256)
void score_out_kernel(const float* __restrict__ xt, const float* __restrict__ G,
                      float* __restrict__ preout, float* __restrict__ attn2)
{
    extern __shared__ float sm[];
    float* xts = sm;                  // 8 x 768
    float* Gs  = xts + FF * CC;       // 12 x 768
    float* sc  = Gs + HH * CC;        // 96
    float* pr  = sc + 96;             // 96

    const int bs = blockIdx.x;        // 0..6271
    const int b = bs / SS, s = bs % SS;
    const int tid = threadIdx.x;

    for (int i = tid; i < FF * CC / 4; i += 256)
        reinterpret_cast<float4*>(xts)[i] = reinterpret_cast<const float4*>(xt)[(size_t)bs * (FF * CC / 4) + i];
    for (int i = tid; i < HH * CC / 4; i += 256)
        reinterpret_cast<float4*>(Gs)[i] = reinterpret_cast<const float4*>(G)[(size_t)bs * (HH * CC / 4) + i];
    __syncthreads();

    const int w = tid >> 5, l = tid & 31;
    for (int idx = w; idx < 96; idx += 8) {
        int h = idx >> 3, f = idx & 7;
        const float4* gp = reinterpret_cast<const float4*>(Gs + h * CC);
        const float4* xp = reinterpret_cast<const float4*>(xts + f * CC);
        float part = 0.f;
#pragma unroll
        for (int c4 = l; c4 < CC / 4; c4 += 32) {
            float4 g = gp[c4], x = xp[c4];
            part += g.x*x.x + g.y*x.y + g.z*x.z + g.w*x.w;
        }
#pragma unroll
        for (int o = 16; o > 0; o >>= 1) part += __shfl_xor_sync(0xffffffffu, part, o);
        if (l == 0) sc[idx] = part;
    }
    __syncthreads();

    if (tid < HH) {
        int h = tid;
        float mx = -1e30f;
#pragma unroll
        for (int f = 0; f < FF; f++) mx = fmaxf(mx, sc[h * 8 + f]);
        float sum = 0.f;
        float e[FF];
#pragma unroll
        for (int f = 0; f < FF; f++) { e[f] = __expf(sc[h * 8 + f] - mx); sum += e[f]; }
        float inv = 1.f / sum;
#pragma unroll
        for (int f = 0; f < FF; f++) {
            float p = e[f] * inv;
            pr[h * 8 + f] = p;
            attn2[((size_t)(b * HH + h) * SS + s) * FF + f] = p;
        }
    }
    __syncthreads();

    for (int c = tid; c < CC; c += 256) {
        int h = c >> 6;
        float v = 0.f;
#pragma unroll
        for (int f = 0; f < FF; f++) v += pr[h * 8 + f] * xts[f * CC + c];
        preout[(size_t)(b * NN + 1 + s) * CC + c] = v;
    }
}

// =============================================================
// host launch
// =============================================================
extern "C" void kernel_launch(void* const* d_in, const int* in_sizes, int n_in,
                              void* d_out, int out_size)
{
    const float* x      = (const float*)d_in[0];
    const float* w_qkv  = (const float*)d_in[1];
    const float* w_q    = (const float*)d_in[2];
    const float* w_kv   = (const float*)d_in[3];
    const float* w_proj = (const float*)d_in[4];
    const float* b_proj = (const float*)d_in[5];

    float *p_qkv, *p_xt, *p_xd, *p_q2, *p_G, *p_pre;
    cudaGetSymbolAddress((void**)&p_qkv, g_qkv);
    cudaGetSymbolAddress((void**)&p_xt,  g_xt);
    cudaGetSymbolAddress((void**)&p_xd,  g_xd);
    cudaGetSymbolAddress((void**)&p_q2,  g_q2);
    cudaGetSymbolAddress((void**)&p_G,   g_G);
    cudaGetSymbolAddress((void**)&p_pre, g_pre);

    cudaFuncSetAttribute(space_attn_kernel, cudaFuncAttributeMaxDynamicSharedMemorySize, SA_SMEM);
    cudaFuncSetAttribute(score_out_kernel,  cudaFuncAttributeMaxDynamicSharedMemorySize, SO_SMEM);

    float* outp  = (float*)d_out;
    float* attn2 = outp + OUT_ELEMS;

    // 1) qkv = x @ w_qkv
    sgemm128<false><<<dim3(N_QKV/128, (M_QKV+127)/128), 256>>>(
        x, w_qkv, p_qkv, nullptr, M_QKV, N_QKV, CC, CC, N_QKV, N_QKV, 1.f);

    // 2) cls attention -> preout rows n=0
    cls_attn_kernel<<<BATCH*HH, 256>>>(p_qkv, p_pre);

    // 3) fused space attention -> xt (B,S,F,C)
    space_attn_kernel<<<dim3((SS+63)/64, FF, BATCH*HH), 256, SA_SMEM>>>(p_qkv, p_xt);

    // 4) gather x_diag
    {
        size_t total = (size_t)M_S * (CC/4);
        gather_xdiag_kernel<<<(unsigned)((total + 255)/256), 256>>>(p_xt, p_xd);
    }

    // 5) q2 = scale * x_diag @ w_q
    sgemm128<false><<<dim3(CC/128, M_S/128), 256>>>(
        p_xd, w_q, p_q2, nullptr, M_S, CC, CC, CC, CC, CC, SCALE);

    // 6) G[b,s,h,:] = q2_h @ Wk_h^T  (k2 GEMM eliminated algebraically)
    gemm_G_kernel<<<dim3(M_S/64, CC/64, HH), 256>>>(p_q2, w_kv, p_G);

    // 7) scores + softmax(F) -> attn2 output; weighted xt -> preout rows 1+s
    score_out_kernel<<<M_S, 256, SO_SMEM>>>(p_xt, p_G, p_pre, attn2);

    // 8) out = preout @ w_proj + b_proj
    sgemm128<true><<<dim3(CC/128, (M_QKV+127)/128), 256>>>(
        p_pre, w_proj, outp, b_proj, M_QKV, CC, CC, CC, CC, CC, 1.f);
}

// round 2
// speedup vs baseline: 1.0004x; 1.0004x over previous
#include <cuda_runtime.h>
#include <cuda_bf16.h>
#include <math.h>

// ---------------- problem constants ----------------
#define BATCH 4
#define PP    196
#define FF    8
#define CC    768
#define NN    1569          // 1 + F*P
#define SS    1568          // F*P
#define HH    12
#define DD    64
#define SCALE 0.125f        // d^-0.5

#define M_QKV   (BATCH*NN)          // 6276
#define N_QKV   (3*CC)              // 2304
#define M_S     (BATCH*SS)          // 6272
#define OUT_ELEMS ((size_t)BATCH*NN*CC)   // 4,819,968

// ---------------- scratch ----------------
__device__ float g_qkv[(size_t)M_QKV * N_QKV];        // (B,N,3C)
__device__ float g_xt [(size_t)M_S * FF * CC];        // (B,S,F,C)
__device__ float g_xd [(size_t)M_S * CC];             // x_diag (B,S,C)
__device__ float g_q2 [(size_t)M_S * CC];             // (B,S,C) scaled
__device__ float g_G  [(size_t)M_S * HH * CC];        // (B,S,h,C)
__device__ float g_pre[(size_t)M_QKV * CC];           // pre-proj (B,N,C)

// =============================================================
// Generic SGEMM: C = alpha * A(MxK) @ B(KxN) (+bias), row-major.
// 128x128 tile, BK=8, 256 threads, 8x8 per thread. N%128==0, K%8==0.
// =============================================================
template<bool HAS_BIAS>
__global__ __launch_bounds__(256)
void sgemm128(const float* __restrict__ A, const float* __restrict__ Bm,
              float* __restrict__ Cm, const float* __restrict__ bias,
              int M, int N, int K, int lda, int ldb, int ldc, float alpha)
{
    __shared__ float As[8][128];
    __shared__ float Bs[8][128];

    const int tid = threadIdx.x;
    const int tx  = tid & 15;
    const int ty  = tid >> 4;
    const int m0  = blockIdx.y * 128;
    const int n0  = blockIdx.x * 128;

    const int arow = tid >> 1;          // 0..127
    const int ak   = (tid & 1) * 4;     // 0 or 4
    const int brow = tid >> 5;          // 0..7
    const int bcol = (tid & 31) * 4;

    const bool arow_ok = (m0 + arow) < M;

    float acc[8][8];
#pragma unroll
    for (int i = 0; i < 8; i++)
#pragma unroll
        for (int j = 0; j < 8; j++) acc[i][j] = 0.f;

    for (int k0 = 0; k0 < K; k0 += 8) {
        float4 av = make_float4(0.f,0.f,0.f,0.f);
        if (arow_ok)
            av = *reinterpret_cast<const float4*>(A + (size_t)(m0 + arow) * lda + k0 + ak);
        float4 bv = *reinterpret_cast<const float4*>(Bm + (size_t)(k0 + brow) * ldb + n0 + bcol);

        __syncthreads();
        As[ak + 0][arow] = av.x;
        As[ak + 1][arow] = av.y;
        As[ak + 2][arow] = av.z;
        As[ak + 3][arow] = av.w;
        *reinterpret_cast<float4*>(&Bs[brow][bcol]) = bv;
        __syncthreads();

#pragma unroll
        for (int kk = 0; kk < 8; kk++) {
            float a[8], b[8];
            float4 t;
            t = *reinterpret_cast<const float4*>(&As[kk][ty * 4]);      a[0]=t.x; a[1]=t.y; a[2]=t.z; a[3]=t.w;
            t = *reinterpret_cast<const float4*>(&As[kk][64 + ty * 4]); a[4]=t.x; a[5]=t.y; a[6]=t.z; a[7]=t.w;
            t = *reinterpret_cast<const float4*>(&Bs[kk][tx * 4]);      b[0]=t.x; b[1]=t.y; b[2]=t.z; b[3]=t.w;
            t = *reinterpret_cast<const float4*>(&Bs[kk][64 + tx * 4]); b[4]=t.x; b[5]=t.y; b[6]=t.z; b[7]=t.w;
#pragma unroll
            for (int i = 0; i < 8; i++)
#pragma unroll
                for (int j = 0; j < 8; j++) acc[i][j] += a[i] * b[j];
        }
    }

#pragma unroll
    for (int ih = 0; ih < 2; ih++) {
#pragma unroll
        for (int i = 0; i < 4; i++) {
            int m = m0 + ih * 64 + ty * 4 + i;
            if (m < M) {
                float* crow = Cm + (size_t)m * ldc + n0;
#pragma unroll
                for (int jh = 0; jh < 2; jh++) {
                    float4 r;
                    r.x = acc[ih*4+i][jh*4+0] * alpha;
                    r.y = acc[ih*4+i][jh*4+1] * alpha;
                    r.z = acc[ih*4+i][jh*4+2] * alpha;
                    r.w = acc[ih*4+i][jh*4+3] * alpha;
                    if (HAS_BIAS) {
                        float4 bb = *reinterpret_cast<const float4*>(bias + n0 + jh*64 + tx*4);
                        r.x += bb.x; r.y += bb.y; r.z += bb.z; r.w += bb.w;
                    }
                    *reinterpret_cast<float4*>(crow + jh*64 + tx*4) = r;
                }
            }
        }
    }
}

// =============================================================
// CLS attention: 48 blocks (b,h). Attends over all N tokens.
// =============================================================
__global__ __launch_bounds__(256)
void cls_attn_kernel(const float* __restrict__ qkv, float* __restrict__ preout)
{
    __shared__ float sim[NN];
    __shared__ float qv[DD];
    __shared__ float red[256];
    __shared__ float accred[4 * DD];

    const int b = blockIdx.x / HH;
    const int h = blockIdx.x % HH;
    const int tid = threadIdx.x;

    if (tid < DD)
        qv[tid] = qkv[(size_t)(b * NN) * N_QKV + h * DD + tid] * SCALE;
    __syncthreads();

    for (int n = tid; n < NN; n += 256) {
        const float* kp = qkv + (size_t)(b * NN + n) * N_QKV + CC + h * DD;
        float d = 0.f;
#pragma unroll
        for (int c4 = 0; c4 < DD / 4; c4++) {
            float4 k4 = *reinterpret_cast<const float4*>(kp + c4 * 4);
            d += qv[c4*4+0]*k4.x + qv[c4*4+1]*k4.y + qv[c4*4+2]*k4.z + qv[c4*4+3]*k4.w;
        }
        sim[n] = d;
    }
    __syncthreads();

    float m = -1e30f;
    for (int n = tid; n < NN; n += 256) m = fmaxf(m, sim[n]);
    red[tid] = m; __syncthreads();
    for (int o = 128; o > 0; o >>= 1) { if (tid < o) red[tid] = fmaxf(red[tid], red[tid+o]); __syncthreads(); }
    const float mx = red[0];
    __syncthreads();

    float s = 0.f;
    for (int n = tid; n < NN; n += 256) { float e = __expf(sim[n] - mx); sim[n] = e; s += e; }
    red[tid] = s; __syncthreads();
    for (int o = 128; o > 0; o >>= 1) { if (tid < o) red[tid] += red[tid+o]; __syncthreads(); }
    const float inv = 1.f / red[0];
    __syncthreads();

    const int g = tid >> 6, dd = tid & 63;
    float a = 0.f;
    for (int n = g; n < NN; n += 4)
        a += sim[n] * qkv[(size_t)(b * NN + n) * N_QKV + 2 * CC + h * DD + dd];
    accred[g * DD + dd] = a;
    __syncthreads();
    if (tid < DD)
        preout[(size_t)(b * NN) * CC + h * DD + tid] =
            (accred[tid] + accred[DD + tid] + accred[2*DD + tid] + accred[3*DD + tid]) * inv;
}

// =============================================================
// Space attention: block = (qtile 0..24, f 0..7, bh 0..47).
// Q tile 64xD, K/V frame tiles 196xD in smem; softmax over P.
// =============================================================
#define SA_PAD 68
#define SA_SCLD 200
#define SA_SMEM ((2*196*SA_PAD + 64*SA_PAD + 64*SA_SCLD) * 4)

__global__ __launch_bounds__(256)
void space_attn_kernel(const float* __restrict__ qkv, float* __restrict__ xt)
{
    extern __shared__ float sm[];
    float* Ksm = sm;                       // 196 x 68
    float* Vsm = Ksm + 196 * SA_PAD;       // 196 x 68
    float* Qsm = Vsm + 196 * SA_PAD;       // 64 x 68
    float* Sc  = Qsm + 64 * SA_PAD;        // 64 x 200

    const int bh = blockIdx.z;
    const int b = bh / HH, h = bh % HH;
    const int f = blockIdx.y;
    const int q0 = blockIdx.x * 64;
    const int tid = threadIdx.x;

    // load K,V (frame f) : 196 rows x 16 float4
    for (int i = tid; i < 196 * 16; i += 256) {
        int r = i >> 4, c4 = i & 15;
        size_t base = (size_t)(b * NN + 1 + f * PP + r) * N_QKV + h * DD + c4 * 4;
        *reinterpret_cast<float4*>(Ksm + r * SA_PAD + c4 * 4) =
            *reinterpret_cast<const float4*>(qkv + base + CC);
        *reinterpret_cast<float4*>(Vsm + r * SA_PAD + c4 * 4) =
            *reinterpret_cast<const float4*>(qkv + base + 2 * CC);
    }
    // load Q tile
    for (int i = tid; i < 64 * 16; i += 256) {
        int r = i >> 4, c4 = i & 15;
        int sq = q0 + r;
        float4 qv = make_float4(0.f,0.f,0.f,0.f);
        if (sq < SS)
            qv = *reinterpret_cast<const float4*>(qkv + (size_t)(b * NN + 1 + sq) * N_QKV + h * DD + c4 * 4);
        *reinterpret_cast<float4*>(Qsm + r * SA_PAD + c4 * 4) = qv;
    }
    __syncthreads();

    // phase 1: scores. warp w -> q rows 8w..8w+7, lane l -> p = l+32j
    const int w = tid >> 5, l = tid & 31;
    float acc[8][7];
#pragma unroll
    for (int qi = 0; qi < 8; qi++)
#pragma unroll
        for (int j = 0; j < 7; j++) acc[qi][j] = 0.f;

#pragma unroll 4
    for (int k4 = 0; k4 < 16; k4++) {
        float4 kreg[7];
#pragma unroll
        for (int j = 0; j < 7; j++) {
            int p = l + 32 * j;
            kreg[j] = (p < 196) ? *reinterpret_cast<const float4*>(Ksm + p * SA_PAD + 4 * k4)
                                : make_float4(0.f,0.f,0.f,0.f);
        }
#pragma unroll
        for (int qi = 0; qi < 8; qi++) {
            float4 qv = *reinterpret_cast<const float4*>(Qsm + (8 * w + qi) * SA_PAD + 4 * k4);
#pragma unroll
            for (int j = 0; j < 7; j++)
                acc[qi][j] += qv.x*kreg[j].x + qv.y*kreg[j].y + qv.z*kreg[j].z + qv.w*kreg[j].w;
        }
    }

    // softmax over p (196) per q row
#pragma unroll
    for (int qi = 0; qi < 8; qi++) {
        float mx = -1e30f;
#pragma unroll
        for (int j = 0; j < 7; j++) {
            float v = acc[qi][j] * SCALE;
            acc[qi][j] = v;
            if (l + 32 * j < 196) mx = fmaxf(mx, v);
        }
#pragma unroll
        for (int o = 16; o > 0; o >>= 1) mx = fmaxf(mx, __shfl_xor_sync(0xffffffffu, mx, o));
        float sum = 0.f;
#pragma unroll
        for (int j = 0; j < 7; j++) {
            float e = (l + 32 * j < 196) ? __expf(acc[qi][j] - mx) : 0.f;
            acc[qi][j] = e; sum += e;
        }
#pragma unroll
        for (int o = 16; o > 0; o >>= 1) sum += __shfl_xor_sync(0xffffffffu, sum, o);
        float inv = 1.f / sum;
        int q = 8 * w + qi;
#pragma unroll
        for (int j = 0; j < 7; j++) {
            int p = l + 32 * j;
            if (p < 196) Sc[q * SA_SCLD + p] = acc[qi][j] * inv;
        }
    }
    __syncthreads();

    // phase 3: out(64x64) = Sc(64x196) @ V(196x64)
    const int ty = tid >> 4, tx = tid & 15;
    float o2[4][4];
#pragma unroll
    for (int i = 0; i < 4; i++)
#pragma unroll
        for (int j = 0; j < 4; j++) o2[i][j] = 0.f;

#pragma unroll 4
    for (int p = 0; p < 196; p++) {
        float4 vv = *reinterpret_cast<const float4*>(Vsm + p * SA_PAD + 4 * tx);
#pragma unroll
        for (int i = 0; i < 4; i++) {
            float s = Sc[(ty * 4 + i) * SA_SCLD + p];
            o2[i][0] += s * vv.x; o2[i][1] += s * vv.y;
            o2[i][2] += s * vv.z; o2[i][3] += s * vv.w;
        }
    }

#pragma unroll
    for (int i = 0; i < 4; i++) {
        int sq = q0 + ty * 4 + i;
        if (sq < SS) {
            float4 r = make_float4(o2[i][0], o2[i][1], o2[i][2], o2[i][3]);
            *reinterpret_cast<float4*>(xt + ((size_t)(b * SS + sq) * FF + f) * CC + h * DD + 4 * tx) = r;
        }
    }
}

// =============================================================
// Gather x_diag[b,s,:] = xt[b,s,s/P,:]
// =============================================================
__global__ __launch_bounds__(256)
void gather_xdiag_kernel(const float* __restrict__ xt, float* __restrict__ xd)
{
    size_t idx = (size_t)blockIdx.x * 256 + threadIdx.x;     // float4 index
    const size_t total = (size_t)M_S * (CC / 4);
    if (idx < total) {
        size_t m = idx / (CC / 4);
        int c4 = (int)(idx % (CC / 4));
        int s = (int)(m % SS);
        int f = s / PP;
        reinterpret_cast<float4*>(xd)[idx] =
            reinterpret_cast<const float4*>(xt)[(m * FF + f) * (CC / 4) + c4];
    }
}

// =============================================================
// G[b,s,h,c] = sum_dd q2[b,s,h*64+dd] * w_kv[c, h*64+dd]   (NT, K=64)
// grid: (98, 12, 12) = (mtile, ctile, head)
// =============================================================
__global__ __launch_bounds__(256)
void gemm_G_kernel(const float* __restrict__ q2, const float* __restrict__ wkv,
                   float* __restrict__ G)
{
    __shared__ float As[64][68];
    __shared__ float Bs[64][68];
    const int mt = blockIdx.x, ct = blockIdx.y, h = blockIdx.z;
    const int tid = threadIdx.x;

    for (int i = tid; i < 64 * 16; i += 256) {
        int r = i >> 4, c4 = i & 15;
        *reinterpret_cast<float4*>(&As[r][4 * c4]) =
            *reinterpret_cast<const float4*>(q2 + (size_t)(mt * 64 + r) * CC + h * DD + 4 * c4);
        *reinterpret_cast<float4*>(&Bs[r][4 * c4]) =
            *reinterpret_cast<const float4*>(wkv + (size_t)(ct * 64 + r) * (2 * CC) + h * DD + 4 * c4);
    }
    __syncthreads();

    const int tx = tid & 15, ty = tid >> 4;
    float acc[4][4];
#pragma unroll
    for (int i = 0; i < 4; i++)
#pragma unroll
        for (int j = 0; j < 4; j++) acc[i][j] = 0.f;

#pragma unroll 4
    for (int k4 = 0; k4 < 16; k4++) {
        float4 a[4], b[4];
#pragma unroll
        for (int jm = 0; jm < 4; jm++) a[jm] = *reinterpret_cast<const float4*>(&As[ty + 16 * jm][4 * k4]);
#pragma unroll
        for (int jc = 0; jc < 4; jc++) b[jc] = *reinterpret_cast<const float4*>(&Bs[tx + 16 * jc][4 * k4]);
#pragma unroll
        for (int jm = 0; jm < 4; jm++)
#pragma unroll
            for (int jc = 0; jc < 4; jc++)
                acc[jm][jc] += a[jm].x*b[jc].x + a[jm].y*b[jc].y + a[jm].z*b[jc].z + a[jm].w*b[jc].w;
    }

#pragma unroll
    for (int jm = 0; jm < 4; jm++) {
        size_t m = (size_t)mt * 64 + ty + 16 * jm;
#pragma unroll
        for (int jc = 0; jc < 4; jc++)
            G[(m * HH + h) * CC + ct * 64 + tx + 16 * jc] = acc[jm][jc];
    }
}

// =============================================================
// Per (b,s): scores(12x8) = G . xt, softmax over f -> attn2 out,
// out row = sum_f attn2 * xt  -> preout (row 1+s)
// =============================================================
#define SO_SMEM ((FF*CC + HH*CC + 96 + 96) * 4)

__global__ __launch_bounds__(256)
void score_out_kernel(const float* __restrict__ xt, const float* __restrict__ G,
                      float* __restrict__ preout, float* __restrict__ attn2)
{
    extern __shared__ float sm[];
    float* xts = sm;                  // 8 x 768
    float* Gs  = xts + FF * CC;       // 12 x 768
    float* sc  = Gs + HH * CC;        // 96
    float* pr  = sc + 96;             // 96

    const int bs = blockIdx.x;        // 0..6271
    const int b = bs / SS, s = bs % SS;
    const int tid = threadIdx.x;

    for (int i = tid; i < FF * CC / 4; i += 256)
        reinterpret_cast<float4*>(xts)[i] = reinterpret_cast<const float4*>(xt)[(size_t)bs * (FF * CC / 4) + i];
    for (int i = tid; i < HH * CC / 4; i += 256)
        reinterpret_cast<float4*>(Gs)[i] = reinterpret_cast<const float4*>(G)[(size_t)bs * (HH * CC / 4) + i];
    __syncthreads();

    const int w = tid >> 5, l = tid & 31;
    for (int idx = w; idx < 96; idx += 8) {
        int h = idx >> 3, f = idx & 7;
        const float4* gp = reinterpret_cast<const float4*>(Gs + h * CC);
        const float4* xp = reinterpret_cast<const float4*>(xts + f * CC);
        float part = 0.f;
#pragma unroll
        for (int c4 = l; c4 < CC / 4; c4 += 32) {
            float4 g = gp[c4], x = xp[c4];
            part += g.x*x.x + g.y*x.y + g.z*x.z + g.w*x.w;
        }
#pragma unroll
        for (int o = 16; o > 0; o >>= 1) part += __shfl_xor_sync(0xffffffffu, part, o);
        if (l == 0) sc[idx] = part;
    }
    __syncthreads();

    if (tid < HH) {
        int h = tid;
        float mx = -1e30f;
#pragma unroll
        for (int f = 0; f < FF; f++) mx = fmaxf(mx, sc[h * 8 + f]);
        float sum = 0.f;
        float e[FF];
#pragma unroll
        for (int f = 0; f < FF; f++) { e[f] = __expf(sc[h * 8 + f] - mx); sum += e[f]; }
        float inv = 1.f / sum;
#pragma unroll
        for (int f = 0; f < FF; f++) {
            float p = e[f] * inv;
            pr[h * 8 + f] = p;
            attn2[((size_t)(b * HH + h) * SS + s) * FF + f] = p;
        }
    }
    __syncthreads();

    for (int c = tid; c < CC; c += 256) {
        int h = c >> 6;
        float v = 0.f;
#pragma unroll
        for (int f = 0; f < FF; f++) v += pr[h * 8 + f] * xts[f * CC + c];
        preout[(size_t)(b * NN + 1 + s) * CC + c] = v;
    }
}

// =============================================================
// host launch
// =============================================================
extern "C" void kernel_launch(void* const* d_in, const int* in_sizes, int n_in,
                              void* d_out, int out_size)
{
    const float* x      = (const float*)d_in[0];
    const float* w_qkv  = (const float*)d_in[1];
    const float* w_q    = (const float*)d_in[2];
    const float* w_kv   = (const float*)d_in[3];
    const float* w_proj = (const float*)d_in[4];
    const float* b_proj = (const float*)d_in[5];

    float *p_qkv, *p_xt, *p_xd, *p_q2, *p_G, *p_pre;
    cudaGetSymbolAddress((void**)&p_qkv, g_qkv);
    cudaGetSymbolAddress((void**)&p_xt,  g_xt);
    cudaGetSymbolAddress((void**)&p_xd,  g_xd);
    cudaGetSymbolAddress((void**)&p_q2,  g_q2);
    cudaGetSymbolAddress((void**)&p_G,   g_G);
    cudaGetSymbolAddress((void**)&p_pre, g_pre);

    cudaFuncSetAttribute(space_attn_kernel, cudaFuncAttributeMaxDynamicSharedMemorySize, SA_SMEM);
    cudaFuncSetAttribute(score_out_kernel,  cudaFuncAttributeMaxDynamicSharedMemorySize, SO_SMEM);

    float* outp  = (float*)d_out;
    float* attn2 = outp + OUT_ELEMS;

    // 1) qkv = x @ w_qkv
    sgemm128<false><<<dim3(N_QKV/128, (M_QKV+127)/128), 256>>>(
        x, w_qkv, p_qkv, nullptr, M_QKV, N_QKV, CC, CC, N_QKV, N_QKV, 1.f);

    // 2) cls attention -> preout rows n=0
    cls_attn_kernel<<<BATCH*HH, 256>>>(p_qkv, p_pre);

    // 3) fused space attention -> xt (B,S,F,C)
    space_attn_kernel<<<dim3((SS+63)/64, FF, BATCH*HH), 256, SA_SMEM>>>(p_qkv, p_xt);

    // 4) gather x_diag
    {
        size_t total = (size_t)M_S * (CC/4);
        gather_xdiag_kernel<<<(unsigned)((total + 255)/256), 256>>>(p_xt, p_xd);
    }

    // 5) q2 = scale * x_diag @ w_q
    sgemm128<false><<<dim3(CC/128, M_S/128), 256>>>(
        p_xd, w_q, p_q2, nullptr, M_S, CC, CC, CC, CC, CC, SCALE);

    // 6) G[b,s,h,:] = q2_h @ Wk_h^T  (k2 GEMM eliminated algebraically)
    gemm_G_kernel<<<dim3(M_S/64, CC/64, HH), 256>>>(p_q2, w_kv, p_G);

    // 7) scores + softmax(F) -> attn2 output; weighted xt -> preout rows 1+s
    score_out_kernel<<<M_S, 256, SO_SMEM>>>(p_xt, p_G, p_pre, attn2);

    // 8) out = preout @ w_proj + b_proj
    sgemm128<true><<<dim3(CC/128, (M_QKV+127)/128), 256>>>(
        p_pre, w_proj, outp, b_proj, M_QKV, CC, CC, CC, CC, CC, 1.f);
}

// round 3
// speedup vs baseline: 1.2280x; 1.2275x over previous
#include <cuda_runtime.h>
#include <cuda_bf16.h>
#include <math.h>
#include <stdint.h>

// ---------------- problem constants ----------------
#define BATCH 4
#define PP    196
#define FF    8
#define CC    768
#define NN    1569          // 1 + F*P
#define SS    1568          // F*P
#define HH    12
#define DD    64
#define SCALE 0.125f        // d^-0.5

#define M_QKV   (BATCH*NN)          // 6276
#define N_QKV   (3*CC)              // 2304
#define M_S     (BATCH*SS)          // 6272
#define OUT_ELEMS ((size_t)BATCH*NN*CC)   // 4,819,968

// ---------------- scratch ----------------
__device__ float g_qkv[(size_t)M_QKV * N_QKV];        // (B,N,3C)
__device__ float g_xt [(size_t)M_S * FF * CC];        // (B,S,F,C)
__device__ float g_xd [(size_t)M_S * CC];             // x_diag (B,S,C)
__device__ float g_q2 [(size_t)M_S * CC];             // (B,S,C) scaled
__device__ float g_G  [(size_t)M_S * HH * CC];        // (B,S,h,C)
__device__ float g_pre[(size_t)M_QKV * CC];           // pre-proj (B,N,C)

// =============================================================
// TF32 tensor-core GEMM: C = alpha * A(MxK) @ B(KxN) (+bias).
// Row-major A,B,C. 128x128x16 tile, 256 thr, 8 warps (2x4),
// warp tile 64x32 via m16n8k8 tf32 mma. N%128==0, K%16==0.
// Inputs rounded to tf32 with cvt.rna (unbiased).
// =============================================================
__device__ __forceinline__ float f2tf(float x) {
    uint32_t u;
    asm("cvt.rna.tf32.f32 %0, %1;" : "=r"(u) : "f"(x));
    return __uint_as_float(u);
}

__device__ __forceinline__ void mma_tf32(float* c, const uint32_t* a, const uint32_t* b) {
    asm volatile("mma.sync.aligned.m16n8k8.row.col.f32.tf32.tf32.f32 "
        "{%0,%1,%2,%3}, {%4,%5,%6,%7}, {%8,%9}, {%0,%1,%2,%3};"
        : "+f"(c[0]), "+f"(c[1]), "+f"(c[2]), "+f"(c[3])
        : "r"(a[0]), "r"(a[1]), "r"(a[2]), "r"(a[3]), "r"(b[0]), "r"(b[1]));
}

#define ALD 20     // As row stride (floats): banks (20m+k)%32 distinct
#define BLD 136    // Bs row stride (floats): stride%32==8 -> (8k+n)%32 distinct

template<bool HAS_BIAS>
__global__ __launch_bounds__(256)
void gemm_tf32(const float* __restrict__ A, const float* __restrict__ Bm,
               float* __restrict__ Cm, const float* __restrict__ bias,
               int M, int N, int K, int lda, int ldb, int ldc, float alpha)
{
    __shared__ float As[2][128 * ALD];
    __shared__ float Bs[2][16 * BLD];

    const int tid  = threadIdx.x;
    const int lane = tid & 31;
    const int warp = tid >> 5;
    const int wm   = (warp >> 2) * 64;   // 0 or 64
    const int wn   = (warp & 3) * 32;    // 0,32,64,96
    const int m0   = blockIdx.y * 128;
    const int n0   = blockIdx.x * 128;

    // global staging indices
    const int a_row0 = tid >> 2;          // + i*64
    const int a_k0   = (tid & 3) * 4;
    const int b_row0 = tid >> 5;          // + i*8
    const int b_c0   = (tid & 31) * 4;

    float4 ra[2], rb[2];

    // ---- load tile 0 ----
#pragma unroll
    for (int i = 0; i < 2; i++) {
        int row = a_row0 + i * 64;
        ra[i] = (m0 + row < M) ? *(const float4*)(A + (size_t)(m0 + row) * lda + a_k0)
                               : make_float4(0.f, 0.f, 0.f, 0.f);
        rb[i] = *(const float4*)(Bm + (size_t)(b_row0 + i * 8) * ldb + n0 + b_c0);
    }
#pragma unroll
    for (int i = 0; i < 2; i++) {
        float* p = &As[0][(a_row0 + i * 64) * ALD + a_k0];
        p[0] = f2tf(ra[i].x); p[1] = f2tf(ra[i].y); p[2] = f2tf(ra[i].z); p[3] = f2tf(ra[i].w);
        float* q = &Bs[0][(b_row0 + i * 8) * BLD + b_c0];
        q[0] = f2tf(rb[i].x); q[1] = f2tf(rb[i].y); q[2] = f2tf(rb[i].z); q[3] = f2tf(rb[i].w);
    }
    __syncthreads();

    float acc[4][4][4];
#pragma unroll
    for (int i = 0; i < 4; i++)
#pragma unroll
        for (int j = 0; j < 4; j++)
#pragma unroll
            for (int r = 0; r < 4; r++) acc[i][j][r] = 0.f;

    const int ntiles = K / 16;
    for (int t = 0; t < ntiles; t++) {
        const int cur = t & 1;
        const bool more = (t + 1 < ntiles);
        if (more) {
            const int k0 = (t + 1) * 16;
#pragma unroll
            for (int i = 0; i < 2; i++) {
                int row = a_row0 + i * 64;
                ra[i] = (m0 + row < M) ? *(const float4*)(A + (size_t)(m0 + row) * lda + k0 + a_k0)
                                       : make_float4(0.f, 0.f, 0.f, 0.f);
                rb[i] = *(const float4*)(Bm + (size_t)(k0 + b_row0 + i * 8) * ldb + n0 + b_c0);
            }
        }

#pragma unroll
        for (int ks = 0; ks < 2; ks++) {
            const int kb = ks * 8;
            uint32_t af[4][4], bf[4][2];
#pragma unroll
            for (int i = 0; i < 4; i++) {
                const float* base = &As[cur][(wm + i * 16 + (lane >> 2)) * ALD + kb + (lane & 3)];
                af[i][0] = __float_as_uint(base[0]);
                af[i][1] = __float_as_uint(base[8 * ALD]);
                af[i][2] = __float_as_uint(base[4]);
                af[i][3] = __float_as_uint(base[8 * ALD + 4]);
            }
#pragma unroll
            for (int j = 0; j < 4; j++) {
                const float* base = &Bs[cur][(kb + (lane & 3)) * BLD + wn + j * 8 + (lane >> 2)];
                bf[j][0] = __float_as_uint(base[0]);
                bf[j][1] = __float_as_uint(base[4 * BLD]);
            }
#pragma unroll
            for (int i = 0; i < 4; i++)
#pragma unroll
                for (int j = 0; j < 4; j++)
                    mma_tf32(acc[i][j], af[i], bf[j]);
        }

        if (more) {
            const int nxt = (t + 1) & 1;
#pragma unroll
            for (int i = 0; i < 2; i++) {
                float* p = &As[nxt][(a_row0 + i * 64) * ALD + a_k0];
                p[0] = f2tf(ra[i].x); p[1] = f2tf(ra[i].y); p[2] = f2tf(ra[i].z); p[3] = f2tf(ra[i].w);
                float* q = &Bs[nxt][(b_row0 + i * 8) * BLD + b_c0];
                q[0] = f2tf(rb[i].x); q[1] = f2tf(rb[i].y); q[2] = f2tf(rb[i].z); q[3] = f2tf(rb[i].w);
            }
            __syncthreads();
        }
    }

    // ---- epilogue ----
#pragma unroll
    for (int i = 0; i < 4; i++) {
        const int rbase = m0 + wm + i * 16 + (lane >> 2);
#pragma unroll
        for (int h = 0; h < 2; h++) {
            const int row = rbase + h * 8;
            if (row < M) {
#pragma unroll
                for (int j = 0; j < 4; j++) {
                    const int col = n0 + wn + j * 8 + (lane & 3) * 2;
                    float2 r;
                    r.x = acc[i][j][h * 2 + 0] * alpha;
                    r.y = acc[i][j][h * 2 + 1] * alpha;
                    if (HAS_BIAS) { r.x += bias[col]; r.y += bias[col + 1]; }
                    *(float2*)(Cm + (size_t)row * ldc + col) = r;
                }
            }
        }
    }
}

// =============================================================
// CLS attention: 48 blocks (b,h). Attends over all N tokens.
// =============================================================
__global__ __launch_bounds__(256)
void cls_attn_kernel(const float* __restrict__ qkv, float* __restrict__ preout)
{
    __shared__ float sim[NN];
    __shared__ float qv[DD];
    __shared__ float red[256];
    __shared__ float accred[4 * DD];

    const int b = blockIdx.x / HH;
    const int h = blockIdx.x % HH;
    const int tid = threadIdx.x;

    if (tid < DD)
        qv[tid] = qkv[(size_t)(b * NN) * N_QKV + h * DD + tid] * SCALE;
    __syncthreads();

    for (int n = tid; n < NN; n += 256) {
        const float* kp = qkv + (size_t)(b * NN + n) * N_QKV + CC + h * DD;
        float d = 0.f;
#pragma unroll
        for (int c4 = 0; c4 < DD / 4; c4++) {
            float4 k4 = *reinterpret_cast<const float4*>(kp + c4 * 4);
            d += qv[c4*4+0]*k4.x + qv[c4*4+1]*k4.y + qv[c4*4+2]*k4.z + qv[c4*4+3]*k4.w;
        }
        sim[n] = d;
    }
    __syncthreads();

    float m = -1e30f;
    for (int n = tid; n < NN; n += 256) m = fmaxf(m, sim[n]);
    red[tid] = m; __syncthreads();
    for (int o = 128; o > 0; o >>= 1) { if (tid < o) red[tid] = fmaxf(red[tid], red[tid+o]); __syncthreads(); }
    const float mx = red[0];
    __syncthreads();

    float s = 0.f;
    for (int n = tid; n < NN; n += 256) { float e = __expf(sim[n] - mx); sim[n] = e; s += e; }
    red[tid] = s; __syncthreads();
    for (int o = 128; o > 0; o >>= 1) { if (tid < o) red[tid] += red[tid+o]; __syncthreads(); }
    const float inv = 1.f / red[0];
    __syncthreads();

    const int g = tid >> 6, dd = tid & 63;
    float a = 0.f;
    for (int n = g; n < NN; n += 4)
        a += sim[n] * qkv[(size_t)(b * NN + n) * N_QKV + 2 * CC + h * DD + dd];
    accred[g * DD + dd] = a;
    __syncthreads();
    if (tid < DD)
        preout[(size_t)(b * NN) * CC + h * DD + tid] =
            (accred[tid] + accred[DD + tid] + accred[2*DD + tid] + accred[3*DD + tid]) * inv;
}

// =============================================================
// Space attention: block = (qtile 0..24, f 0..7, bh 0..47).
// =============================================================
#define SA_PAD 68
#define SA_SCLD 200
#define SA_SMEM ((2*196*SA_PAD + 64*SA_PAD + 64*SA_SCLD) * 4)

__global__ __launch_bounds__(256)
void space_attn_kernel(const float* __restrict__ qkv, float* __restrict__ xt)
{
    extern __shared__ float sm[];
    float* Ksm = sm;                       // 196 x 68
    float* Vsm = Ksm + 196 * SA_PAD;       // 196 x 68
    float* Qsm = Vsm + 196 * SA_PAD;       // 64 x 68
    float* Sc  = Qsm + 64 * SA_PAD;        // 64 x 200

    const int bh = blockIdx.z;
    const int b = bh / HH, h = bh % HH;
    const int f = blockIdx.y;
    const int q0 = blockIdx.x * 64;
    const int tid = threadIdx.x;

    for (int i = tid; i < 196 * 16; i += 256) {
        int r = i >> 4, c4 = i & 15;
        size_t base = (size_t)(b * NN + 1 + f * PP + r) * N_QKV + h * DD + c4 * 4;
        *reinterpret_cast<float4*>(Ksm + r * SA_PAD + c4 * 4) =
            *reinterpret_cast<const float4*>(qkv + base + CC);
        *reinterpret_cast<float4*>(Vsm + r * SA_PAD + c4 * 4) =
            *reinterpret_cast<const float4*>(qkv + base + 2 * CC);
    }
    for (int i = tid; i < 64 * 16; i += 256) {
        int r = i >> 4, c4 = i & 15;
        int sq = q0 + r;
        float4 qv = make_float4(0.f,0.f,0.f,0.f);
        if (sq < SS)
            qv = *reinterpret_cast<const float4*>(qkv + (size_t)(b * NN + 1 + sq) * N_QKV + h * DD + c4 * 4);
        *reinterpret_cast<float4*>(Qsm + r * SA_PAD + c4 * 4) = qv;
    }
    __syncthreads();

    const int w = tid >> 5, l = tid & 31;
    float acc[8][7];
#pragma unroll
    for (int qi = 0; qi < 8; qi++)
#pragma unroll
        for (int j = 0; j < 7; j++) acc[qi][j] = 0.f;

#pragma unroll 4
    for (int k4 = 0; k4 < 16; k4++) {
        float4 kreg[7];
#pragma unroll
        for (int j = 0; j < 7; j++) {
            int p = l + 32 * j;
            kreg[j] = (p < 196) ? *reinterpret_cast<const float4*>(Ksm + p * SA_PAD + 4 * k4)
                                : make_float4(0.f,0.f,0.f,0.f);
        }
#pragma unroll
        for (int qi = 0; qi < 8; qi++) {
            float4 qv = *reinterpret_cast<const float4*>(Qsm + (8 * w + qi) * SA_PAD + 4 * k4);
#pragma unroll
            for (int j = 0; j < 7; j++)
                acc[qi][j] += qv.x*kreg[j].x + qv.y*kreg[j].y + qv.z*kreg[j].z + qv.w*kreg[j].w;
        }
    }

#pragma unroll
    for (int qi = 0; qi < 8; qi++) {
        float mx = -1e30f;
#pragma unroll
        for (int j = 0; j < 7; j++) {
            float v = acc[qi][j] * SCALE;
            acc[qi][j] = v;
            if (l + 32 * j < 196) mx = fmaxf(mx, v);
        }
#pragma unroll
        for (int o = 16; o > 0; o >>= 1) mx = fmaxf(mx, __shfl_xor_sync(0xffffffffu, mx, o));
        float sum = 0.f;
#pragma unroll
        for (int j = 0; j < 7; j++) {
            float e = (l + 32 * j < 196) ? __expf(acc[qi][j] - mx) : 0.f;
            acc[qi][j] = e; sum += e;
        }
#pragma unroll
        for (int o = 16; o > 0; o >>= 1) sum += __shfl_xor_sync(0xffffffffu, sum, o);
        float inv = 1.f / sum;
        int q = 8 * w + qi;
#pragma unroll
        for (int j = 0; j < 7; j++) {
            int p = l + 32 * j;
            if (p < 196) Sc[q * SA_SCLD + p] = acc[qi][j] * inv;
        }
    }
    __syncthreads();

    const int ty = tid >> 4, tx = tid & 15;
    float o2[4][4];
#pragma unroll
    for (int i = 0; i < 4; i++)
#pragma unroll
        for (int j = 0; j < 4; j++) o2[i][j] = 0.f;

#pragma unroll 4
    for (int p = 0; p < 196; p++) {
        float4 vv = *reinterpret_cast<const float4*>(Vsm + p * SA_PAD + 4 * tx);
#pragma unroll
        for (int i = 0; i < 4; i++) {
            float s = Sc[(ty * 4 + i) * SA_SCLD + p];
            o2[i][0] += s * vv.x; o2[i][1] += s * vv.y;
            o2[i][2] += s * vv.z; o2[i][3] += s * vv.w;
        }
    }

#pragma unroll
    for (int i = 0; i < 4; i++) {
        int sq = q0 + ty * 4 + i;
        if (sq < SS) {
            float4 r = make_float4(o2[i][0], o2[i][1], o2[i][2], o2[i][3]);
            *reinterpret_cast<float4*>(xt + ((size_t)(b * SS + sq) * FF + f) * CC + h * DD + 4 * tx) = r;
        }
    }
}

// =============================================================
// Gather x_diag[b,s,:] = xt[b,s,s/P,:]
// =============================================================
__global__ __launch_bounds__(256)
void gather_xdiag_kernel(const float* __restrict__ xt, float* __restrict__ xd)
{
    size_t idx = (size_t)blockIdx.x * 256 + threadIdx.x;
    const size_t total = (size_t)M_S * (CC / 4);
    if (idx < total) {
        size_t m = idx / (CC / 4);
        int c4 = (int)(idx % (CC / 4));
        int s = (int)(m % SS);
        int f = s / PP;
        reinterpret_cast<float4*>(xd)[idx] =
            reinterpret_cast<const float4*>(xt)[(m * FF + f) * (CC / 4) + c4];
    }
}

// =============================================================
// G[b,s,h,c] = sum_dd q2[b,s,h*64+dd] * w_kv[c, h*64+dd]
// =============================================================
__global__ __launch_bounds__(256)
void gemm_G_kernel(const float* __restrict__ q2, const float* __restrict__ wkv,
                   float* __restrict__ G)
{
    __shared__ float As[64][68];
    __shared__ float Bs[64][68];
    const int mt = blockIdx.x, ct = blockIdx.y, h = blockIdx.z;
    const int tid = threadIdx.x;

    for (int i = tid; i < 64 * 16; i += 256) {
        int r = i >> 4, c4 = i & 15;
        *reinterpret_cast<float4*>(&As[r][4 * c4]) =
            *reinterpret_cast<const float4*>(q2 + (size_t)(mt * 64 + r) * CC + h * DD + 4 * c4);
        *reinterpret_cast<float4*>(&Bs[r][4 * c4]) =
            *reinterpret_cast<const float4*>(wkv + (size_t)(ct * 64 + r) * (2 * CC) + h * DD + 4 * c4);
    }
    __syncthreads();

    const int tx = tid & 15, ty = tid >> 4;
    float acc[4][4];
#pragma unroll
    for (int i = 0; i < 4; i++)
#pragma unroll
        for (int j = 0; j < 4; j++) acc[i][j] = 0.f;

#pragma unroll 4
    for (int k4 = 0; k4 < 16; k4++) {
        float4 a[4], b[4];
#pragma unroll
        for (int jm = 0; jm < 4; jm++) a[jm] = *reinterpret_cast<const float4*>(&As[ty + 16 * jm][4 * k4]);
#pragma unroll
        for (int jc = 0; jc < 4; jc++) b[jc] = *reinterpret_cast<const float4*>(&Bs[tx + 16 * jc][4 * k4]);
#pragma unroll
        for (int jm = 0; jm < 4; jm++)
#pragma unroll
            for (int jc = 0; jc < 4; jc++)
                acc[jm][jc] += a[jm].x*b[jc].x + a[jm].y*b[jc].y + a[jm].z*b[jc].z + a[jm].w*b[jc].w;
    }

#pragma unroll
    for (int jm = 0; jm < 4; jm++) {
        size_t m = (size_t)mt * 64 + ty + 16 * jm;
#pragma unroll
        for (int jc = 0; jc < 4; jc++)
            G[(m * HH + h) * CC + ct * 64 + tx + 16 * jc] = acc[jm][jc];
    }
}

// =============================================================
// Per (b,s): scores(12x8), softmax over f, weighted sum.
// =============================================================
#define SO_SMEM ((FF*CC + HH*CC + 96 + 96) * 4)

__global__ __launch_bounds__(256)
void score_out_kernel(const float* __restrict__ xt, const float* __restrict__ G,
                      float* __restrict__ preout, float* __restrict__ attn2)
{
    extern __shared__ float sm[];
    float* xts = sm;
    float* Gs  = xts + FF * CC;
    float* sc  = Gs + HH * CC;
    float* pr  = sc + 96;

    const int bs = blockIdx.x;
    const int b = bs / SS, s = bs % SS;
    const int tid = threadIdx.x;

    for (int i = tid; i < FF * CC / 4; i += 256)
        reinterpret_cast<float4*>(xts)[i] = reinterpret_cast<const float4*>(xt)[(size_t)bs * (FF * CC / 4) + i];
    for (int i = tid; i < HH * CC / 4; i += 256)
        reinterpret_cast<float4*>(Gs)[i] = reinterpret_cast<const float4*>(G)[(size_t)bs * (HH * CC / 4) + i];
    __syncthreads();

    const int w = tid >> 5, l = tid & 31;
    for (int idx = w; idx < 96; idx += 8) {
        int h = idx >> 3, f = idx & 7;
        const float4* gp = reinterpret_cast<const float4*>(Gs + h * CC);
        const float4* xp = reinterpret_cast<const float4*>(xts + f * CC);
        float part = 0.f;
#pragma unroll
        for (int c4 = l; c4 < CC / 4; c4 += 32) {
            float4 g = gp[c4], x = xp[c4];
            part += g.x*x.x + g.y*x.y + g.z*x.z + g.w*x.w;
        }
#pragma unroll
        for (int o = 16; o > 0; o >>= 1) part += __shfl_xor_sync(0xffffffffu, part, o);
        if (l == 0) sc[idx] = part;
    }
    __syncthreads();

    if (tid < HH) {
        int h = tid;
        float mx = -1e30f;
#pragma unroll
        for (int f = 0; f < FF; f++) mx = fmaxf(mx, sc[h * 8 + f]);
        float sum = 0.f;
        float e[FF];
#pragma unroll
        for (int f = 0; f < FF; f++) { e[f] = __expf(sc[h * 8 + f] - mx); sum += e[f]; }
        float inv = 1.f / sum;
#pragma unroll
        for (int f = 0; f < FF; f++) {
            float p = e[f] * inv;
            pr[h * 8 + f] = p;
            attn2[((size_t)(b * HH + h) * SS + s) * FF + f] = p;
        }
    }
    __syncthreads();

    for (int c = tid; c < CC; c += 256) {
        int h = c >> 6;
        float v = 0.f;
#pragma unroll
        for (int f = 0; f < FF; f++) v += pr[h * 8 + f] * xts[f * CC + c];
        preout[(size_t)(b * NN + 1 + s) * CC + c] = v;
    }
}

// =============================================================
// host launch
// =============================================================
extern "C" void kernel_launch(void* const* d_in, const int* in_sizes, int n_in,
                              void* d_out, int out_size)
{
    const float* x      = (const float*)d_in[0];
    const float* w_qkv  = (const float*)d_in[1];
    const float* w_q    = (const float*)d_in[2];
    const float* w_kv   = (const float*)d_in[3];
    const float* w_proj = (const float*)d_in[4];
    const float* b_proj = (const float*)d_in[5];

    float *p_qkv, *p_xt, *p_xd, *p_q2, *p_G, *p_pre;
    cudaGetSymbolAddress((void**)&p_qkv, g_qkv);
    cudaGetSymbolAddress((void**)&p_xt,  g_xt);
    cudaGetSymbolAddress((void**)&p_xd,  g_xd);
    cudaGetSymbolAddress((void**)&p_q2,  g_q2);
    cudaGetSymbolAddress((void**)&p_G,   g_G);
    cudaGetSymbolAddress((void**)&p_pre, g_pre);

    cudaFuncSetAttribute(space_attn_kernel, cudaFuncAttributeMaxDynamicSharedMemorySize, SA_SMEM);
    cudaFuncSetAttribute(score_out_kernel,  cudaFuncAttributeMaxDynamicSharedMemorySize, SO_SMEM);

    float* outp  = (float*)d_out;
    float* attn2 = outp + OUT_ELEMS;

    // 1) qkv = x @ w_qkv   (tf32 tensor cores)
    gemm_tf32<false><<<dim3(N_QKV/128, (M_QKV+127)/128), 256>>>(
        x, w_qkv, p_qkv, nullptr, M_QKV, N_QKV, CC, CC, N_QKV, N_QKV, 1.f);

    // 2) cls attention -> preout rows n=0
    cls_attn_kernel<<<BATCH*HH, 256>>>(p_qkv, p_pre);

    // 3) fused space attention -> xt (B,S,F,C)
    space_attn_kernel<<<dim3((SS+63)/64, FF, BATCH*HH), 256, SA_SMEM>>>(p_qkv, p_xt);

    // 4) gather x_diag
    {
        size_t total = (size_t)M_S * (CC/4);
        gather_xdiag_kernel<<<(unsigned)((total + 255)/256), 256>>>(p_xt, p_xd);
    }

    // 5) q2 = scale * x_diag @ w_q   (tf32)
    gemm_tf32<false><<<dim3(CC/128, M_S/128), 256>>>(
        p_xd, w_q, p_q2, nullptr, M_S, CC, CC, CC, CC, CC, SCALE);

    // 6) G[b,s,h,:] = q2_h @ Wk_h^T  (k2 GEMM eliminated algebraically)
    gemm_G_kernel<<<dim3(M_S/64, CC/64, HH), 256>>>(p_q2, w_kv, p_G);

    // 7) scores + softmax(F) -> attn2 output; weighted xt -> preout rows 1+s
    score_out_kernel<<<M_S, 256, SO_SMEM>>>(p_xt, p_G, p_pre, attn2);

    // 8) out = preout @ w_proj + b_proj   (tf32)
    gemm_tf32<true><<<dim3(CC/128, (M_QKV+127)/128), 256>>>(
        p_pre, w_proj, outp, b_proj, M_QKV, CC, CC, CC, CC, CC, 1.f);
}

// round 4
// speedup vs baseline: 1.4113x; 1.1492x over previous
#include <cuda_runtime.h>
#include <cuda_bf16.h>
#include <math.h>
#include <stdint.h>

// ---------------- problem constants ----------------
#define BATCH 4
#define PP    196
#define FF    8
#define CC    768
#define NN    1569          // 1 + F*P
#define SS    1568          // F*P
#define HH    12
#define DD    64
#define SCALE 0.125f        // d^-0.5

#define M_QKV   (BATCH*NN)          // 6276
#define N_QKV   (3*CC)              // 2304
#define M_S     (BATCH*SS)          // 6272
#define OUT_ELEMS ((size_t)BATCH*NN*CC)   // 4,819,968

// ---------------- scratch ----------------
__device__ float g_qkv[(size_t)M_QKV * N_QKV];        // (B,N,3C)
__device__ float g_xt [(size_t)M_S * FF * CC];        // (B,S,F,C)
__device__ float g_xd [(size_t)M_S * CC];             // x_diag (B,S,C)
__device__ float g_q2 [(size_t)M_S * CC];             // (B,S,C) scaled
__device__ float g_G  [(size_t)M_S * HH * CC];        // (B,S,h,C)
__device__ float g_pre[(size_t)M_QKV * CC];           // pre-proj (B,N,C)

// ---------------- tf32 helpers ----------------
__device__ __forceinline__ float f2tf(float x) {
    uint32_t u;
    asm("cvt.rna.tf32.f32 %0, %1;" : "=r"(u) : "f"(x));
    return __uint_as_float(u);
}

__device__ __forceinline__ void mma_tf32(float* c, const uint32_t* a, const uint32_t* b) {
    asm volatile("mma.sync.aligned.m16n8k8.row.col.f32.tf32.tf32.f32 "
        "{%0,%1,%2,%3}, {%4,%5,%6,%7}, {%8,%9}, {%0,%1,%2,%3};"
        : "+f"(c[0]), "+f"(c[1]), "+f"(c[2]), "+f"(c[3])
        : "r"(a[0]), "r"(a[1]), "r"(a[2]), "r"(a[3]), "r"(b[0]), "r"(b[1]));
}

// =============================================================
// TF32 tensor-core GEMM: C = alpha * A(MxK) @ B(KxN) (+bias).
// =============================================================
#define ALD 20     // As row stride (floats)
#define BLD 136    // Bs row stride (floats)

template<bool HAS_BIAS>
__global__ __launch_bounds__(256)
void gemm_tf32(const float* __restrict__ A, const float* __restrict__ Bm,
               float* __restrict__ Cm, const float* __restrict__ bias,
               int M, int N, int K, int lda, int ldb, int ldc, float alpha)
{
    __shared__ float As[2][128 * ALD];
    __shared__ float Bs[2][16 * BLD];

    const int tid  = threadIdx.x;
    const int lane = tid & 31;
    const int warp = tid >> 5;
    const int wm   = (warp >> 2) * 64;
    const int wn   = (warp & 3) * 32;
    const int m0   = blockIdx.y * 128;
    const int n0   = blockIdx.x * 128;

    const int a_row0 = tid >> 2;
    const int a_k0   = (tid & 3) * 4;
    const int b_row0 = tid >> 5;
    const int b_c0   = (tid & 31) * 4;

    float4 ra[2], rb[2];

#pragma unroll
    for (int i = 0; i < 2; i++) {
        int row = a_row0 + i * 64;
        ra[i] = (m0 + row < M) ? *(const float4*)(A + (size_t)(m0 + row) * lda + a_k0)
                               : make_float4(0.f, 0.f, 0.f, 0.f);
        rb[i] = *(const float4*)(Bm + (size_t)(b_row0 + i * 8) * ldb + n0 + b_c0);
    }
#pragma unroll
    for (int i = 0; i < 2; i++) {
        float* p = &As[0][(a_row0 + i * 64) * ALD + a_k0];
        p[0] = f2tf(ra[i].x); p[1] = f2tf(ra[i].y); p[2] = f2tf(ra[i].z); p[3] = f2tf(ra[i].w);
        float* q = &Bs[0][(b_row0 + i * 8) * BLD + b_c0];
        q[0] = f2tf(rb[i].x); q[1] = f2tf(rb[i].y); q[2] = f2tf(rb[i].z); q[3] = f2tf(rb[i].w);
    }
    __syncthreads();

    float acc[4][4][4];
#pragma unroll
    for (int i = 0; i < 4; i++)
#pragma unroll
        for (int j = 0; j < 4; j++)
#pragma unroll
            for (int r = 0; r < 4; r++) acc[i][j][r] = 0.f;

    const int ntiles = K / 16;
    for (int t = 0; t < ntiles; t++) {
        const int cur = t & 1;
        const bool more = (t + 1 < ntiles);
        if (more) {
            const int k0 = (t + 1) * 16;
#pragma unroll
            for (int i = 0; i < 2; i++) {
                int row = a_row0 + i * 64;
                ra[i] = (m0 + row < M) ? *(const float4*)(A + (size_t)(m0 + row) * lda + k0 + a_k0)
                                       : make_float4(0.f, 0.f, 0.f, 0.f);
                rb[i] = *(const float4*)(Bm + (size_t)(k0 + b_row0 + i * 8) * ldb + n0 + b_c0);
            }
        }

#pragma unroll
        for (int ks = 0; ks < 2; ks++) {
            const int kb = ks * 8;
            uint32_t af[4][4], bf[4][2];
#pragma unroll
            for (int i = 0; i < 4; i++) {
                const float* base = &As[cur][(wm + i * 16 + (lane >> 2)) * ALD + kb + (lane & 3)];
                af[i][0] = __float_as_uint(base[0]);
                af[i][1] = __float_as_uint(base[8 * ALD]);
                af[i][2] = __float_as_uint(base[4]);
                af[i][3] = __float_as_uint(base[8 * ALD + 4]);
            }
#pragma unroll
            for (int j = 0; j < 4; j++) {
                const float* base = &Bs[cur][(kb + (lane & 3)) * BLD + wn + j * 8 + (lane >> 2)];
                bf[j][0] = __float_as_uint(base[0]);
                bf[j][1] = __float_as_uint(base[4 * BLD]);
            }
#pragma unroll
            for (int i = 0; i < 4; i++)
#pragma unroll
                for (int j = 0; j < 4; j++)
                    mma_tf32(acc[i][j], af[i], bf[j]);
        }

        if (more) {
            const int nxt = (t + 1) & 1;
#pragma unroll
            for (int i = 0; i < 2; i++) {
                float* p = &As[nxt][(a_row0 + i * 64) * ALD + a_k0];
                p[0] = f2tf(ra[i].x); p[1] = f2tf(ra[i].y); p[2] = f2tf(ra[i].z); p[3] = f2tf(ra[i].w);
                float* q = &Bs[nxt][(b_row0 + i * 8) * BLD + b_c0];
                q[0] = f2tf(rb[i].x); q[1] = f2tf(rb[i].y); q[2] = f2tf(rb[i].z); q[3] = f2tf(rb[i].w);
            }
            __syncthreads();
        }
    }

#pragma unroll
    for (int i = 0; i < 4; i++) {
        const int rbase = m0 + wm + i * 16 + (lane >> 2);
#pragma unroll
        for (int h = 0; h < 2; h++) {
            const int row = rbase + h * 8;
            if (row < M) {
#pragma unroll
                for (int j = 0; j < 4; j++) {
                    const int col = n0 + wn + j * 8 + (lane & 3) * 2;
                    float2 r;
                    r.x = acc[i][j][h * 2 + 0] * alpha;
                    r.y = acc[i][j][h * 2 + 1] * alpha;
                    if (HAS_BIAS) { r.x += bias[col]; r.y += bias[col + 1]; }
                    *(float2*)(Cm + (size_t)row * ldc + col) = r;
                }
            }
        }
    }
}

// =============================================================
// CLS attention: 48 blocks (b,h).
// =============================================================
__global__ __launch_bounds__(256)
void cls_attn_kernel(const float* __restrict__ qkv, float* __restrict__ preout)
{
    __shared__ float sim[NN];
    __shared__ float qv[DD];
    __shared__ float red[256];
    __shared__ float accred[4 * DD];

    const int b = blockIdx.x / HH;
    const int h = blockIdx.x % HH;
    const int tid = threadIdx.x;

    if (tid < DD)
        qv[tid] = qkv[(size_t)(b * NN) * N_QKV + h * DD + tid] * SCALE;
    __syncthreads();

    for (int n = tid; n < NN; n += 256) {
        const float* kp = qkv + (size_t)(b * NN + n) * N_QKV + CC + h * DD;
        float d = 0.f;
#pragma unroll
        for (int c4 = 0; c4 < DD / 4; c4++) {
            float4 k4 = *reinterpret_cast<const float4*>(kp + c4 * 4);
            d += qv[c4*4+0]*k4.x + qv[c4*4+1]*k4.y + qv[c4*4+2]*k4.z + qv[c4*4+3]*k4.w;
        }
        sim[n] = d;
    }
    __syncthreads();

    float m = -1e30f;
    for (int n = tid; n < NN; n += 256) m = fmaxf(m, sim[n]);
    red[tid] = m; __syncthreads();
    for (int o = 128; o > 0; o >>= 1) { if (tid < o) red[tid] = fmaxf(red[tid], red[tid+o]); __syncthreads(); }
    const float mx = red[0];
    __syncthreads();

    float s = 0.f;
    for (int n = tid; n < NN; n += 256) { float e = __expf(sim[n] - mx); sim[n] = e; s += e; }
    red[tid] = s; __syncthreads();
    for (int o = 128; o > 0; o >>= 1) { if (tid < o) red[tid] += red[tid+o]; __syncthreads(); }
    const float inv = 1.f / red[0];
    __syncthreads();

    const int g = tid >> 6, dd = tid & 63;
    float a = 0.f;
    for (int n = g; n < NN; n += 4)
        a += sim[n] * qkv[(size_t)(b * NN + n) * N_QKV + 2 * CC + h * DD + dd];
    accred[g * DD + dd] = a;
    __syncthreads();
    if (tid < DD)
        preout[(size_t)(b * NN) * CC + h * DD + tid] =
            (accred[tid] + accred[DD + tid] + accred[2*DD + tid] + accred[3*DD + tid]) * inv;
}

// =============================================================
// Space attention: QK^T via tf32 MMA, softmax fp32, PV fp32.
// block = (qtile 0..24, f 0..7, bh 0..47), 256 thr (8 warps).
// smem: Ksm[208][68] (tf32, rows>=196 zero), Vsm[196][68] fp32,
//       Qsm[64][68] (tf32), Sc[64][212]
// =============================================================
#define SA_PAD 68
#define SC_LD  212
#define SA_SMEM ((208*SA_PAD + 196*SA_PAD + 64*SA_PAD + 64*SC_LD) * 4)

__global__ __launch_bounds__(256)
void space_attn_kernel(const float* __restrict__ qkv, float* __restrict__ xt)
{
    extern __shared__ float sm[];
    float* Ksm = sm;                        // 208 x 68 (tf32)
    float* Vsm = Ksm + 208 * SA_PAD;        // 196 x 68 (fp32)
    float* Qsm = Vsm + 196 * SA_PAD;        // 64 x 68 (tf32)
    float* Sc  = Qsm + 64 * SA_PAD;         // 64 x 212

    const int bh = blockIdx.z;
    const int b = bh / HH, h = bh % HH;
    const int f = blockIdx.y;
    const int q0 = blockIdx.x * 64;
    const int tid = threadIdx.x;

    // K (tf32, zero-pad rows 196..207) + V (fp32)
    for (int i = tid; i < 208 * 16; i += 256) {
        int r = i >> 4, c4 = i & 15;
        if (r < 196) {
            size_t base = (size_t)(b * NN + 1 + f * PP + r) * N_QKV + h * DD + c4 * 4;
            float4 kv = *reinterpret_cast<const float4*>(qkv + base + CC);
            float* kp = &Ksm[r * SA_PAD + c4 * 4];
            kp[0] = f2tf(kv.x); kp[1] = f2tf(kv.y); kp[2] = f2tf(kv.z); kp[3] = f2tf(kv.w);
            *reinterpret_cast<float4*>(Vsm + r * SA_PAD + c4 * 4) =
                *reinterpret_cast<const float4*>(qkv + base + 2 * CC);
        } else {
            float* kp = &Ksm[r * SA_PAD + c4 * 4];
            kp[0] = 0.f; kp[1] = 0.f; kp[2] = 0.f; kp[3] = 0.f;
        }
    }
    // Q tile (tf32)
    for (int i = tid; i < 64 * 16; i += 256) {
        int r = i >> 4, c4 = i & 15;
        int sq = q0 + r;
        float4 qv = make_float4(0.f,0.f,0.f,0.f);
        if (sq < SS)
            qv = *reinterpret_cast<const float4*>(qkv + (size_t)(b * NN + 1 + sq) * N_QKV + h * DD + c4 * 4);
        float* qp = &Qsm[r * SA_PAD + c4 * 4];
        qp[0] = f2tf(qv.x); qp[1] = f2tf(qv.y); qp[2] = f2tf(qv.z); qp[3] = f2tf(qv.w);
    }
    __syncthreads();

    const int w = tid >> 5, lane = tid & 31;

    // ---- phase 1: S = Q @ K^T via tf32 MMA ----
    {
        const int mrow  = (w & 3) * 16;        // 0,16,32,48
        const int nbase = (w >> 2) * 104;      // 0 or 104 (13 n8 tiles each)
        float acc[13][4];
#pragma unroll
        for (int nt = 0; nt < 13; nt++)
#pragma unroll
            for (int r = 0; r < 4; r++) acc[nt][r] = 0.f;

#pragma unroll
        for (int kb = 0; kb < 64; kb += 8) {
            uint32_t a[4];
            const float* ab = &Qsm[(mrow + (lane >> 2)) * SA_PAD + kb + (lane & 3)];
            a[0] = __float_as_uint(ab[0]);
            a[1] = __float_as_uint(ab[8 * SA_PAD]);
            a[2] = __float_as_uint(ab[4]);
            a[3] = __float_as_uint(ab[8 * SA_PAD + 4]);
#pragma unroll
            for (int nt = 0; nt < 13; nt++) {
                uint32_t bfr[2];
                const float* bb = &Ksm[(nbase + nt * 8 + (lane >> 2)) * SA_PAD + kb + (lane & 3)];
                bfr[0] = __float_as_uint(bb[0]);
                bfr[1] = __float_as_uint(bb[4]);
                mma_tf32(acc[nt], a, bfr);
            }
        }
        // store scaled scores
        const int r0 = mrow + (lane >> 2);
#pragma unroll
        for (int nt = 0; nt < 13; nt++) {
            int col = nbase + nt * 8 + (lane & 3) * 2;
            float2 s0 = make_float2(acc[nt][0] * SCALE, acc[nt][1] * SCALE);
            float2 s1 = make_float2(acc[nt][2] * SCALE, acc[nt][3] * SCALE);
            *reinterpret_cast<float2*>(&Sc[r0 * SC_LD + col]) = s0;
            *reinterpret_cast<float2*>(&Sc[(r0 + 8) * SC_LD + col]) = s1;
        }
    }
    __syncthreads();

    // ---- phase 2: softmax over p (196) per q row ----
    {
        const int l = lane;
#pragma unroll
        for (int qi = 0; qi < 8; qi++) {
            const int q = 8 * w + qi;
            float v[7];
            float mx = -1e30f;
#pragma unroll
            for (int j = 0; j < 7; j++) {
                int p = l + 32 * j;
                v[j] = (p < 196) ? Sc[q * SC_LD + p] : -1e30f;
                mx = fmaxf(mx, v[j]);
            }
#pragma unroll
            for (int o = 16; o > 0; o >>= 1) mx = fmaxf(mx, __shfl_xor_sync(0xffffffffu, mx, o));
            float sum = 0.f;
#pragma unroll
            for (int j = 0; j < 7; j++) {
                int p = l + 32 * j;
                float e = (p < 196) ? __expf(v[j] - mx) : 0.f;
                v[j] = e; sum += e;
            }
#pragma unroll
            for (int o = 16; o > 0; o >>= 1) sum += __shfl_xor_sync(0xffffffffu, sum, o);
            float inv = 1.f / sum;
#pragma unroll
            for (int j = 0; j < 7; j++) {
                int p = l + 32 * j;
                if (p < 196) Sc[q * SC_LD + p] = v[j] * inv;
            }
        }
    }
    __syncthreads();

    // ---- phase 3: out(64x64) = Sc(64x196) @ V(196x64), fp32 ----
    const int ty = tid >> 4, tx = tid & 15;
    float o2[4][4];
#pragma unroll
    for (int i = 0; i < 4; i++)
#pragma unroll
        for (int j = 0; j < 4; j++) o2[i][j] = 0.f;

#pragma unroll 4
    for (int p = 0; p < 196; p++) {
        float4 vv = *reinterpret_cast<const float4*>(Vsm + p * SA_PAD + 4 * tx);
#pragma unroll
        for (int i = 0; i < 4; i++) {
            float s = Sc[(ty * 4 + i) * SC_LD + p];
            o2[i][0] += s * vv.x; o2[i][1] += s * vv.y;
            o2[i][2] += s * vv.z; o2[i][3] += s * vv.w;
        }
    }

#pragma unroll
    for (int i = 0; i < 4; i++) {
        int sq = q0 + ty * 4 + i;
        if (sq < SS) {
            float4 r = make_float4(o2[i][0], o2[i][1], o2[i][2], o2[i][3]);
            *reinterpret_cast<float4*>(xt + ((size_t)(b * SS + sq) * FF + f) * CC + h * DD + 4 * tx) = r;
        }
    }
}

// =============================================================
// Gather x_diag[b,s,:] = xt[b,s,s/P,:]
// =============================================================
__global__ __launch_bounds__(256)
void gather_xdiag_kernel(const float* __restrict__ xt, float* __restrict__ xd)
{
    size_t idx = (size_t)blockIdx.x * 256 + threadIdx.x;
    const size_t total = (size_t)M_S * (CC / 4);
    if (idx < total) {
        size_t m = idx / (CC / 4);
        int c4 = (int)(idx % (CC / 4));
        int s = (int)(m % SS);
        int f = s / PP;
        reinterpret_cast<float4*>(xd)[idx] =
            reinterpret_cast<const float4*>(xt)[(m * FF + f) * (CC / 4) + c4];
    }
}

// =============================================================
// gemm_G tf32: per head h, G[m,c] = sum_k q2[m,h64+k]*wkv[c,h64+k]
// NT GEMM, M=6272, N=768, K=64. Tile 128x128, single K pass.
// grid (49, 6, 12), 256 threads.
// =============================================================
__global__ __launch_bounds__(256)
void gemm_G_tf32(const float* __restrict__ q2, const float* __restrict__ wkv,
                 float* __restrict__ G)
{
    __shared__ float As[128 * 68];
    __shared__ float Bs[128 * 68];

    const int mt = blockIdx.x, ct = blockIdx.y, h = blockIdx.z;
    const int tid = threadIdx.x;
    const int lane = tid & 31;
    const int w = tid >> 5;

    for (int i = tid; i < 128 * 16; i += 256) {
        int r = i >> 4, c4 = i & 15;
        float4 a = *reinterpret_cast<const float4*>(q2 + (size_t)(mt * 128 + r) * CC + h * DD + 4 * c4);
        float* pa = &As[r * 68 + 4 * c4];
        pa[0] = f2tf(a.x); pa[1] = f2tf(a.y); pa[2] = f2tf(a.z); pa[3] = f2tf(a.w);
        float4 bv = *reinterpret_cast<const float4*>(wkv + (size_t)(ct * 128 + r) * (2 * CC) + h * DD + 4 * c4);
        float* pb = &Bs[r * 68 + 4 * c4];
        pb[0] = f2tf(bv.x); pb[1] = f2tf(bv.y); pb[2] = f2tf(bv.z); pb[3] = f2tf(bv.w);
    }
    __syncthreads();

    const int wm = (w >> 2) * 64;
    const int wn = (w & 3) * 32;

    float acc[4][4][4];
#pragma unroll
    for (int i = 0; i < 4; i++)
#pragma unroll
        for (int j = 0; j < 4; j++)
#pragma unroll
            for (int r = 0; r < 4; r++) acc[i][j][r] = 0.f;

#pragma unroll
    for (int kb = 0; kb < 64; kb += 8) {
        uint32_t af[4][4], bf[4][2];
#pragma unroll
        for (int i = 0; i < 4; i++) {
            const float* base = &As[(wm + i * 16 + (lane >> 2)) * 68 + kb + (lane & 3)];
            af[i][0] = __float_as_uint(base[0]);
            af[i][1] = __float_as_uint(base[8 * 68]);
            af[i][2] = __float_as_uint(base[4]);
            af[i][3] = __float_as_uint(base[8 * 68 + 4]);
        }
#pragma unroll
        for (int j = 0; j < 4; j++) {
            const float* base = &Bs[(wn + j * 8 + (lane >> 2)) * 68 + kb + (lane & 3)];
            bf[j][0] = __float_as_uint(base[0]);
            bf[j][1] = __float_as_uint(base[4]);
        }
#pragma unroll
        for (int i = 0; i < 4; i++)
#pragma unroll
            for (int j = 0; j < 4; j++)
                mma_tf32(acc[i][j], af[i], bf[j]);
    }

#pragma unroll
    for (int i = 0; i < 4; i++) {
        const int rbase = mt * 128 + wm + i * 16 + (lane >> 2);
#pragma unroll
        for (int hh2 = 0; hh2 < 2; hh2++) {
            const size_t row = rbase + hh2 * 8;
            float* gp = G + (row * HH + h) * CC + ct * 128;
#pragma unroll
            for (int j = 0; j < 4; j++) {
                const int col = wn + j * 8 + (lane & 3) * 2;
                float2 r;
                r.x = acc[i][j][hh2 * 2 + 0];
                r.y = acc[i][j][hh2 * 2 + 1];
                *reinterpret_cast<float2*>(gp + col) = r;
            }
        }
    }
}

// =============================================================
// Per (b,s): scores(12x8), softmax over f, weighted sum.
// =============================================================
#define SO_SMEM ((FF*CC + HH*CC + 96 + 96) * 4)

__global__ __launch_bounds__(256)
void score_out_kernel(const float* __restrict__ xt, const float* __restrict__ G,
                      float* __restrict__ preout, float* __restrict__ attn2)
{
    extern __shared__ float sm[];
    float* xts = sm;
    float* Gs  = xts + FF * CC;
    float* sc  = Gs + HH * CC;
    float* pr  = sc + 96;

    const int bs = blockIdx.x;
    const int b = bs / SS, s = bs % SS;
    const int tid = threadIdx.x;

    for (int i = tid; i < FF * CC / 4; i += 256)
        reinterpret_cast<float4*>(xts)[i] = reinterpret_cast<const float4*>(xt)[(size_t)bs * (FF * CC / 4) + i];
    for (int i = tid; i < HH * CC / 4; i += 256)
        reinterpret_cast<float4*>(Gs)[i] = reinterpret_cast<const float4*>(G)[(size_t)bs * (HH * CC / 4) + i];
    __syncthreads();

    const int w = tid >> 5, l = tid & 31;
    for (int idx = w; idx < 96; idx += 8) {
        int h = idx >> 3, f = idx & 7;
        const float4* gp = reinterpret_cast<const float4*>(Gs + h * CC);
        const float4* xp = reinterpret_cast<const float4*>(xts + f * CC);
        float part = 0.f;
#pragma unroll
        for (int c4 = l; c4 < CC / 4; c4 += 32) {
            float4 g = gp[c4], x = xp[c4];
            part += g.x*x.x + g.y*x.y + g.z*x.z + g.w*x.w;
        }
#pragma unroll
        for (int o = 16; o > 0; o >>= 1) part += __shfl_xor_sync(0xffffffffu, part, o);
        if (l == 0) sc[idx] = part;
    }
    __syncthreads();

    if (tid < HH) {
        int h = tid;
        float mx = -1e30f;
#pragma unroll
        for (int f = 0; f < FF; f++) mx = fmaxf(mx, sc[h * 8 + f]);
        float sum = 0.f;
        float e[FF];
#pragma unroll
        for (int f = 0; f < FF; f++) { e[f] = __expf(sc[h * 8 + f] - mx); sum += e[f]; }
        float inv = 1.f / sum;
#pragma unroll
        for (int f = 0; f < FF; f++) {
            float p = e[f] * inv;
            pr[h * 8 + f] = p;
            attn2[((size_t)(b * HH + h) * SS + s) * FF + f] = p;
        }
    }
    __syncthreads();

    for (int c = tid; c < CC; c += 256) {
        int h = c >> 6;
        float v = 0.f;
#pragma unroll
        for (int f = 0; f < FF; f++) v += pr[h * 8 + f] * xts[f * CC + c];
        preout[(size_t)(b * NN + 1 + s) * CC + c] = v;
    }
}

// =============================================================
// host launch
// =============================================================
extern "C" void kernel_launch(void* const* d_in, const int* in_sizes, int n_in,
                              void* d_out, int out_size)
{
    const float* x      = (const float*)d_in[0];
    const float* w_qkv  = (const float*)d_in[1];
    const float* w_q    = (const float*)d_in[2];
    const float* w_kv   = (const float*)d_in[3];
    const float* w_proj = (const float*)d_in[4];
    const float* b_proj = (const float*)d_in[5];

    float *p_qkv, *p_xt, *p_xd, *p_q2, *p_G, *p_pre;
    cudaGetSymbolAddress((void**)&p_qkv, g_qkv);
    cudaGetSymbolAddress((void**)&p_xt,  g_xt);
    cudaGetSymbolAddress((void**)&p_xd,  g_xd);
    cudaGetSymbolAddress((void**)&p_q2,  g_q2);
    cudaGetSymbolAddress((void**)&p_G,   g_G);
    cudaGetSymbolAddress((void**)&p_pre, g_pre);

    cudaFuncSetAttribute(space_attn_kernel, cudaFuncAttributeMaxDynamicSharedMemorySize, SA_SMEM);
    cudaFuncSetAttribute(score_out_kernel,  cudaFuncAttributeMaxDynamicSharedMemorySize, SO_SMEM);

    float* outp  = (float*)d_out;
    float* attn2 = outp + OUT_ELEMS;

    // 1) qkv = x @ w_qkv   (tf32)
    gemm_tf32<false><<<dim3(N_QKV/128, (M_QKV+127)/128), 256>>>(
        x, w_qkv, p_qkv, nullptr, M_QKV, N_QKV, CC, CC, N_QKV, N_QKV, 1.f);

    // 2) cls attention -> preout rows n=0
    cls_attn_kernel<<<BATCH*HH, 256>>>(p_qkv, p_pre);

    // 3) fused space attention (tf32 QK^T, fp32 softmax+PV) -> xt
    space_attn_kernel<<<dim3((SS+63)/64, FF, BATCH*HH), 256, SA_SMEM>>>(p_qkv, p_xt);

    // 4) gather x_diag
    {
        size_t total = (size_t)M_S * (CC/4);
        gather_xdiag_kernel<<<(unsigned)((total + 255)/256), 256>>>(p_xt, p_xd);
    }

    // 5) q2 = scale * x_diag @ w_q   (tf32)
    gemm_tf32<false><<<dim3(CC/128, M_S/128), 256>>>(
        p_xd, w_q, p_q2, nullptr, M_S, CC, CC, CC, CC, CC, SCALE);

    // 6) G = per-head q2 @ Wk_h^T   (tf32 MMA)
    gemm_G_tf32<<<dim3(M_S/128, CC/128, HH), 256>>>(p_q2, w_kv, p_G);

    // 7) scores + softmax(F) -> attn2; weighted xt -> preout rows 1+s
    score_out_kernel<<<M_S, 256, SO_SMEM>>>(p_xt, p_G, p_pre, attn2);

    // 8) out = preout @ w_proj + b_proj   (tf32)
    gemm_tf32<true><<<dim3(CC/128, (M_QKV+127)/128), 256>>>(
        p_pre, w_proj, outp, b_proj, M_QKV, CC, CC, CC, CC, CC, 1.f);
}

// round 5
// speedup vs baseline: 1.7058x; 1.2087x over previous
#include <cuda_runtime.h>
#include <cuda_bf16.h>
#include <math.h>
#include <stdint.h>

// ---------------- problem constants ----------------
#define BATCH 4
#define PP    196
#define FF    8
#define CC    768
#define NN    1569          // 1 + F*P
#define SS    1568          // F*P
#define HH    12
#define DD    64
#define SCALE 0.125f        // d^-0.5

#define M_QKV   (BATCH*NN)          // 6276
#define N_QKV   (3*CC)              // 2304
#define M_S     (BATCH*SS)          // 6272
#define OUT_ELEMS ((size_t)BATCH*NN*CC)   // 4,819,968

// ---------------- scratch ----------------
__device__ float g_qkv[(size_t)M_QKV * N_QKV];        // (B,N,3C)
__device__ float g_xt [(size_t)M_S * FF * CC];        // (B,S,F,C)
__device__ float g_xd [(size_t)M_S * CC];             // x_diag (B,S,C)
__device__ float g_q2 [(size_t)M_S * CC];             // (B,S,C) scaled
__device__ float g_G  [(size_t)M_S * HH * CC];        // (B,S,h,C)
__device__ float g_pre[(size_t)M_QKV * CC];           // pre-proj (B,N,C)

// ---------------- tf32 helpers ----------------
__device__ __forceinline__ float f2tf(float x) {
    uint32_t u;
    asm("cvt.rna.tf32.f32 %0, %1;" : "=r"(u) : "f"(x));
    return __uint_as_float(u);
}

__device__ __forceinline__ void mma_tf32(float* c, const uint32_t* a, const uint32_t* b) {
    asm volatile("mma.sync.aligned.m16n8k8.row.col.f32.tf32.tf32.f32 "
        "{%0,%1,%2,%3}, {%4,%5,%6,%7}, {%8,%9}, {%0,%1,%2,%3};"
        : "+f"(c[0]), "+f"(c[1]), "+f"(c[2]), "+f"(c[3])
        : "r"(a[0]), "r"(a[1]), "r"(a[2]), "r"(a[3]), "r"(b[0]), "r"(b[1]));
}

// =============================================================
// TF32 tensor-core GEMM: C = alpha * A(MxK) @ B(KxN) (+bias).
// =============================================================
#define ALD 20     // As row stride (floats)
#define BLD 136    // Bs row stride (floats)

template<bool HAS_BIAS>
__global__ __launch_bounds__(256)
void gemm_tf32(const float* __restrict__ A, const float* __restrict__ Bm,
               float* __restrict__ Cm, const float* __restrict__ bias,
               int M, int N, int K, int lda, int ldb, int ldc, float alpha)
{
    __shared__ float As[2][128 * ALD];
    __shared__ float Bs[2][16 * BLD];

    const int tid  = threadIdx.x;
    const int lane = tid & 31;
    const int warp = tid >> 5;
    const int wm   = (warp >> 2) * 64;
    const int wn   = (warp & 3) * 32;
    const int m0   = blockIdx.y * 128;
    const int n0   = blockIdx.x * 128;

    const int a_row0 = tid >> 2;
    const int a_k0   = (tid & 3) * 4;
    const int b_row0 = tid >> 5;
    const int b_c0   = (tid & 31) * 4;

    float4 ra[2], rb[2];

#pragma unroll
    for (int i = 0; i < 2; i++) {
        int row = a_row0 + i * 64;
        ra[i] = (m0 + row < M) ? *(const float4*)(A + (size_t)(m0 + row) * lda + a_k0)
                               : make_float4(0.f, 0.f, 0.f, 0.f);
        rb[i] = *(const float4*)(Bm + (size_t)(b_row0 + i * 8) * ldb + n0 + b_c0);
    }
#pragma unroll
    for (int i = 0; i < 2; i++) {
        float* p = &As[0][(a_row0 + i * 64) * ALD + a_k0];
        p[0] = f2tf(ra[i].x); p[1] = f2tf(ra[i].y); p[2] = f2tf(ra[i].z); p[3] = f2tf(ra[i].w);
        float* q = &Bs[0][(b_row0 + i * 8) * BLD + b_c0];
        q[0] = f2tf(rb[i].x); q[1] = f2tf(rb[i].y); q[2] = f2tf(rb[i].z); q[3] = f2tf(rb[i].w);
    }
    __syncthreads();

    float acc[4][4][4];
#pragma unroll
    for (int i = 0; i < 4; i++)
#pragma unroll
        for (int j = 0; j < 4; j++)
#pragma unroll
            for (int r = 0; r < 4; r++) acc[i][j][r] = 0.f;

    const int ntiles = K / 16;
    for (int t = 0; t < ntiles; t++) {
        const int cur = t & 1;
        const bool more = (t + 1 < ntiles);
        if (more) {
            const int k0 = (t + 1) * 16;
#pragma unroll
            for (int i = 0; i < 2; i++) {
                int row = a_row0 + i * 64;
                ra[i] = (m0 + row < M) ? *(const float4*)(A + (size_t)(m0 + row) * lda + k0 + a_k0)
                                       : make_float4(0.f, 0.f, 0.f, 0.f);
                rb[i] = *(const float4*)(Bm + (size_t)(k0 + b_row0 + i * 8) * ldb + n0 + b_c0);
            }
        }

#pragma unroll
        for (int ks = 0; ks < 2; ks++) {
            const int kb = ks * 8;
            uint32_t af[4][4], bf[4][2];
#pragma unroll
            for (int i = 0; i < 4; i++) {
                const float* base = &As[cur][(wm + i * 16 + (lane >> 2)) * ALD + kb + (lane & 3)];
                af[i][0] = __float_as_uint(base[0]);
                af[i][1] = __float_as_uint(base[8 * ALD]);
                af[i][2] = __float_as_uint(base[4]);
                af[i][3] = __float_as_uint(base[8 * ALD + 4]);
            }
#pragma unroll
            for (int j = 0; j < 4; j++) {
                const float* base = &Bs[cur][(kb + (lane & 3)) * BLD + wn + j * 8 + (lane >> 2)];
                bf[j][0] = __float_as_uint(base[0]);
                bf[j][1] = __float_as_uint(base[4 * BLD]);
            }
#pragma unroll
            for (int i = 0; i < 4; i++)
#pragma unroll
                for (int j = 0; j < 4; j++)
                    mma_tf32(acc[i][j], af[i], bf[j]);
        }

        if (more) {
            const int nxt = (t + 1) & 1;
#pragma unroll
            for (int i = 0; i < 2; i++) {
                float* p = &As[nxt][(a_row0 + i * 64) * ALD + a_k0];
                p[0] = f2tf(ra[i].x); p[1] = f2tf(ra[i].y); p[2] = f2tf(ra[i].z); p[3] = f2tf(ra[i].w);
                float* q = &Bs[nxt][(b_row0 + i * 8) * BLD + b_c0];
                q[0] = f2tf(rb[i].x); q[1] = f2tf(rb[i].y); q[2] = f2tf(rb[i].z); q[3] = f2tf(rb[i].w);
            }
            __syncthreads();
        }
    }

#pragma unroll
    for (int i = 0; i < 4; i++) {
        const int rbase = m0 + wm + i * 16 + (lane >> 2);
#pragma unroll
        for (int h = 0; h < 2; h++) {
            const int row = rbase + h * 8;
            if (row < M) {
#pragma unroll
                for (int j = 0; j < 4; j++) {
                    const int col = n0 + wn + j * 8 + (lane & 3) * 2;
                    float2 r;
                    r.x = acc[i][j][h * 2 + 0] * alpha;
                    r.y = acc[i][j][h * 2 + 1] * alpha;
                    if (HAS_BIAS) { r.x += bias[col]; r.y += bias[col + 1]; }
                    *(float2*)(Cm + (size_t)row * ldc + col) = r;
                }
            }
        }
    }
}

// =============================================================
// CLS attention: 48 blocks (b,h).
// =============================================================
__global__ __launch_bounds__(256)
void cls_attn_kernel(const float* __restrict__ qkv, float* __restrict__ preout)
{
    __shared__ float sim[NN];
    __shared__ float qv[DD];
    __shared__ float red[256];
    __shared__ float accred[4 * DD];

    const int b = blockIdx.x / HH;
    const int h = blockIdx.x % HH;
    const int tid = threadIdx.x;

    if (tid < DD)
        qv[tid] = qkv[(size_t)(b * NN) * N_QKV + h * DD + tid] * SCALE;
    __syncthreads();

    for (int n = tid; n < NN; n += 256) {
        const float* kp = qkv + (size_t)(b * NN + n) * N_QKV + CC + h * DD;
        float d = 0.f;
#pragma unroll
        for (int c4 = 0; c4 < DD / 4; c4++) {
            float4 k4 = *reinterpret_cast<const float4*>(kp + c4 * 4);
            d += qv[c4*4+0]*k4.x + qv[c4*4+1]*k4.y + qv[c4*4+2]*k4.z + qv[c4*4+3]*k4.w;
        }
        sim[n] = d;
    }
    __syncthreads();

    float m = -1e30f;
    for (int n = tid; n < NN; n += 256) m = fmaxf(m, sim[n]);
    red[tid] = m; __syncthreads();
    for (int o = 128; o > 0; o >>= 1) { if (tid < o) red[tid] = fmaxf(red[tid], red[tid+o]); __syncthreads(); }
    const float mx = red[0];
    __syncthreads();

    float s = 0.f;
    for (int n = tid; n < NN; n += 256) { float e = __expf(sim[n] - mx); sim[n] = e; s += e; }
    red[tid] = s; __syncthreads();
    for (int o = 128; o > 0; o >>= 1) { if (tid < o) red[tid] += red[tid+o]; __syncthreads(); }
    const float inv = 1.f / red[0];
    __syncthreads();

    const int g = tid >> 6, dd = tid & 63;
    float a = 0.f;
    for (int n = g; n < NN; n += 4)
        a += sim[n] * qkv[(size_t)(b * NN + n) * N_QKV + 2 * CC + h * DD + dd];
    accred[g * DD + dd] = a;
    __syncthreads();
    if (tid < DD)
        preout[(size_t)(b * NN) * CC + h * DD + tid] =
            (accred[tid] + accred[DD + tid] + accred[2*DD + tid] + accred[3*DD + tid]) * inv;
}

// =============================================================
// Space attention v2: QK^T tf32 MMA + fp32 softmax + PV tf32 MMA.
// smem: Qsm[64][68] tf32 | Ksm[208][68] tf32 (reused as Sc[64][204])
//       | Vt[64][212] tf32 (transposed V, cols 196..207 zero)
// block = (qtile 0..24, f 0..7, bh 0..47), 256 thr (8 warps).
// =============================================================
#define SA_QLD 68
#define SA_KLD 68
#define SC_LD  204
#define VT_LD  212
#define Q_FLOATS (64 * SA_QLD)       // 4352
#define K_FLOATS (208 * SA_KLD)      // 14144
#define VT_FLOATS (64 * VT_LD)       // 13568
#define SA_SMEM ((Q_FLOATS + K_FLOATS + VT_FLOATS) * 4)

__global__ __launch_bounds__(256)
void space_attn_kernel(const float* __restrict__ qkv, float* __restrict__ xt)
{
    extern __shared__ float sm[];
    float* Qsm = sm;                      // 64 x 68
    float* Ksm = Qsm + Q_FLOATS;          // 208 x 68; later Sc 64 x 204
    float* Sc  = Ksm;
    float* Vt  = Ksm + K_FLOATS;          // 64 x 212 (dv, p)

    const int bh = blockIdx.z;
    const int b = bh / HH, h = bh % HH;
    const int f = blockIdx.y;
    const int q0 = blockIdx.x * 64;
    const int tid = threadIdx.x;
    const int w = tid >> 5, lane = tid & 31;

    // ---- loads ----
    // K rows (tf32) + zero-pad rows 196..207; V transposed into Vt (tf32)
    for (int i = tid; i < 208 * 16; i += 256) {
        int r = i >> 4, c4 = i & 15;
        float* kp = &Ksm[r * SA_KLD + c4 * 4];
        if (r < 196) {
            size_t base = (size_t)(b * NN + 1 + f * PP + r) * N_QKV + h * DD + c4 * 4;
            float4 kv = *reinterpret_cast<const float4*>(qkv + base + CC);
            kp[0] = f2tf(kv.x); kp[1] = f2tf(kv.y); kp[2] = f2tf(kv.z); kp[3] = f2tf(kv.w);
            float4 vv = *reinterpret_cast<const float4*>(qkv + base + 2 * CC);
            Vt[(4 * c4 + 0) * VT_LD + r] = f2tf(vv.x);
            Vt[(4 * c4 + 1) * VT_LD + r] = f2tf(vv.y);
            Vt[(4 * c4 + 2) * VT_LD + r] = f2tf(vv.z);
            Vt[(4 * c4 + 3) * VT_LD + r] = f2tf(vv.w);
        } else {
            kp[0] = 0.f; kp[1] = 0.f; kp[2] = 0.f; kp[3] = 0.f;
        }
    }
    // zero Vt pad columns p=196..207 (so pad scores * 0 = 0 in PV)
    for (int i = tid; i < 64 * 12; i += 256) {
        int dv = i / 12, p = 196 + (i % 12);
        Vt[dv * VT_LD + p] = 0.f;
    }
    // Q tile (tf32), zero rows beyond SS
    for (int i = tid; i < 64 * 16; i += 256) {
        int r = i >> 4, c4 = i & 15;
        int sq = q0 + r;
        float4 qv = make_float4(0.f, 0.f, 0.f, 0.f);
        if (sq < SS)
            qv = *reinterpret_cast<const float4*>(qkv + (size_t)(b * NN + 1 + sq) * N_QKV + h * DD + c4 * 4);
        float* qp = &Qsm[r * SA_QLD + c4 * 4];
        qp[0] = f2tf(qv.x); qp[1] = f2tf(qv.y); qp[2] = f2tf(qv.z); qp[3] = f2tf(qv.w);
    }
    __syncthreads();

    // ---- phase 1: S = Q @ K^T (tf32 MMA), scores kept in registers ----
    const int mrow  = (w & 3) * 16;       // 0,16,32,48
    const int nbase = (w >> 2) * 104;     // 0 or 104 (13 n8 tiles)
    float acc[13][4];
#pragma unroll
    for (int nt = 0; nt < 13; nt++)
#pragma unroll
        for (int r = 0; r < 4; r++) acc[nt][r] = 0.f;

#pragma unroll
    for (int kb = 0; kb < 64; kb += 8) {
        uint32_t a[4];
        const float* ab = &Qsm[(mrow + (lane >> 2)) * SA_QLD + kb + (lane & 3)];
        a[0] = __float_as_uint(ab[0]);
        a[1] = __float_as_uint(ab[8 * SA_QLD]);
        a[2] = __float_as_uint(ab[4]);
        a[3] = __float_as_uint(ab[8 * SA_QLD + 4]);
#pragma unroll
        for (int nt = 0; nt < 13; nt++) {
            uint32_t bfr[2];
            const float* bb = &Ksm[(nbase + nt * 8 + (lane >> 2)) * SA_KLD + kb + (lane & 3)];
            bfr[0] = __float_as_uint(bb[0]);
            bfr[1] = __float_as_uint(bb[4]);
            mma_tf32(acc[nt], a, bfr);
        }
    }
    __syncthreads();   // all K reads done; Sc may overwrite Ksm

    // store scaled scores into Sc (overlay)
    {
        const int r0 = mrow + (lane >> 2);
#pragma unroll
        for (int nt = 0; nt < 13; nt++) {
            int col = nbase + nt * 8 + (lane & 3) * 2;
            if (col < 196) {   // cols >=196 remain finite garbage (old K data); V pad is zero
                Sc[r0 * SC_LD + col]     = acc[nt][0] * SCALE;
                Sc[r0 * SC_LD + col + 1] = acc[nt][1] * SCALE;
                Sc[(r0 + 8) * SC_LD + col]     = acc[nt][2] * SCALE;
                Sc[(r0 + 8) * SC_LD + col + 1] = acc[nt][3] * SCALE;
            }
        }
    }
    __syncthreads();

    // ---- phase 2: softmax over p (196) per q row; write tf32-rounded probs ----
#pragma unroll
    for (int qi = 0; qi < 8; qi++) {
        const int q = 8 * w + qi;
        float v[7];
        float mx = -1e30f;
#pragma unroll
        for (int j = 0; j < 7; j++) {
            int p = lane + 32 * j;
            v[j] = (p < 196) ? Sc[q * SC_LD + p] : -1e30f;
            mx = fmaxf(mx, v[j]);
        }
#pragma unroll
        for (int o = 16; o > 0; o >>= 1) mx = fmaxf(mx, __shfl_xor_sync(0xffffffffu, mx, o));
        float sum = 0.f;
#pragma unroll
        for (int j = 0; j < 7; j++) {
            int p = lane + 32 * j;
            float e = (p < 196) ? __expf(v[j] - mx) : 0.f;
            v[j] = e; sum += e;
        }
#pragma unroll
        for (int o = 16; o > 0; o >>= 1) sum += __shfl_xor_sync(0xffffffffu, sum, o);
        float inv = 1.f / sum;
#pragma unroll
        for (int j = 0; j < 7; j++) {
            int p = lane + 32 * j;
            if (p < 196) Sc[q * SC_LD + p] = f2tf(v[j] * inv);
        }
    }
    __syncthreads();

    // ---- phase 3: out(64x64) = Sc(64x208) @ V(208x64) via tf32 MMA ----
    {
        const int mbase = (w & 3) * 16;     // query rows
        const int nb    = (w >> 2) * 32;    // dv cols
        float o2[4][4];
#pragma unroll
        for (int j = 0; j < 4; j++)
#pragma unroll
            for (int r = 0; r < 4; r++) o2[j][r] = 0.f;

#pragma unroll
        for (int kb = 0; kb < 208; kb += 8) {
            uint32_t a[4];
            const float* ab = &Sc[(mbase + (lane >> 2)) * SC_LD + kb + (lane & 3)];
            a[0] = __float_as_uint(ab[0]);
            a[1] = __float_as_uint(ab[8 * SC_LD]);
            a[2] = __float_as_uint(ab[4]);
            a[3] = __float_as_uint(ab[8 * SC_LD + 4]);
#pragma unroll
            for (int j = 0; j < 4; j++) {
                uint32_t bfr[2];
                const float* bb = &Vt[(nb + j * 8 + (lane >> 2)) * VT_LD + kb + (lane & 3)];
                bfr[0] = __float_as_uint(bb[0]);
                bfr[1] = __float_as_uint(bb[4]);
                mma_tf32(o2[j], a, bfr);
            }
        }

        // epilogue: write xt
        const int r0 = mbase + (lane >> 2);
#pragma unroll
        for (int hh2 = 0; hh2 < 2; hh2++) {
            const int sq = q0 + r0 + hh2 * 8;
            if (sq < SS) {
                float* xp = xt + ((size_t)(b * SS + sq) * FF + f) * CC + h * DD;
#pragma unroll
                for (int j = 0; j < 4; j++) {
                    const int dv = nb + j * 8 + (lane & 3) * 2;
                    float2 r;
                    r.x = o2[j][hh2 * 2 + 0];
                    r.y = o2[j][hh2 * 2 + 1];
                    *reinterpret_cast<float2*>(xp + dv) = r;
                }
            }
        }
    }
}

// =============================================================
// Gather x_diag[b,s,:] = xt[b,s,s/P,:]
// =============================================================
__global__ __launch_bounds__(256)
void gather_xdiag_kernel(const float* __restrict__ xt, float* __restrict__ xd)
{
    size_t idx = (size_t)blockIdx.x * 256 + threadIdx.x;
    const size_t total = (size_t)M_S * (CC / 4);
    if (idx < total) {
        size_t m = idx / (CC / 4);
        int c4 = (int)(idx % (CC / 4));
        int s = (int)(m % SS);
        int f = s / PP;
        reinterpret_cast<float4*>(xd)[idx] =
            reinterpret_cast<const float4*>(xt)[(m * FF + f) * (CC / 4) + c4];
    }
}

// =============================================================
// gemm_G tf32: per head h, G[m,c] = sum_k q2[m,h64+k]*wkv[c,h64+k]
// =============================================================
__global__ __launch_bounds__(256)
void gemm_G_tf32(const float* __restrict__ q2, const float* __restrict__ wkv,
                 float* __restrict__ G)
{
    __shared__ float As[128 * 68];
    __shared__ float Bs[128 * 68];

    const int mt = blockIdx.x, ct = blockIdx.y, h = blockIdx.z;
    const int tid = threadIdx.x;
    const int lane = tid & 31;
    const int w = tid >> 5;

    for (int i = tid; i < 128 * 16; i += 256) {
        int r = i >> 4, c4 = i & 15;
        float4 a = *reinterpret_cast<const float4*>(q2 + (size_t)(mt * 128 + r) * CC + h * DD + 4 * c4);
        float* pa = &As[r * 68 + 4 * c4];
        pa[0] = f2tf(a.x); pa[1] = f2tf(a.y); pa[2] = f2tf(a.z); pa[3] = f2tf(a.w);
        float4 bv = *reinterpret_cast<const float4*>(wkv + (size_t)(ct * 128 + r) * (2 * CC) + h * DD + 4 * c4);
        float* pb = &Bs[r * 68 + 4 * c4];
        pb[0] = f2tf(bv.x); pb[1] = f2tf(bv.y); pb[2] = f2tf(bv.z); pb[3] = f2tf(bv.w);
    }
    __syncthreads();

    const int wm = (w >> 2) * 64;
    const int wn = (w & 3) * 32;

    float acc[4][4][4];
#pragma unroll
    for (int i = 0; i < 4; i++)
#pragma unroll
        for (int j = 0; j < 4; j++)
#pragma unroll
            for (int r = 0; r < 4; r++) acc[i][j][r] = 0.f;

#pragma unroll
    for (int kb = 0; kb < 64; kb += 8) {
        uint32_t af[4][4], bf[4][2];
#pragma unroll
        for (int i = 0; i < 4; i++) {
            const float* base = &As[(wm + i * 16 + (lane >> 2)) * 68 + kb + (lane & 3)];
            af[i][0] = __float_as_uint(base[0]);
            af[i][1] = __float_as_uint(base[8 * 68]);
            af[i][2] = __float_as_uint(base[4]);
            af[i][3] = __float_as_uint(base[8 * 68 + 4]);
        }
#pragma unroll
        for (int j = 0; j < 4; j++) {
            const float* base = &Bs[(wn + j * 8 + (lane >> 2)) * 68 + kb + (lane & 3)];
            bf[j][0] = __float_as_uint(base[0]);
            bf[j][1] = __float_as_uint(base[4]);
        }
#pragma unroll
        for (int i = 0; i < 4; i++)
#pragma unroll
            for (int j = 0; j < 4; j++)
                mma_tf32(acc[i][j], af[i], bf[j]);
    }

#pragma unroll
    for (int i = 0; i < 4; i++) {
        const int rbase = mt * 128 + wm + i * 16 + (lane >> 2);
#pragma unroll
        for (int hh2 = 0; hh2 < 2; hh2++) {
            const size_t row = rbase + hh2 * 8;
            float* gp = G + (row * HH + h) * CC + ct * 128;
#pragma unroll
            for (int j = 0; j < 4; j++) {
                const int col = wn + j * 8 + (lane & 3) * 2;
                float2 r;
                r.x = acc[i][j][hh2 * 2 + 0];
                r.y = acc[i][j][hh2 * 2 + 1];
                *reinterpret_cast<float2*>(gp + col) = r;
            }
        }
    }
}

// =============================================================
// Per (b,s): scores(12x8), softmax over f, weighted sum.
// =============================================================
#define SO_SMEM ((FF*CC + HH*CC + 96 + 96) * 4)

__global__ __launch_bounds__(256)
void score_out_kernel(const float* __restrict__ xt, const float* __restrict__ G,
                      float* __restrict__ preout, float* __restrict__ attn2)
{
    extern __shared__ float sm[];
    float* xts = sm;
    float* Gs  = xts + FF * CC;
    float* sc  = Gs + HH * CC;
    float* pr  = sc + 96;

    const int bs = blockIdx.x;
    const int b = bs / SS, s = bs % SS;
    const int tid = threadIdx.x;

    for (int i = tid; i < FF * CC / 4; i += 256)
        reinterpret_cast<float4*>(xts)[i] = reinterpret_cast<const float4*>(xt)[(size_t)bs * (FF * CC / 4) + i];
    for (int i = tid; i < HH * CC / 4; i += 256)
        reinterpret_cast<float4*>(Gs)[i] = reinterpret_cast<const float4*>(G)[(size_t)bs * (HH * CC / 4) + i];
    __syncthreads();

    const int w = tid >> 5, l = tid & 31;
    for (int idx = w; idx < 96; idx += 8) {
        int h = idx >> 3, f = idx & 7;
        const float4* gp = reinterpret_cast<const float4*>(Gs + h * CC);
        const float4* xp = reinterpret_cast<const float4*>(xts + f * CC);
        float part = 0.f;
#pragma unroll
        for (int c4 = l; c4 < CC / 4; c4 += 32) {
            float4 g = gp[c4], x = xp[c4];
            part += g.x*x.x + g.y*x.y + g.z*x.z + g.w*x.w;
        }
#pragma unroll
        for (int o = 16; o > 0; o >>= 1) part += __shfl_xor_sync(0xffffffffu, part, o);
        if (l == 0) sc[idx] = part;
    }
    __syncthreads();

    if (tid < HH) {
        int h = tid;
        float mx = -1e30f;
#pragma unroll
        for (int f = 0; f < FF; f++) mx = fmaxf(mx, sc[h * 8 + f]);
        float sum = 0.f;
        float e[FF];
#pragma unroll
        for (int f = 0; f < FF; f++) { e[f] = __expf(sc[h * 8 + f] - mx); sum += e[f]; }
        float inv = 1.f / sum;
#pragma unroll
        for (int f = 0; f < FF; f++) {
            float p = e[f] * inv;
            pr[h * 8 + f] = p;
            attn2[((size_t)(b * HH + h) * SS + s) * FF + f] = p;
        }
    }
    __syncthreads();

    for (int c = tid; c < CC; c += 256) {
        int h = c >> 6;
        float v = 0.f;
#pragma unroll
        for (int f = 0; f < FF; f++) v += pr[h * 8 + f] * xts[f * CC + c];
        preout[(size_t)(b * NN + 1 + s) * CC + c] = v;
    }
}

// =============================================================
// host launch
// =============================================================
extern "C" void kernel_launch(void* const* d_in, const int* in_sizes, int n_in,
                              void* d_out, int out_size)
{
    const float* x      = (const float*)d_in[0];
    const float* w_qkv  = (const float*)d_in[1];
    const float* w_q    = (const float*)d_in[2];
    const float* w_kv   = (const float*)d_in[3];
    const float* w_proj = (const float*)d_in[4];
    const float* b_proj = (const float*)d_in[5];

    float *p_qkv, *p_xt, *p_xd, *p_q2, *p_G, *p_pre;
    cudaGetSymbolAddress((void**)&p_qkv, g_qkv);
    cudaGetSymbolAddress((void**)&p_xt,  g_xt);
    cudaGetSymbolAddress((void**)&p_xd,  g_xd);
    cudaGetSymbolAddress((void**)&p_q2,  g_q2);
    cudaGetSymbolAddress((void**)&p_G,   g_G);
    cudaGetSymbolAddress((void**)&p_pre, g_pre);

    cudaFuncSetAttribute(space_attn_kernel, cudaFuncAttributeMaxDynamicSharedMemorySize, SA_SMEM);
    cudaFuncSetAttribute(score_out_kernel,  cudaFuncAttributeMaxDynamicSharedMemorySize, SO_SMEM);

    float* outp  = (float*)d_out;
    float* attn2 = outp + OUT_ELEMS;

    // 1) qkv = x @ w_qkv   (tf32)
    gemm_tf32<false><<<dim3(N_QKV/128, (M_QKV+127)/128), 256>>>(
        x, w_qkv, p_qkv, nullptr, M_QKV, N_QKV, CC, CC, N_QKV, N_QKV, 1.f);

    // 2) cls attention -> preout rows n=0
    cls_attn_kernel<<<BATCH*HH, 256>>>(p_qkv, p_pre);

    // 3) fused space attention (tf32 QK^T + tf32 PV) -> xt
    space_attn_kernel<<<dim3((SS+63)/64, FF, BATCH*HH), 256, SA_SMEM>>>(p_qkv, p_xt);

    // 4) gather x_diag
    {
        size_t total = (size_t)M_S * (CC/4);
        gather_xdiag_kernel<<<(unsigned)((total + 255)/256), 256>>>(p_xt, p_xd);
    }

    // 5) q2 = scale * x_diag @ w_q   (tf32)
    gemm_tf32<false><<<dim3(CC/128, M_S/128), 256>>>(
        p_xd, w_q, p_q2, nullptr, M_S, CC, CC, CC, CC, CC, SCALE);

    // 6) G = per-head q2 @ Wk_h^T   (tf32 MMA)
    gemm_G_tf32<<<dim3(M_S/128, CC/128, HH), 256>>>(p_q2, w_kv, p_G);

    // 7) scores + softmax(F) -> attn2; weighted xt -> preout rows 1+s
    score_out_kernel<<<M_S, 256, SO_SMEM>>>(p_xt, p_G, p_pre, attn2);

    // 8) out = preout @ w_proj + b_proj   (tf32)
    gemm_tf32<true><<<dim3(CC/128, (M_QKV+127)/128), 256>>>(
        p_pre, w_proj, outp, b_proj, M_QKV, CC, CC, CC, CC, CC, 1.f);
}

// round 6
// speedup vs baseline: 1.8939x; 1.1103x over previous
#include <cuda_runtime.h>
#include <cuda_bf16.h>
#include <math.h>
#include <stdint.h>

// ---------------- problem constants ----------------
#define BATCH 4
#define PP    196
#define FF    8
#define CC    768
#define NN    1569          // 1 + F*P
#define SS    1568          // F*P
#define HH    12
#define DD    64
#define SCALE 0.125f        // d^-0.5

#define M_QKV   (BATCH*NN)          // 6276
#define N_QKV   (3*CC)              // 2304
#define M_S     (BATCH*SS)          // 6272
#define OUT_ELEMS ((size_t)BATCH*NN*CC)   // 4,819,968

// ---------------- scratch ----------------
__device__ float g_qkv[(size_t)M_QKV * N_QKV];        // (B,N,3C)
__device__ float g_xt [(size_t)M_S * FF * CC];        // (B,S,F,C)
__device__ float g_xd [(size_t)M_S * CC];             // x_diag (B,S,C)
__device__ float g_q2 [(size_t)M_S * CC];             // (B,S,C) scaled
__device__ float g_G  [(size_t)M_S * HH * CC];        // (B,S,h,C)
__device__ float g_pre[(size_t)M_QKV * CC];           // pre-proj (B,N,C)

// ---------------- tf32 helpers ----------------
__device__ __forceinline__ float f2tf(float x) {
    uint32_t u;
    asm("cvt.rna.tf32.f32 %0, %1;" : "=r"(u) : "f"(x));
    return __uint_as_float(u);
}

__device__ __forceinline__ void mma_tf32(float* c, const uint32_t* a, const uint32_t* b) {
    asm volatile("mma.sync.aligned.m16n8k8.row.col.f32.tf32.tf32.f32 "
        "{%0,%1,%2,%3}, {%4,%5,%6,%7}, {%8,%9}, {%0,%1,%2,%3};"
        : "+f"(c[0]), "+f"(c[1]), "+f"(c[2]), "+f"(c[3])
        : "r"(a[0]), "r"(a[1]), "r"(a[2]), "r"(a[3]), "r"(b[0]), "r"(b[1]));
}

// =============================================================
// TF32 tensor-core GEMM: C = alpha * A(MxK) @ B(KxN) (+bias).
// =============================================================
#define ALD 20
#define BLD 136

template<bool HAS_BIAS>
__global__ __launch_bounds__(256)
void gemm_tf32(const float* __restrict__ A, const float* __restrict__ Bm,
               float* __restrict__ Cm, const float* __restrict__ bias,
               int M, int N, int K, int lda, int ldb, int ldc, float alpha)
{
    __shared__ float As[2][128 * ALD];
    __shared__ float Bs[2][16 * BLD];

    const int tid  = threadIdx.x;
    const int lane = tid & 31;
    const int warp = tid >> 5;
    const int wm   = (warp >> 2) * 64;
    const int wn   = (warp & 3) * 32;
    const int m0   = blockIdx.y * 128;
    const int n0   = blockIdx.x * 128;

    const int a_row0 = tid >> 2;
    const int a_k0   = (tid & 3) * 4;
    const int b_row0 = tid >> 5;
    const int b_c0   = (tid & 31) * 4;

    float4 ra[2], rb[2];

#pragma unroll
    for (int i = 0; i < 2; i++) {
        int row = a_row0 + i * 64;
        ra[i] = (m0 + row < M) ? *(const float4*)(A + (size_t)(m0 + row) * lda + a_k0)
                               : make_float4(0.f, 0.f, 0.f, 0.f);
        rb[i] = *(const float4*)(Bm + (size_t)(b_row0 + i * 8) * ldb + n0 + b_c0);
    }
#pragma unroll
    for (int i = 0; i < 2; i++) {
        float* p = &As[0][(a_row0 + i * 64) * ALD + a_k0];
        p[0] = f2tf(ra[i].x); p[1] = f2tf(ra[i].y); p[2] = f2tf(ra[i].z); p[3] = f2tf(ra[i].w);
        float* q = &Bs[0][(b_row0 + i * 8) * BLD + b_c0];
        q[0] = f2tf(rb[i].x); q[1] = f2tf(rb[i].y); q[2] = f2tf(rb[i].z); q[3] = f2tf(rb[i].w);
    }
    __syncthreads();

    float acc[4][4][4];
#pragma unroll
    for (int i = 0; i < 4; i++)
#pragma unroll
        for (int j = 0; j < 4; j++)
#pragma unroll
            for (int r = 0; r < 4; r++) acc[i][j][r] = 0.f;

    const int ntiles = K / 16;
    for (int t = 0; t < ntiles; t++) {
        const int cur = t & 1;
        const bool more = (t + 1 < ntiles);
        if (more) {
            const int k0 = (t + 1) * 16;
#pragma unroll
            for (int i = 0; i < 2; i++) {
                int row = a_row0 + i * 64;
                ra[i] = (m0 + row < M) ? *(const float4*)(A + (size_t)(m0 + row) * lda + k0 + a_k0)
                                       : make_float4(0.f, 0.f, 0.f, 0.f);
                rb[i] = *(const float4*)(Bm + (size_t)(k0 + b_row0 + i * 8) * ldb + n0 + b_c0);
            }
        }

#pragma unroll
        for (int ks = 0; ks < 2; ks++) {
            const int kb = ks * 8;
            uint32_t af[4][4], bf[4][2];
#pragma unroll
            for (int i = 0; i < 4; i++) {
                const float* base = &As[cur][(wm + i * 16 + (lane >> 2)) * ALD + kb + (lane & 3)];
                af[i][0] = __float_as_uint(base[0]);
                af[i][1] = __float_as_uint(base[8 * ALD]);
                af[i][2] = __float_as_uint(base[4]);
                af[i][3] = __float_as_uint(base[8 * ALD + 4]);
            }
#pragma unroll
            for (int j = 0; j < 4; j++) {
                const float* base = &Bs[cur][(kb + (lane & 3)) * BLD + wn + j * 8 + (lane >> 2)];
                bf[j][0] = __float_as_uint(base[0]);
                bf[j][1] = __float_as_uint(base[4 * BLD]);
            }
#pragma unroll
            for (int i = 0; i < 4; i++)
#pragma unroll
                for (int j = 0; j < 4; j++)
                    mma_tf32(acc[i][j], af[i], bf[j]);
        }

        if (more) {
            const int nxt = (t + 1) & 1;
#pragma unroll
            for (int i = 0; i < 2; i++) {
                float* p = &As[nxt][(a_row0 + i * 64) * ALD + a_k0];
                p[0] = f2tf(ra[i].x); p[1] = f2tf(ra[i].y); p[2] = f2tf(ra[i].z); p[3] = f2tf(ra[i].w);
                float* q = &Bs[nxt][(b_row0 + i * 8) * BLD + b_c0];
                q[0] = f2tf(rb[i].x); q[1] = f2tf(rb[i].y); q[2] = f2tf(rb[i].z); q[3] = f2tf(rb[i].w);
            }
            __syncthreads();
        }
    }

#pragma unroll
    for (int i = 0; i < 4; i++) {
        const int rbase = m0 + wm + i * 16 + (lane >> 2);
#pragma unroll
        for (int h = 0; h < 2; h++) {
            const int row = rbase + h * 8;
            if (row < M) {
#pragma unroll
                for (int j = 0; j < 4; j++) {
                    const int col = n0 + wn + j * 8 + (lane & 3) * 2;
                    float2 r;
                    r.x = acc[i][j][h * 2 + 0] * alpha;
                    r.y = acc[i][j][h * 2 + 1] * alpha;
                    if (HAS_BIAS) { r.x += bias[col]; r.y += bias[col + 1]; }
                    *(float2*)(Cm + (size_t)row * ldc + col) = r;
                }
            }
        }
    }
}

// =============================================================
// CLS attention: 48 blocks (b,h).
// =============================================================
__global__ __launch_bounds__(256)
void cls_attn_kernel(const float* __restrict__ qkv, float* __restrict__ preout)
{
    __shared__ float sim[NN];
    __shared__ float qv[DD];
    __shared__ float red[256];
    __shared__ float accred[4 * DD];

    const int b = blockIdx.x / HH;
    const int h = blockIdx.x % HH;
    const int tid = threadIdx.x;

    if (tid < DD)
        qv[tid] = qkv[(size_t)(b * NN) * N_QKV + h * DD + tid] * SCALE;
    __syncthreads();

    for (int n = tid; n < NN; n += 256) {
        const float* kp = qkv + (size_t)(b * NN + n) * N_QKV + CC + h * DD;
        float d = 0.f;
#pragma unroll
        for (int c4 = 0; c4 < DD / 4; c4++) {
            float4 k4 = *reinterpret_cast<const float4*>(kp + c4 * 4);
            d += qv[c4*4+0]*k4.x + qv[c4*4+1]*k4.y + qv[c4*4+2]*k4.z + qv[c4*4+3]*k4.w;
        }
        sim[n] = d;
    }
    __syncthreads();

    float m = -1e30f;
    for (int n = tid; n < NN; n += 256) m = fmaxf(m, sim[n]);
    red[tid] = m; __syncthreads();
    for (int o = 128; o > 0; o >>= 1) { if (tid < o) red[tid] = fmaxf(red[tid], red[tid+o]); __syncthreads(); }
    const float mx = red[0];
    __syncthreads();

    float s = 0.f;
    for (int n = tid; n < NN; n += 256) { float e = __expf(sim[n] - mx); sim[n] = e; s += e; }
    red[tid] = s; __syncthreads();
    for (int o = 128; o > 0; o >>= 1) { if (tid < o) red[tid] += red[tid+o]; __syncthreads(); }
    const float inv = 1.f / red[0];
    __syncthreads();

    const int g = tid >> 6, dd = tid & 63;
    float a = 0.f;
    for (int n = g; n < NN; n += 4)
        a += sim[n] * qkv[(size_t)(b * NN + n) * N_QKV + 2 * CC + h * DD + dd];
    accred[g * DD + dd] = a;
    __syncthreads();
    if (tid < DD)
        preout[(size_t)(b * NN) * CC + h * DD + tid] =
            (accred[tid] + accred[DD + tid] + accred[2*DD + tid] + accred[3*DD + tid]) * inv;
}

// =============================================================
// Space attention v3: 128-row q-tiles, QK^T + PV both tf32 MMA.
// Also emits x_diag rows (f == sq/P) to xd, replacing gather.
// smem layout (floats):
//   region A [0 .. 27136): Qsm[128][68] @0, Ksm[208][68] @8704,
//                          then Sc[128][212] overlays @0
//   Vt[64][212] @27136
// block = (qtile 0..12, f 0..7, bh 0..47), 256 thr (8 warps).
// =============================================================
#define SA_QLD 68
#define SA_KLD 68
#define SC_LD  212
#define VT_LD  212
#define K_OFF  (128 * SA_QLD)            // 8704
#define REGION_A (128 * SC_LD)           // 27136
#define VT_OFF REGION_A
#define SA_SMEM ((REGION_A + 64 * VT_LD) * 4)   // 162816 B

__global__ __launch_bounds__(256)
void space_attn_kernel(const float* __restrict__ qkv, float* __restrict__ xt,
                       float* __restrict__ xd)
{
    extern __shared__ float sm[];
    float* Qsm = sm;                 // 128 x 68 (tf32)
    float* Ksm = sm + K_OFF;         // 208 x 68 (tf32, rows 196..207 zero)
    float* Sc  = sm;                 // 128 x 212 (overlays Q+K after phase 1)
    float* Vt  = sm + VT_OFF;        // 64 x 212 (dv, p) tf32, cols 196..207 zero

    const int bh = blockIdx.z;
    const int b = bh / HH, h = bh % HH;
    const int f = blockIdx.y;
    const int q0 = blockIdx.x * 128;
    const int tid = threadIdx.x;
    const int w = tid >> 5, lane = tid & 31;

    // ---- loads ----
    for (int i = tid; i < 208 * 16; i += 256) {
        int r = i >> 4, c4 = i & 15;
        float* kp = &Ksm[r * SA_KLD + c4 * 4];
        if (r < 196) {
            size_t base = (size_t)(b * NN + 1 + f * PP + r) * N_QKV + h * DD + c4 * 4;
            float4 kv = *reinterpret_cast<const float4*>(qkv + base + CC);
            kp[0] = f2tf(kv.x); kp[1] = f2tf(kv.y); kp[2] = f2tf(kv.z); kp[3] = f2tf(kv.w);
            float4 vv = *reinterpret_cast<const float4*>(qkv + base + 2 * CC);
            Vt[(4 * c4 + 0) * VT_LD + r] = f2tf(vv.x);
            Vt[(4 * c4 + 1) * VT_LD + r] = f2tf(vv.y);
            Vt[(4 * c4 + 2) * VT_LD + r] = f2tf(vv.z);
            Vt[(4 * c4 + 3) * VT_LD + r] = f2tf(vv.w);
        } else {
            kp[0] = 0.f; kp[1] = 0.f; kp[2] = 0.f; kp[3] = 0.f;
        }
    }
    // zero Vt pad columns p=196..211
    for (int i = tid; i < 64 * 16; i += 256) {
        int dv = i >> 4, p = 196 + (i & 15);
        Vt[dv * VT_LD + p] = 0.f;
    }
    // Q tile 128 rows (tf32), zero rows beyond SS
    for (int i = tid; i < 128 * 16; i += 256) {
        int r = i >> 4, c4 = i & 15;
        int sq = q0 + r;
        float4 qv = make_float4(0.f, 0.f, 0.f, 0.f);
        if (sq < SS)
            qv = *reinterpret_cast<const float4*>(qkv + (size_t)(b * NN + 1 + sq) * N_QKV + h * DD + c4 * 4);
        float* qp = &Qsm[r * SA_QLD + c4 * 4];
        qp[0] = f2tf(qv.x); qp[1] = f2tf(qv.y); qp[2] = f2tf(qv.z); qp[3] = f2tf(qv.w);
    }
    __syncthreads();

    // ---- phase 1: S[128][208] = Q @ K^T (tf32 MMA) ----
    const int mrow = w * 16;
    float acc[26][4];
#pragma unroll
    for (int nt = 0; nt < 26; nt++)
#pragma unroll
        for (int r = 0; r < 4; r++) acc[nt][r] = 0.f;

#pragma unroll
    for (int kb = 0; kb < 64; kb += 8) {
        uint32_t a[4];
        const float* ab = &Qsm[(mrow + (lane >> 2)) * SA_QLD + kb + (lane & 3)];
        a[0] = __float_as_uint(ab[0]);
        a[1] = __float_as_uint(ab[8 * SA_QLD]);
        a[2] = __float_as_uint(ab[4]);
        a[3] = __float_as_uint(ab[8 * SA_QLD + 4]);
#pragma unroll
        for (int nt = 0; nt < 26; nt++) {
            uint32_t bfr[2];
            const float* bb = &Ksm[(nt * 8 + (lane >> 2)) * SA_KLD + kb + (lane & 3)];
            bfr[0] = __float_as_uint(bb[0]);
            bfr[1] = __float_as_uint(bb[4]);
            mma_tf32(acc[nt], a, bfr);
        }
    }
    __syncthreads();   // Q/K reads done; Sc overlays them

    // store scaled scores; zero Sc pad cols 196..211
    {
        const int r0 = mrow + (lane >> 2);
#pragma unroll
        for (int nt = 0; nt < 26; nt++) {
            int col = nt * 8 + (lane & 3) * 2;
            if (col < 196) {
                Sc[r0 * SC_LD + col]       = acc[nt][0] * SCALE;
                Sc[r0 * SC_LD + col + 1]   = acc[nt][1] * SCALE;
                Sc[(r0 + 8) * SC_LD + col]     = acc[nt][2] * SCALE;
                Sc[(r0 + 8) * SC_LD + col + 1] = acc[nt][3] * SCALE;
            }
        }
        for (int i = tid; i < 128 * 16; i += 256) {
            int r = i >> 4, p = 196 + (i & 15);
            Sc[r * SC_LD + p] = 0.f;
        }
    }
    __syncthreads();

    // ---- phase 2: softmax over p (196) per q row (16 rows/warp) ----
#pragma unroll
    for (int qi = 0; qi < 16; qi++) {
        const int q = mrow + qi;
        float v[7];
        float mx = -1e30f;
#pragma unroll
        for (int j = 0; j < 7; j++) {
            int p = lane + 32 * j;
            v[j] = (p < 196) ? Sc[q * SC_LD + p] : -1e30f;
            mx = fmaxf(mx, v[j]);
        }
#pragma unroll
        for (int o = 16; o > 0; o >>= 1) mx = fmaxf(mx, __shfl_xor_sync(0xffffffffu, mx, o));
        float sum = 0.f;
#pragma unroll
        for (int j = 0; j < 7; j++) {
            int p = lane + 32 * j;
            float e = (p < 196) ? __expf(v[j] - mx) : 0.f;
            v[j] = e; sum += e;
        }
#pragma unroll
        for (int o = 16; o > 0; o >>= 1) sum += __shfl_xor_sync(0xffffffffu, sum, o);
        float inv = 1.f / sum;
#pragma unroll
        for (int j = 0; j < 7; j++) {
            int p = lane + 32 * j;
            if (p < 196) Sc[q * SC_LD + p] = f2tf(v[j] * inv);
        }
    }
    __syncthreads();

    // ---- phase 3: out[128][64] = Sc @ Vt^T (tf32 MMA) ----
    {
        float o2[8][4];
#pragma unroll
        for (int j = 0; j < 8; j++)
#pragma unroll
            for (int r = 0; r < 4; r++) o2[j][r] = 0.f;

#pragma unroll
        for (int kb = 0; kb < 208; kb += 8) {
            uint32_t a[4];
            const float* ab = &Sc[(mrow + (lane >> 2)) * SC_LD + kb + (lane & 3)];
            a[0] = __float_as_uint(ab[0]);
            a[1] = __float_as_uint(ab[8 * SC_LD]);
            a[2] = __float_as_uint(ab[4]);
            a[3] = __float_as_uint(ab[8 * SC_LD + 4]);
#pragma unroll
            for (int j = 0; j < 8; j++) {
                uint32_t bfr[2];
                const float* bb = &Vt[(j * 8 + (lane >> 2)) * VT_LD + kb + (lane & 3)];
                bfr[0] = __float_as_uint(bb[0]);
                bfr[1] = __float_as_uint(bb[4]);
                mma_tf32(o2[j], a, bfr);
            }
        }

        // epilogue: write xt (+ x_diag rows when f == sq/P)
        const int r0 = mrow + (lane >> 2);
#pragma unroll
        for (int hh2 = 0; hh2 < 2; hh2++) {
            const int sq = q0 + r0 + hh2 * 8;
            if (sq < SS) {
                float* xp = xt + ((size_t)(b * SS + sq) * FF + f) * CC + h * DD;
                const bool diag = (sq / PP == f);
                float* dp = xd + (size_t)(b * SS + sq) * CC + h * DD;
#pragma unroll
                for (int j = 0; j < 8; j++) {
                    const int dv = j * 8 + (lane & 3) * 2;
                    float2 r;
                    r.x = o2[j][hh2 * 2 + 0];
                    r.y = o2[j][hh2 * 2 + 1];
                    *reinterpret_cast<float2*>(xp + dv) = r;
                    if (diag) *reinterpret_cast<float2*>(dp + dv) = r;
                }
            }
        }
    }
}

// =============================================================
// gemm_G tf32: per head h, G[m,c] = sum_k q2[m,h64+k]*wkv[c,h64+k]
// =============================================================
__global__ __launch_bounds__(256)
void gemm_G_tf32(const float* __restrict__ q2, const float* __restrict__ wkv,
                 float* __restrict__ G)
{
    __shared__ float As[128 * 68];
    __shared__ float Bs[128 * 68];

    const int mt = blockIdx.x, ct = blockIdx.y, h = blockIdx.z;
    const int tid = threadIdx.x;
    const int lane = tid & 31;
    const int w = tid >> 5;

    for (int i = tid; i < 128 * 16; i += 256) {
        int r = i >> 4, c4 = i & 15;
        float4 a = *reinterpret_cast<const float4*>(q2 + (size_t)(mt * 128 + r) * CC + h * DD + 4 * c4);
        float* pa = &As[r * 68 + 4 * c4];
        pa[0] = f2tf(a.x); pa[1] = f2tf(a.y); pa[2] = f2tf(a.z); pa[3] = f2tf(a.w);
        float4 bv = *reinterpret_cast<const float4*>(wkv + (size_t)(ct * 128 + r) * (2 * CC) + h * DD + 4 * c4);
        float* pb = &Bs[r * 68 + 4 * c4];
        pb[0] = f2tf(bv.x); pb[1] = f2tf(bv.y); pb[2] = f2tf(bv.z); pb[3] = f2tf(bv.w);
    }
    __syncthreads();

    const int wm = (w >> 2) * 64;
    const int wn = (w & 3) * 32;

    float acc[4][4][4];
#pragma unroll
    for (int i = 0; i < 4; i++)
#pragma unroll
        for (int j = 0; j < 4; j++)
#pragma unroll
            for (int r = 0; r < 4; r++) acc[i][j][r] = 0.f;

#pragma unroll
    for (int kb = 0; kb < 64; kb += 8) {
        uint32_t af[4][4], bf[4][2];
#pragma unroll
        for (int i = 0; i < 4; i++) {
            const float* base = &As[(wm + i * 16 + (lane >> 2)) * 68 + kb + (lane & 3)];
            af[i][0] = __float_as_uint(base[0]);
            af[i][1] = __float_as_uint(base[8 * 68]);
            af[i][2] = __float_as_uint(base[4]);
            af[i][3] = __float_as_uint(base[8 * 68 + 4]);
        }
#pragma unroll
        for (int j = 0; j < 4; j++) {
            const float* base = &Bs[(wn + j * 8 + (lane >> 2)) * 68 + kb + (lane & 3)];
            bf[j][0] = __float_as_uint(base[0]);
            bf[j][1] = __float_as_uint(base[4]);
        }
#pragma unroll
        for (int i = 0; i < 4; i++)
#pragma unroll
            for (int j = 0; j < 4; j++)
                mma_tf32(acc[i][j], af[i], bf[j]);
    }

#pragma unroll
    for (int i = 0; i < 4; i++) {
        const int rbase = mt * 128 + wm + i * 16 + (lane >> 2);
#pragma unroll
        for (int hh2 = 0; hh2 < 2; hh2++) {
            const size_t row = rbase + hh2 * 8;
            float* gp = G + (row * HH + h) * CC + ct * 128;
#pragma unroll
            for (int j = 0; j < 4; j++) {
                const int col = wn + j * 8 + (lane & 3) * 2;
                float2 r;
                r.x = acc[i][j][hh2 * 2 + 0];
                r.y = acc[i][j][hh2 * 2 + 1];
                *reinterpret_cast<float2*>(gp + col) = r;
            }
        }
    }
}

// =============================================================
// Per (b,s): scores(12x8), softmax over f, weighted sum.
// =============================================================
#define SO_SMEM ((FF*CC + HH*CC + 96 + 96) * 4)

__global__ __launch_bounds__(256)
void score_out_kernel(const float* __restrict__ xt, const float* __restrict__ G,
                      float* __restrict__ preout, float* __restrict__ attn2)
{
    extern __shared__ float sm[];
    float* xts = sm;
    float* Gs  = xts + FF * CC;
    float* sc  = Gs + HH * CC;
    float* pr  = sc + 96;

    const int bs = blockIdx.x;
    const int b = bs / SS, s = bs % SS;
    const int tid = threadIdx.x;

    for (int i = tid; i < FF * CC / 4; i += 256)
        reinterpret_cast<float4*>(xts)[i] = reinterpret_cast<const float4*>(xt)[(size_t)bs * (FF * CC / 4) + i];
    for (int i = tid; i < HH * CC / 4; i += 256)
        reinterpret_cast<float4*>(Gs)[i] = reinterpret_cast<const float4*>(G)[(size_t)bs * (HH * CC / 4) + i];
    __syncthreads();

    const int w = tid >> 5, l = tid & 31;
    for (int idx = w; idx < 96; idx += 8) {
        int h = idx >> 3, f = idx & 7;
        const float4* gp = reinterpret_cast<const float4*>(Gs + h * CC);
        const float4* xp = reinterpret_cast<const float4*>(xts + f * CC);
        float part = 0.f;
#pragma unroll
        for (int c4 = l; c4 < CC / 4; c4 += 32) {
            float4 g = gp[c4], x = xp[c4];
            part += g.x*x.x + g.y*x.y + g.z*x.z + g.w*x.w;
        }
#pragma unroll
        for (int o = 16; o > 0; o >>= 1) part += __shfl_xor_sync(0xffffffffu, part, o);
        if (l == 0) sc[idx] = part;
    }
    __syncthreads();

    if (tid < HH) {
        int h = tid;
        float mx = -1e30f;
#pragma unroll
        for (int f = 0; f < FF; f++) mx = fmaxf(mx, sc[h * 8 + f]);
        float sum = 0.f;
        float e[FF];
#pragma unroll
        for (int f = 0; f < FF; f++) { e[f] = __expf(sc[h * 8 + f] - mx); sum += e[f]; }
        float inv = 1.f / sum;
#pragma unroll
        for (int f = 0; f < FF; f++) {
            float p = e[f] * inv;
            pr[h * 8 + f] = p;
            attn2[((size_t)(b * HH + h) * SS + s) * FF + f] = p;
        }
    }
    __syncthreads();

    for (int c = tid; c < CC; c += 256) {
        int h = c >> 6;
        float v = 0.f;
#pragma unroll
        for (int f = 0; f < FF; f++) v += pr[h * 8 + f] * xts[f * CC + c];
        preout[(size_t)(b * NN + 1 + s) * CC + c] = v;
    }
}

// =============================================================
// host launch
// =============================================================
extern "C" void kernel_launch(void* const* d_in, const int* in_sizes, int n_in,
                              void* d_out, int out_size)
{
    const float* x      = (const float*)d_in[0];
    const float* w_qkv  = (const float*)d_in[1];
    const float* w_q    = (const float*)d_in[2];
    const float* w_kv   = (const float*)d_in[3];
    const float* w_proj = (const float*)d_in[4];
    const float* b_proj = (const float*)d_in[5];

    float *p_qkv, *p_xt, *p_xd, *p_q2, *p_G, *p_pre;
    cudaGetSymbolAddress((void**)&p_qkv, g_qkv);
    cudaGetSymbolAddress((void**)&p_xt,  g_xt);
    cudaGetSymbolAddress((void**)&p_xd,  g_xd);
    cudaGetSymbolAddress((void**)&p_q2,  g_q2);
    cudaGetSymbolAddress((void**)&p_G,   g_G);
    cudaGetSymbolAddress((void**)&p_pre, g_pre);

    cudaFuncSetAttribute(space_attn_kernel, cudaFuncAttributeMaxDynamicSharedMemorySize, SA_SMEM);
    cudaFuncSetAttribute(score_out_kernel,  cudaFuncAttributeMaxDynamicSharedMemorySize, SO_SMEM);

    float* outp  = (float*)d_out;
    float* attn2 = outp + OUT_ELEMS;

    // 1) qkv = x @ w_qkv   (tf32)
    gemm_tf32<false><<<dim3(N_QKV/128, (M_QKV+127)/128), 256>>>(
        x, w_qkv, p_qkv, nullptr, M_QKV, N_QKV, CC, CC, N_QKV, N_QKV, 1.f);

    // 2) cls attention -> preout rows n=0
    cls_attn_kernel<<<BATCH*HH, 256>>>(p_qkv, p_pre);

    // 3) fused space attention (tf32 QK^T + tf32 PV, 128-row q tiles)
    //    also writes x_diag rows -> xd
    space_attn_kernel<<<dim3((SS+127)/128, FF, BATCH*HH), 256, SA_SMEM>>>(p_qkv, p_xt, p_xd);

    // 4) q2 = scale * x_diag @ w_q   (tf32)
    gemm_tf32<false><<<dim3(CC/128, M_S/128), 256>>>(
        p_xd, w_q, p_q2, nullptr, M_S, CC, CC, CC, CC, CC, SCALE);

    // 5) G = per-head q2 @ Wk_h^T   (tf32 MMA)
    gemm_G_tf32<<<dim3(M_S/128, CC/128, HH), 256>>>(p_q2, w_kv, p_G);

    // 6) scores + softmax(F) -> attn2; weighted xt -> preout rows 1+s
    score_out_kernel<<<M_S, 256, SO_SMEM>>>(p_xt, p_G, p_pre, attn2);

    // 7) out = preout @ w_proj + b_proj   (tf32)
    gemm_tf32<true><<<dim3(CC/128, (M_QKV+127)/128), 256>>>(
        p_pre, w_proj, outp, b_proj, M_QKV, CC, CC, CC, CC, CC, 1.f);
}

// round 7
// speedup vs baseline: 1.9636x; 1.0368x over previous
#include <cuda_runtime.h>
#include <cuda_bf16.h>
#include <math.h>
#include <stdint.h>

// ---------------- problem constants ----------------
#define BATCH 4
#define PP    196
#define FF    8
#define CC    768
#define NN    1569          // 1 + F*P
#define SS    1568          // F*P
#define HH    12
#define DD    64
#define SCALE 0.125f        // d^-0.5

#define M_QKV   (BATCH*NN)          // 6276
#define N_QKV   (3*CC)              // 2304
#define M_S     (BATCH*SS)          // 6272
#define OUT_ELEMS ((size_t)BATCH*NN*CC)   // 4,819,968

// ---------------- scratch ----------------
__device__ float g_qkv[(size_t)M_QKV * N_QKV];        // (B,N,3C) tf32-rounded
__device__ float g_xt [(size_t)M_S * FF * CC];        // (B,S,F,C)
__device__ float g_xd [(size_t)M_S * CC];             // x_diag (B,S,C)
__device__ float g_q2 [(size_t)M_S * CC];             // (B,S,C) scaled, tf32-rounded
__device__ float g_G  [(size_t)M_S * HH * CC];        // (B,S,h,C)
__device__ float g_pre[(size_t)M_QKV * CC];           // pre-proj (B,N,C)

// ---------------- tf32 helpers ----------------
__device__ __forceinline__ float f2tf(float x) {
    uint32_t u;
    asm("cvt.rna.tf32.f32 %0, %1;" : "=r"(u) : "f"(x));
    return __uint_as_float(u);
}

__device__ __forceinline__ void mma_tf32(float* c, const uint32_t* a, const uint32_t* b) {
    asm volatile("mma.sync.aligned.m16n8k8.row.col.f32.tf32.tf32.f32 "
        "{%0,%1,%2,%3}, {%4,%5,%6,%7}, {%8,%9}, {%0,%1,%2,%3};"
        : "+f"(c[0]), "+f"(c[1]), "+f"(c[2]), "+f"(c[3])
        : "r"(a[0]), "r"(a[1]), "r"(a[2]), "r"(a[3]), "r"(b[0]), "r"(b[1]));
}

// =============================================================
// TF32 GEMM v2: block 128x256x16, 8 warps, warp tile 64x64.
// C = alpha*A@B (+bias), optional tf32-rounded output.
// N%256==0, K%16==0. Dynamic smem.
// =============================================================
#define ALD 20      // As row stride
#define BLD 264     // Bs row stride (256+8; stride%32==8 -> conflict-free)
#define AS_FLOATS (128 * ALD)          // 2560
#define BS_FLOATS (16 * BLD)           // 4224
#define GT_SMEM ((2 * AS_FLOATS + 2 * BS_FLOATS) * 4)   // 54272 B

template<bool HAS_BIAS, bool ROUND_OUT>
__global__ __launch_bounds__(256)
void gemm_tf32(const float* __restrict__ A, const float* __restrict__ Bm,
               float* __restrict__ Cm, const float* __restrict__ bias,
               int M, int N, int K, int lda, int ldb, int ldc, float alpha)
{
    extern __shared__ float smg[];
    float* As0 = smg;
    float* As1 = smg + AS_FLOATS;
    float* Bs0 = smg + 2 * AS_FLOATS;
    float* Bs1 = Bs0 + BS_FLOATS;

    const int tid  = threadIdx.x;
    const int lane = tid & 31;
    const int warp = tid >> 5;
    const int wm   = (warp & 1) * 64;        // 2 warps in m
    const int wn   = (warp >> 1) * 64;       // 4 warps in n
    const int m0   = blockIdx.y * 128;
    const int n0   = blockIdx.x * 256;

    const int a_row0 = tid >> 2;             // +64
    const int a_k0   = (tid & 3) * 4;
    const int b_row0 = tid >> 6;             // +4i
    const int b_c0   = (tid & 63) * 4;

    float4 ra[2], rb[4];

    // ---- load tile 0 ----
#pragma unroll
    for (int i = 0; i < 2; i++) {
        int row = a_row0 + i * 64;
        ra[i] = (m0 + row < M) ? *(const float4*)(A + (size_t)(m0 + row) * lda + a_k0)
                               : make_float4(0.f, 0.f, 0.f, 0.f);
    }
#pragma unroll
    for (int i = 0; i < 4; i++)
        rb[i] = *(const float4*)(Bm + (size_t)(b_row0 + i * 4) * ldb + n0 + b_c0);

#pragma unroll
    for (int i = 0; i < 2; i++) {
        float* p = &As0[(a_row0 + i * 64) * ALD + a_k0];
        p[0] = f2tf(ra[i].x); p[1] = f2tf(ra[i].y); p[2] = f2tf(ra[i].z); p[3] = f2tf(ra[i].w);
    }
#pragma unroll
    for (int i = 0; i < 4; i++) {
        float* q = &Bs0[(b_row0 + i * 4) * BLD + b_c0];
        q[0] = f2tf(rb[i].x); q[1] = f2tf(rb[i].y); q[2] = f2tf(rb[i].z); q[3] = f2tf(rb[i].w);
    }
    __syncthreads();

    float acc[4][8][4];
#pragma unroll
    for (int i = 0; i < 4; i++)
#pragma unroll
        for (int j = 0; j < 8; j++)
#pragma unroll
            for (int r = 0; r < 4; r++) acc[i][j][r] = 0.f;

    const int ntiles = K / 16;
    for (int t = 0; t < ntiles; t++) {
        float* Asc = (t & 1) ? As1 : As0;
        float* Bsc = (t & 1) ? Bs1 : Bs0;
        const bool more = (t + 1 < ntiles);
        if (more) {
            const int k0 = (t + 1) * 16;
#pragma unroll
            for (int i = 0; i < 2; i++) {
                int row = a_row0 + i * 64;
                ra[i] = (m0 + row < M) ? *(const float4*)(A + (size_t)(m0 + row) * lda + k0 + a_k0)
                                       : make_float4(0.f, 0.f, 0.f, 0.f);
            }
#pragma unroll
            for (int i = 0; i < 4; i++)
                rb[i] = *(const float4*)(Bm + (size_t)(k0 + b_row0 + i * 4) * ldb + n0 + b_c0);
        }

#pragma unroll
        for (int ks = 0; ks < 2; ks++) {
            const int kb = ks * 8;
            uint32_t af[4][4];
#pragma unroll
            for (int i = 0; i < 4; i++) {
                const float* base = &Asc[(wm + i * 16 + (lane >> 2)) * ALD + kb + (lane & 3)];
                af[i][0] = __float_as_uint(base[0]);
                af[i][1] = __float_as_uint(base[8 * ALD]);
                af[i][2] = __float_as_uint(base[4]);
                af[i][3] = __float_as_uint(base[8 * ALD + 4]);
            }
#pragma unroll
            for (int j = 0; j < 8; j++) {
                uint32_t bf[2];
                const float* base = &Bsc[(kb + (lane & 3)) * BLD + wn + j * 8 + (lane >> 2)];
                bf[0] = __float_as_uint(base[0]);
                bf[1] = __float_as_uint(base[4 * BLD]);
#pragma unroll
                for (int i = 0; i < 4; i++)
                    mma_tf32(acc[i][j], af[i], bf);
            }
        }

        if (more) {
            float* Asn = (t & 1) ? As0 : As1;
            float* Bsn = (t & 1) ? Bs0 : Bs1;
#pragma unroll
            for (int i = 0; i < 2; i++) {
                float* p = &Asn[(a_row0 + i * 64) * ALD + a_k0];
                p[0] = f2tf(ra[i].x); p[1] = f2tf(ra[i].y); p[2] = f2tf(ra[i].z); p[3] = f2tf(ra[i].w);
            }
#pragma unroll
            for (int i = 0; i < 4; i++) {
                float* q = &Bsn[(b_row0 + i * 4) * BLD + b_c0];
                q[0] = f2tf(rb[i].x); q[1] = f2tf(rb[i].y); q[2] = f2tf(rb[i].z); q[3] = f2tf(rb[i].w);
            }
            __syncthreads();
        }
    }

    // ---- epilogue ----
#pragma unroll
    for (int i = 0; i < 4; i++) {
        const int rbase = m0 + wm + i * 16 + (lane >> 2);
#pragma unroll
        for (int h = 0; h < 2; h++) {
            const int row = rbase + h * 8;
            if (row < M) {
#pragma unroll
                for (int j = 0; j < 8; j++) {
                    const int col = n0 + wn + j * 8 + (lane & 3) * 2;
                    float2 r;
                    r.x = acc[i][j][h * 2 + 0] * alpha;
                    r.y = acc[i][j][h * 2 + 1] * alpha;
                    if (HAS_BIAS) { r.x += bias[col]; r.y += bias[col + 1]; }
                    if (ROUND_OUT) { r.x = f2tf(r.x); r.y = f2tf(r.y); }
                    *(float2*)(Cm + (size_t)row * ldc + col) = r;
                }
            }
        }
    }
}

// =============================================================
// CLS attention: 48 blocks (b,h).  (qkv now tf32-rounded; fine.)
// =============================================================
__global__ __launch_bounds__(256)
void cls_attn_kernel(const float* __restrict__ qkv, float* __restrict__ preout)
{
    __shared__ float sim[NN];
    __shared__ float qv[DD];
    __shared__ float red[256];
    __shared__ float accred[4 * DD];

    const int b = blockIdx.x / HH;
    const int h = blockIdx.x % HH;
    const int tid = threadIdx.x;

    if (tid < DD)
        qv[tid] = qkv[(size_t)(b * NN) * N_QKV + h * DD + tid] * SCALE;
    __syncthreads();

    for (int n = tid; n < NN; n += 256) {
        const float* kp = qkv + (size_t)(b * NN + n) * N_QKV + CC + h * DD;
        float d = 0.f;
#pragma unroll
        for (int c4 = 0; c4 < DD / 4; c4++) {
            float4 k4 = *reinterpret_cast<const float4*>(kp + c4 * 4);
            d += qv[c4*4+0]*k4.x + qv[c4*4+1]*k4.y + qv[c4*4+2]*k4.z + qv[c4*4+3]*k4.w;
        }
        sim[n] = d;
    }
    __syncthreads();

    float m = -1e30f;
    for (int n = tid; n < NN; n += 256) m = fmaxf(m, sim[n]);
    red[tid] = m; __syncthreads();
    for (int o = 128; o > 0; o >>= 1) { if (tid < o) red[tid] = fmaxf(red[tid], red[tid+o]); __syncthreads(); }
    const float mx = red[0];
    __syncthreads();

    float s = 0.f;
    for (int n = tid; n < NN; n += 256) { float e = __expf(sim[n] - mx); sim[n] = e; s += e; }
    red[tid] = s; __syncthreads();
    for (int o = 128; o > 0; o >>= 1) { if (tid < o) red[tid] += red[tid+o]; __syncthreads(); }
    const float inv = 1.f / red[0];
    __syncthreads();

    const int g = tid >> 6, dd = tid & 63;
    float a = 0.f;
    for (int n = g; n < NN; n += 4)
        a += sim[n] * qkv[(size_t)(b * NN + n) * N_QKV + 2 * CC + h * DD + dd];
    accred[g * DD + dd] = a;
    __syncthreads();
    if (tid < DD)
        preout[(size_t)(b * NN) * CC + h * DD + tid] =
            (accred[tid] + accred[DD + tid] + accred[2*DD + tid] + accred[3*DD + tid]) * inv;
}

// =============================================================
// Space attention v4: 128-row q-tiles; fatter warp tiles.
// qkv pre-rounded -> plain float4 smem fills.
// phase1 warps (4m,2n): 32x104; phase3 warps (4m,2n): 32x32.
// =============================================================
#define SA_QLD 68
#define SA_KLD 68
#define SC_LD  212
#define VT_LD  212
#define K_OFF  (128 * SA_QLD)            // 8704
#define REGION_A (128 * SC_LD)           // 27136
#define VT_OFF REGION_A
#define SA_SMEM ((REGION_A + 64 * VT_LD) * 4)   // 162816 B

__global__ __launch_bounds__(256)
void space_attn_kernel(const float* __restrict__ qkv, float* __restrict__ xt,
                       float* __restrict__ xd)
{
    extern __shared__ float sm[];
    float* Qsm = sm;                 // 128 x 68
    float* Ksm = sm + K_OFF;         // 208 x 68 (rows 196..207 zero)
    float* Sc  = sm;                 // 128 x 212 overlays Q+K after phase 1
    float* Vt  = sm + VT_OFF;        // 64 x 212 (dv, p), cols 196..211 zero

    const int bh = blockIdx.z;
    const int b = bh / HH, h = bh % HH;
    const int f = blockIdx.y;
    const int q0 = blockIdx.x * 128;
    const int tid = threadIdx.x;
    const int w = tid >> 5, lane = tid & 31;

    // ---- loads (no cvt; qkv already tf32-rounded) ----
    for (int i = tid; i < 208 * 16; i += 256) {
        int r = i >> 4, c4 = i & 15;
        if (r < 196) {
            size_t base = (size_t)(b * NN + 1 + f * PP + r) * N_QKV + h * DD + c4 * 4;
            *reinterpret_cast<float4*>(&Ksm[r * SA_KLD + c4 * 4]) =
                *reinterpret_cast<const float4*>(qkv + base + CC);
            float4 vv = *reinterpret_cast<const float4*>(qkv + base + 2 * CC);
            Vt[(4 * c4 + 0) * VT_LD + r] = vv.x;
            Vt[(4 * c4 + 1) * VT_LD + r] = vv.y;
            Vt[(4 * c4 + 2) * VT_LD + r] = vv.z;
            Vt[(4 * c4 + 3) * VT_LD + r] = vv.w;
        } else {
            *reinterpret_cast<float4*>(&Ksm[r * SA_KLD + c4 * 4]) = make_float4(0.f,0.f,0.f,0.f);
        }
    }
    for (int i = tid; i < 64 * 16; i += 256) {
        int dv = i >> 4, p = 196 + (i & 15);
        Vt[dv * VT_LD + p] = 0.f;
    }
    for (int i = tid; i < 128 * 16; i += 256) {
        int r = i >> 4, c4 = i & 15;
        int sq = q0 + r;
        float4 qv = make_float4(0.f, 0.f, 0.f, 0.f);
        if (sq < SS)
            qv = *reinterpret_cast<const float4*>(qkv + (size_t)(b * NN + 1 + sq) * N_QKV + h * DD + c4 * 4);
        *reinterpret_cast<float4*>(&Qsm[r * SA_QLD + c4 * 4]) = qv;
    }
    __syncthreads();

    // ---- phase 1: S[128][208] = Q @ K^T, warp tile 32x104 ----
    const int mrow1  = (w >> 1) * 32;
    const int nbase1 = (w & 1) * 104;
    float acc[2][13][4];
#pragma unroll
    for (int mi = 0; mi < 2; mi++)
#pragma unroll
        for (int nt = 0; nt < 13; nt++)
#pragma unroll
            for (int r = 0; r < 4; r++) acc[mi][nt][r] = 0.f;

#pragma unroll
    for (int kb = 0; kb < 64; kb += 8) {
        uint32_t af[2][4];
#pragma unroll
        for (int mi = 0; mi < 2; mi++) {
            const float* ab = &Qsm[(mrow1 + mi * 16 + (lane >> 2)) * SA_QLD + kb + (lane & 3)];
            af[mi][0] = __float_as_uint(ab[0]);
            af[mi][1] = __float_as_uint(ab[8 * SA_QLD]);
            af[mi][2] = __float_as_uint(ab[4]);
            af[mi][3] = __float_as_uint(ab[8 * SA_QLD + 4]);
        }
#pragma unroll
        for (int nt = 0; nt < 13; nt++) {
            uint32_t bfr[2];
            const float* bb = &Ksm[(nbase1 + nt * 8 + (lane >> 2)) * SA_KLD + kb + (lane & 3)];
            bfr[0] = __float_as_uint(bb[0]);
            bfr[1] = __float_as_uint(bb[4]);
#pragma unroll
            for (int mi = 0; mi < 2; mi++)
                mma_tf32(acc[mi][nt], af[mi], bfr);
        }
    }
    __syncthreads();   // Q/K reads done; Sc overlays them

    // store scaled scores; zero pad cols
    {
#pragma unroll
        for (int mi = 0; mi < 2; mi++) {
            const int r0 = mrow1 + mi * 16 + (lane >> 2);
#pragma unroll
            for (int nt = 0; nt < 13; nt++) {
                int col = nbase1 + nt * 8 + (lane & 3) * 2;
                if (col < 196) {
                    Sc[r0 * SC_LD + col]       = acc[mi][nt][0] * SCALE;
                    Sc[r0 * SC_LD + col + 1]   = acc[mi][nt][1] * SCALE;
                    Sc[(r0 + 8) * SC_LD + col]     = acc[mi][nt][2] * SCALE;
                    Sc[(r0 + 8) * SC_LD + col + 1] = acc[mi][nt][3] * SCALE;
                }
            }
        }
        for (int i = tid; i < 128 * 16; i += 256) {
            int r = i >> 4, p = 196 + (i & 15);
            Sc[r * SC_LD + p] = 0.f;
        }
    }
    __syncthreads();

    // ---- phase 2: softmax over p per q row (16 rows/warp) ----
#pragma unroll
    for (int qi = 0; qi < 16; qi++) {
        const int q = w * 16 + qi;
        float v[7];
        float mx = -1e30f;
#pragma unroll
        for (int j = 0; j < 7; j++) {
            int p = lane + 32 * j;
            v[j] = (p < 196) ? Sc[q * SC_LD + p] : -1e30f;
            mx = fmaxf(mx, v[j]);
        }
#pragma unroll
        for (int o = 16; o > 0; o >>= 1) mx = fmaxf(mx, __shfl_xor_sync(0xffffffffu, mx, o));
        float sum = 0.f;
#pragma unroll
        for (int j = 0; j < 7; j++) {
            int p = lane + 32 * j;
            float e = (p < 196) ? __expf(v[j] - mx) : 0.f;
            v[j] = e; sum += e;
        }
#pragma unroll
        for (int o = 16; o > 0; o >>= 1) sum += __shfl_xor_sync(0xffffffffu, sum, o);
        float inv = 1.f / sum;
#pragma unroll
        for (int j = 0; j < 7; j++) {
            int p = lane + 32 * j;
            if (p < 196) Sc[q * SC_LD + p] = f2tf(v[j] * inv);
        }
    }
    __syncthreads();

    // ---- phase 3: out[128][64] = Sc @ Vt^T, warp tile 32x32 ----
    {
        const int m3  = (w >> 1) * 32;
        const int nb3 = (w & 1) * 32;
        float o2[2][4][4];
#pragma unroll
        for (int mi = 0; mi < 2; mi++)
#pragma unroll
            for (int j = 0; j < 4; j++)
#pragma unroll
                for (int r = 0; r < 4; r++) o2[mi][j][r] = 0.f;

#pragma unroll
        for (int kb = 0; kb < 208; kb += 8) {
            uint32_t af[2][4];
#pragma unroll
            for (int mi = 0; mi < 2; mi++) {
                const float* ab = &Sc[(m3 + mi * 16 + (lane >> 2)) * SC_LD + kb + (lane & 3)];
                af[mi][0] = __float_as_uint(ab[0]);
                af[mi][1] = __float_as_uint(ab[8 * SC_LD]);
                af[mi][2] = __float_as_uint(ab[4]);
                af[mi][3] = __float_as_uint(ab[8 * SC_LD + 4]);
            }
#pragma unroll
            for (int j = 0; j < 4; j++) {
                uint32_t bfr[2];
                const float* bb = &Vt[(nb3 + j * 8 + (lane >> 2)) * VT_LD + kb + (lane & 3)];
                bfr[0] = __float_as_uint(bb[0]);
                bfr[1] = __float_as_uint(bb[4]);
#pragma unroll
                for (int mi = 0; mi < 2; mi++)
                    mma_tf32(o2[mi][j], af[mi], bfr);
            }
        }

        // epilogue: write xt (+ x_diag rows when f == sq/P)
#pragma unroll
        for (int mi = 0; mi < 2; mi++) {
            const int r0 = m3 + mi * 16 + (lane >> 2);
#pragma unroll
            for (int hh2 = 0; hh2 < 2; hh2++) {
                const int sq = q0 + r0 + hh2 * 8;
                if (sq < SS) {
                    float* xp = xt + ((size_t)(b * SS + sq) * FF + f) * CC + h * DD;
                    const bool diag = (sq / PP == f);
                    float* dp = xd + (size_t)(b * SS + sq) * CC + h * DD;
#pragma unroll
                    for (int j = 0; j < 4; j++) {
                        const int dv = nb3 + j * 8 + (lane & 3) * 2;
                        float2 r;
                        r.x = o2[mi][j][hh2 * 2 + 0];
                        r.y = o2[mi][j][hh2 * 2 + 1];
                        *reinterpret_cast<float2*>(xp + dv) = r;
                        if (diag) *reinterpret_cast<float2*>(dp + dv) = r;
                    }
                }
            }
        }
    }
}

// =============================================================
// gemm_G tf32: per head h, G[m,c] = sum_k q2[m,h64+k]*wkv[c,h64+k]
// q2 pre-rounded -> vector A fill.
// =============================================================
__global__ __launch_bounds__(256)
void gemm_G_tf32(const float* __restrict__ q2, const float* __restrict__ wkv,
                 float* __restrict__ G)
{
    __shared__ float As[128 * 68];
    __shared__ float Bs[128 * 68];

    const int mt = blockIdx.x, ct = blockIdx.y, h = blockIdx.z;
    const int tid = threadIdx.x;
    const int lane = tid & 31;
    const int w = tid >> 5;

    for (int i = tid; i < 128 * 16; i += 256) {
        int r = i >> 4, c4 = i & 15;
        *reinterpret_cast<float4*>(&As[r * 68 + 4 * c4]) =
            *reinterpret_cast<const float4*>(q2 + (size_t)(mt * 128 + r) * CC + h * DD + 4 * c4);
        float4 bv = *reinterpret_cast<const float4*>(wkv + (size_t)(ct * 128 + r) * (2 * CC) + h * DD + 4 * c4);
        float* pb = &Bs[r * 68 + 4 * c4];
        pb[0] = f2tf(bv.x); pb[1] = f2tf(bv.y); pb[2] = f2tf(bv.z); pb[3] = f2tf(bv.w);
    }
    __syncthreads();

    const int wm = (w >> 2) * 64;
    const int wn = (w & 3) * 32;

    float acc[4][4][4];
#pragma unroll
    for (int i = 0; i < 4; i++)
#pragma unroll
        for (int j = 0; j < 4; j++)
#pragma unroll
            for (int r = 0; r < 4; r++) acc[i][j][r] = 0.f;

#pragma unroll
    for (int kb = 0; kb < 64; kb += 8) {
        uint32_t af[4][4], bf[4][2];
#pragma unroll
        for (int i = 0; i < 4; i++) {
            const float* base = &As[(wm + i * 16 + (lane >> 2)) * 68 + kb + (lane & 3)];
            af[i][0] = __float_as_uint(base[0]);
            af[i][1] = __float_as_uint(base[8 * 68]);
            af[i][2] = __float_as_uint(base[4]);
            af[i][3] = __float_as_uint(base[8 * 68 + 4]);
        }
#pragma unroll
        for (int j = 0; j < 4; j++) {
            const float* base = &Bs[(wn + j * 8 + (lane >> 2)) * 68 + kb + (lane & 3)];
            bf[j][0] = __float_as_uint(base[0]);
            bf[j][1] = __float_as_uint(base[4]);
        }
#pragma unroll
        for (int i = 0; i < 4; i++)
#pragma unroll
            for (int j = 0; j < 4; j++)
                mma_tf32(acc[i][j], af[i], bf[j]);
    }

#pragma unroll
    for (int i = 0; i < 4; i++) {
        const int rbase = mt * 128 + wm + i * 16 + (lane >> 2);
#pragma unroll
        for (int hh2 = 0; hh2 < 2; hh2++) {
            const size_t row = rbase + hh2 * 8;
            float* gp = G + (row * HH + h) * CC + ct * 128;
#pragma unroll
            for (int j = 0; j < 4; j++) {
                const int col = wn + j * 8 + (lane & 3) * 2;
                float2 r;
                r.x = acc[i][j][hh2 * 2 + 0];
                r.y = acc[i][j][hh2 * 2 + 1];
                *reinterpret_cast<float2*>(gp + col) = r;
            }
        }
    }
}

// =============================================================
// Per (b,s): scores(12x8), softmax over f, weighted sum.
// =============================================================
#define SO_SMEM ((FF*CC + HH*CC + 96 + 96) * 4)

__global__ __launch_bounds__(256)
void score_out_kernel(const float* __restrict__ xt, const float* __restrict__ G,
                      float* __restrict__ preout, float* __restrict__ attn2)
{
    extern __shared__ float sm[];
    float* xts = sm;
    float* Gs  = xts + FF * CC;
    float* sc  = Gs + HH * CC;
    float* pr  = sc + 96;

    const int bs = blockIdx.x;
    const int b = bs / SS, s = bs % SS;
    const int tid = threadIdx.x;

    for (int i = tid; i < FF * CC / 4; i += 256)
        reinterpret_cast<float4*>(xts)[i] = reinterpret_cast<const float4*>(xt)[(size_t)bs * (FF * CC / 4) + i];
    for (int i = tid; i < HH * CC / 4; i += 256)
        reinterpret_cast<float4*>(Gs)[i] = reinterpret_cast<const float4*>(G)[(size_t)bs * (HH * CC / 4) + i];
    __syncthreads();

    const int w = tid >> 5, l = tid & 31;
    for (int idx = w; idx < 96; idx += 8) {
        int h = idx >> 3, f = idx & 7;
        const float4* gp = reinterpret_cast<const float4*>(Gs + h * CC);
        const float4* xp = reinterpret_cast<const float4*>(xts + f * CC);
        float part = 0.f;
#pragma unroll
        for (int c4 = l; c4 < CC / 4; c4 += 32) {
            float4 g = gp[c4], x = xp[c4];
            part += g.x*x.x + g.y*x.y + g.z*x.z + g.w*x.w;
        }
#pragma unroll
        for (int o = 16; o > 0; o >>= 1) part += __shfl_xor_sync(0xffffffffu, part, o);
        if (l == 0) sc[idx] = part;
    }
    __syncthreads();

    if (tid < HH) {
        int h = tid;
        float mx = -1e30f;
#pragma unroll
        for (int f = 0; f < FF; f++) mx = fmaxf(mx, sc[h * 8 + f]);
        float sum = 0.f;
        float e[FF];
#pragma unroll
        for (int f = 0; f < FF; f++) { e[f] = __expf(sc[h * 8 + f] - mx); sum += e[f]; }
        float inv = 1.f / sum;
#pragma unroll
        for (int f = 0; f < FF; f++) {
            float p = e[f] * inv;
            pr[h * 8 + f] = p;
            attn2[((size_t)(b * HH + h) * SS + s) * FF + f] = p;
        }
    }
    __syncthreads();

    for (int c = tid; c < CC; c += 256) {
        int h = c >> 6;
        float v = 0.f;
#pragma unroll
        for (int f = 0; f < FF; f++) v += pr[h * 8 + f] * xts[f * CC + c];
        preout[(size_t)(b * NN + 1 + s) * CC + c] = v;
    }
}

// =============================================================
// host launch
// =============================================================
extern "C" void kernel_launch(void* const* d_in, const int* in_sizes, int n_in,
                              void* d_out, int out_size)
{
    const float* x      = (const float*)d_in[0];
    const float* w_qkv  = (const float*)d_in[1];
    const float* w_q    = (const float*)d_in[2];
    const float* w_kv   = (const float*)d_in[3];
    const float* w_proj = (const float*)d_in[4];
    const float* b_proj = (const float*)d_in[5];

    float *p_qkv, *p_xt, *p_xd, *p_q2, *p_G, *p_pre;
    cudaGetSymbolAddress((void**)&p_qkv, g_qkv);
    cudaGetSymbolAddress((void**)&p_xt,  g_xt);
    cudaGetSymbolAddress((void**)&p_xd,  g_xd);
    cudaGetSymbolAddress((void**)&p_q2,  g_q2);
    cudaGetSymbolAddress((void**)&p_G,   g_G);
    cudaGetSymbolAddress((void**)&p_pre, g_pre);

    cudaFuncSetAttribute((const void*)gemm_tf32<false, true>,  cudaFuncAttributeMaxDynamicSharedMemorySize, GT_SMEM);
    cudaFuncSetAttribute((const void*)gemm_tf32<true,  false>, cudaFuncAttributeMaxDynamicSharedMemorySize, GT_SMEM);
    cudaFuncSetAttribute(space_attn_kernel, cudaFuncAttributeMaxDynamicSharedMemorySize, SA_SMEM);
    cudaFuncSetAttribute(score_out_kernel,  cudaFuncAttributeMaxDynamicSharedMemorySize, SO_SMEM);

    float* outp  = (float*)d_out;
    float* attn2 = outp + OUT_ELEMS;

    // 1) qkv = x @ w_qkv (tf32, output rounded to tf32)
    gemm_tf32<false, true><<<dim3(N_QKV/256, (M_QKV+127)/128), 256, GT_SMEM>>>(
        x, w_qkv, p_qkv, nullptr, M_QKV, N_QKV, CC, CC, N_QKV, N_QKV, 1.f);

    // 2) cls attention -> preout rows n=0
    cls_attn_kernel<<<BATCH*HH, 256>>>(p_qkv, p_pre);

    // 3) fused space attention -> xt (+ x_diag rows -> xd)
    space_attn_kernel<<<dim3((SS+127)/128, FF, BATCH*HH), 256, SA_SMEM>>>(p_qkv, p_xt, p_xd);

    // 4) q2 = scale * x_diag @ w_q (tf32, output rounded)
    gemm_tf32<false, true><<<dim3(CC/256, M_S/128), 256, GT_SMEM>>>(
        p_xd, w_q, p_q2, nullptr, M_S, CC, CC, CC, CC, CC, SCALE);

    // 5) G = per-head q2 @ Wk_h^T (tf32 MMA)
    gemm_G_tf32<<<dim3(M_S/128, CC/128, HH), 256>>>(p_q2, w_kv, p_G);

    // 6) scores + softmax(F) -> attn2; weighted xt -> preout rows 1+s
    score_out_kernel<<<M_S, 256, SO_SMEM>>>(p_xt, p_G, p_pre, attn2);

    // 7) out = preout @ w_proj + b_proj (tf32, full-precision output)
    gemm_tf32<true, false><<<dim3(CC/256, (M_QKV+127)/128), 256, GT_SMEM>>>(
        p_pre, w_proj, outp, b_proj, M_QKV, CC, CC, CC, CC, CC, 1.f);
}

// round 8
// speedup vs baseline: 2.2461x; 1.1439x over previous
#include <cuda_runtime.h>
#include <cuda_bf16.h>
#include <math.h>
#include <stdint.h>

// ---------------- problem constants ----------------
#define BATCH 4
#define PP    196
#define FF    8
#define CC    768
#define NN    1569          // 1 + F*P
#define SS    1568          // F*P
#define HH    12
#define DD    64
#define SCALE 0.125f        // d^-0.5

#define M_QKV   (BATCH*NN)          // 6276
#define N_QKV   (3*CC)              // 2304
#define M_S     (BATCH*SS)          // 6272
#define OUT_ELEMS ((size_t)BATCH*NN*CC)   // 4,819,968

// ---------------- scratch ----------------
__device__ float g_qkv[(size_t)M_QKV * N_QKV];        // (B,N,3C) tf32-rounded
__device__ float g_xt [(size_t)M_S * FF * CC];        // (B,S,F,C)
__device__ float g_xd [(size_t)M_S * CC];             // x_diag (B,S,C)
__device__ float g_q2 [(size_t)M_S * CC];             // (B,S,C) scaled, tf32-rounded
__device__ float g_G  [(size_t)M_S * HH * CC];        // (B,S,h,C)
__device__ float g_pre[(size_t)M_QKV * CC];           // pre-proj (B,N,C)

// ---------------- helpers ----------------
__device__ __forceinline__ float f2tf(float x) {
    uint32_t u;
    asm("cvt.rna.tf32.f32 %0, %1;" : "=r"(u) : "f"(x));
    return __uint_as_float(u);
}

__device__ __forceinline__ void mma_tf32(float* c, const uint32_t* a, const uint32_t* b) {
    asm volatile("mma.sync.aligned.m16n8k8.row.col.f32.tf32.tf32.f32 "
        "{%0,%1,%2,%3}, {%4,%5,%6,%7}, {%8,%9}, {%0,%1,%2,%3};"
        : "+f"(c[0]), "+f"(c[1]), "+f"(c[2]), "+f"(c[3])
        : "r"(a[0]), "r"(a[1]), "r"(a[2]), "r"(a[3]), "r"(b[0]), "r"(b[1]));
}

__device__ __forceinline__ uint32_t smem_u32(const void* p) {
    return (uint32_t)__cvta_generic_to_shared(p);
}

__device__ __forceinline__ void cp_async16(uint32_t saddr, const void* gptr, int src_bytes) {
    asm volatile("cp.async.cg.shared.global [%0], [%1], 16, %2;\n"
                 :: "r"(saddr), "l"(gptr), "r"(src_bytes));
}
#define CP_COMMIT() asm volatile("cp.async.commit_group;\n" ::: "memory")
#define CP_WAIT0()  asm volatile("cp.async.wait_group 0;\n" ::: "memory")

// =============================================================
// TF32 GEMM: block 128x256x16, 8 warps, warp tile 64x64.
// =============================================================
#define ALD 20
#define BLD 264
#define AS_FLOATS (128 * ALD)
#define BS_FLOATS (16 * BLD)
#define GT_SMEM ((2 * AS_FLOATS + 2 * BS_FLOATS) * 4)

template<bool HAS_BIAS, bool ROUND_OUT>
__global__ __launch_bounds__(256)
void gemm_tf32(const float* __restrict__ A, const float* __restrict__ Bm,
               float* __restrict__ Cm, const float* __restrict__ bias,
               int M, int N, int K, int lda, int ldb, int ldc, float alpha)
{
    extern __shared__ float smg[];
    float* As0 = smg;
    float* As1 = smg + AS_FLOATS;
    float* Bs0 = smg + 2 * AS_FLOATS;
    float* Bs1 = Bs0 + BS_FLOATS;

    const int tid  = threadIdx.x;
    const int lane = tid & 31;
    const int warp = tid >> 5;
    const int wm   = (warp & 1) * 64;
    const int wn   = (warp >> 1) * 64;
    const int m0   = blockIdx.y * 128;
    const int n0   = blockIdx.x * 256;

    const int a_row0 = tid >> 2;
    const int a_k0   = (tid & 3) * 4;
    const int b_row0 = tid >> 6;
    const int b_c0   = (tid & 63) * 4;

    float4 ra[2], rb[4];

#pragma unroll
    for (int i = 0; i < 2; i++) {
        int row = a_row0 + i * 64;
        ra[i] = (m0 + row < M) ? *(const float4*)(A + (size_t)(m0 + row) * lda + a_k0)
                               : make_float4(0.f, 0.f, 0.f, 0.f);
    }
#pragma unroll
    for (int i = 0; i < 4; i++)
        rb[i] = *(const float4*)(Bm + (size_t)(b_row0 + i * 4) * ldb + n0 + b_c0);

#pragma unroll
    for (int i = 0; i < 2; i++) {
        float* p = &As0[(a_row0 + i * 64) * ALD + a_k0];
        p[0] = f2tf(ra[i].x); p[1] = f2tf(ra[i].y); p[2] = f2tf(ra[i].z); p[3] = f2tf(ra[i].w);
    }
#pragma unroll
    for (int i = 0; i < 4; i++) {
        float* q = &Bs0[(b_row0 + i * 4) * BLD + b_c0];
        q[0] = f2tf(rb[i].x); q[1] = f2tf(rb[i].y); q[2] = f2tf(rb[i].z); q[3] = f2tf(rb[i].w);
    }
    __syncthreads();

    float acc[4][8][4];
#pragma unroll
    for (int i = 0; i < 4; i++)
#pragma unroll
        for (int j = 0; j < 8; j++)
#pragma unroll
            for (int r = 0; r < 4; r++) acc[i][j][r] = 0.f;

    const int ntiles = K / 16;
    for (int t = 0; t < ntiles; t++) {
        float* Asc = (t & 1) ? As1 : As0;
        float* Bsc = (t & 1) ? Bs1 : Bs0;
        const bool more = (t + 1 < ntiles);
        if (more) {
            const int k0 = (t + 1) * 16;
#pragma unroll
            for (int i = 0; i < 2; i++) {
                int row = a_row0 + i * 64;
                ra[i] = (m0 + row < M) ? *(const float4*)(A + (size_t)(m0 + row) * lda + k0 + a_k0)
                                       : make_float4(0.f, 0.f, 0.f, 0.f);
            }
#pragma unroll
            for (int i = 0; i < 4; i++)
                rb[i] = *(const float4*)(Bm + (size_t)(k0 + b_row0 + i * 4) * ldb + n0 + b_c0);
        }

#pragma unroll
        for (int ks = 0; ks < 2; ks++) {
            const int kb = ks * 8;
            uint32_t af[4][4];
#pragma unroll
            for (int i = 0; i < 4; i++) {
                const float* base = &Asc[(wm + i * 16 + (lane >> 2)) * ALD + kb + (lane & 3)];
                af[i][0] = __float_as_uint(base[0]);
                af[i][1] = __float_as_uint(base[8 * ALD]);
                af[i][2] = __float_as_uint(base[4]);
                af[i][3] = __float_as_uint(base[8 * ALD + 4]);
            }
#pragma unroll
            for (int j = 0; j < 8; j++) {
                uint32_t bf[2];
                const float* base = &Bsc[(kb + (lane & 3)) * BLD + wn + j * 8 + (lane >> 2)];
                bf[0] = __float_as_uint(base[0]);
                bf[1] = __float_as_uint(base[4 * BLD]);
#pragma unroll
                for (int i = 0; i < 4; i++)
                    mma_tf32(acc[i][j], af[i], bf);
            }
        }

        if (more) {
            float* Asn = (t & 1) ? As0 : As1;
            float* Bsn = (t & 1) ? Bs0 : Bs1;
#pragma unroll
            for (int i = 0; i < 2; i++) {
                float* p = &Asn[(a_row0 + i * 64) * ALD + a_k0];
                p[0] = f2tf(ra[i].x); p[1] = f2tf(ra[i].y); p[2] = f2tf(ra[i].z); p[3] = f2tf(ra[i].w);
            }
#pragma unroll
            for (int i = 0; i < 4; i++) {
                float* q = &Bsn[(b_row0 + i * 4) * BLD + b_c0];
                q[0] = f2tf(rb[i].x); q[1] = f2tf(rb[i].y); q[2] = f2tf(rb[i].z); q[3] = f2tf(rb[i].w);
            }
            __syncthreads();
        }
    }

#pragma unroll
    for (int i = 0; i < 4; i++) {
        const int rbase = m0 + wm + i * 16 + (lane >> 2);
#pragma unroll
        for (int h = 0; h < 2; h++) {
            const int row = rbase + h * 8;
            if (row < M) {
#pragma unroll
                for (int j = 0; j < 8; j++) {
                    const int col = n0 + wn + j * 8 + (lane & 3) * 2;
                    float2 r;
                    r.x = acc[i][j][h * 2 + 0] * alpha;
                    r.y = acc[i][j][h * 2 + 1] * alpha;
                    if (HAS_BIAS) { r.x += bias[col]; r.y += bias[col + 1]; }
                    if (ROUND_OUT) { r.x = f2tf(r.x); r.y = f2tf(r.y); }
                    *(float2*)(Cm + (size_t)row * ldc + col) = r;
                }
            }
        }
    }
}

// =============================================================
// CLS attention: 48 blocks (b,h).
// =============================================================
__global__ __launch_bounds__(256)
void cls_attn_kernel(const float* __restrict__ qkv, float* __restrict__ preout)
{
    __shared__ float sim[NN];
    __shared__ float qv[DD];
    __shared__ float red[256];
    __shared__ float accred[4 * DD];

    const int b = blockIdx.x / HH;
    const int h = blockIdx.x % HH;
    const int tid = threadIdx.x;

    if (tid < DD)
        qv[tid] = qkv[(size_t)(b * NN) * N_QKV + h * DD + tid] * SCALE;
    __syncthreads();

    for (int n = tid; n < NN; n += 256) {
        const float* kp = qkv + (size_t)(b * NN + n) * N_QKV + CC + h * DD;
        float d = 0.f;
#pragma unroll
        for (int c4 = 0; c4 < DD / 4; c4++) {
            float4 k4 = *reinterpret_cast<const float4*>(kp + c4 * 4);
            d += qv[c4*4+0]*k4.x + qv[c4*4+1]*k4.y + qv[c4*4+2]*k4.z + qv[c4*4+3]*k4.w;
        }
        sim[n] = d;
    }
    __syncthreads();

    float m = -1e30f;
    for (int n = tid; n < NN; n += 256) m = fmaxf(m, sim[n]);
    red[tid] = m; __syncthreads();
    for (int o = 128; o > 0; o >>= 1) { if (tid < o) red[tid] = fmaxf(red[tid], red[tid+o]); __syncthreads(); }
    const float mx = red[0];
    __syncthreads();

    float s = 0.f;
    for (int n = tid; n < NN; n += 256) { float e = __expf(sim[n] - mx); sim[n] = e; s += e; }
    red[tid] = s; __syncthreads();
    for (int o = 128; o > 0; o >>= 1) { if (tid < o) red[tid] += red[tid+o]; __syncthreads(); }
    const float inv = 1.f / red[0];
    __syncthreads();

    const int g = tid >> 6, dd = tid & 63;
    float a = 0.f;
    for (int n = g; n < NN; n += 4)
        a += sim[n] * qkv[(size_t)(b * NN + n) * N_QKV + 2 * CC + h * DD + dd];
    accred[g * DD + dd] = a;
    __syncthreads();
    if (tid < DD)
        preout[(size_t)(b * NN) * CC + h * DD + tid] =
            (accred[tid] + accred[DD + tid] + accred[2*DD + tid] + accred[3*DD + tid]) * inv;
}

// =============================================================
// Space attention v5: K/V-resident blocks.
// block = (qhalf, f, bh); loads K/V once, loops 12-13 q-tiles of 64
// rows with cp.async double-buffered Q.
// smem (floats): Ksm[208][68] @0 | Vt[64][212] @14144 |
//                Q2[2][64][68] @27712 | Sc[64][212] @36416
// =============================================================
#define SA_KLD 68
#define SA_QLD 68
#define VT_LD  212
#define SC_LD  212
#define SA_KOFF  0
#define SA_VTOFF 14144
#define SA_QOFF  27712
#define SA_QBUF  4352
#define SA_SCOFF 36416
#define SA_FLOATS 49984
#define SA_SMEM (SA_FLOATS * 4)          // 199936 B

__global__ __launch_bounds__(256)
void space_attn_kernel(const float* __restrict__ qkv, float* __restrict__ xt,
                       float* __restrict__ xd)
{
    extern __shared__ float sm[];
    float* Ksm = sm + SA_KOFF;       // 208 x 68 (rows 196..207 zero)
    float* Vt  = sm + SA_VTOFF;      // 64 x 212 (dv,p), cols 196..211 zero
    float* Qb  = sm + SA_QOFF;       // 2 x (64 x 68)
    float* Sc  = sm + SA_SCOFF;      // 64 x 212 (pad cols zeroed once)

    const int qhalf = blockIdx.x;            // 0: qtiles 0..12, 1: 13..24
    const int f  = blockIdx.y;
    const int bh = blockIdx.z;
    const int b  = bh / HH, h = bh % HH;
    const int tid = threadIdx.x;
    const int w = tid >> 5, lane = tid & 31;
    const int niters = qhalf ? 12 : 13;
    const int qt0 = qhalf * 13;

    // ---- K/V load (once) ----
    for (int i = tid; i < 208 * 16; i += 256) {
        int r = i >> 4, c4 = i & 15;
        if (r < 196) {
            size_t base = (size_t)(b * NN + 1 + f * PP + r) * N_QKV + h * DD + c4 * 4;
            *reinterpret_cast<float4*>(&Ksm[r * SA_KLD + c4 * 4]) =
                *reinterpret_cast<const float4*>(qkv + base + CC);
            float4 vv = *reinterpret_cast<const float4*>(qkv + base + 2 * CC);
            Vt[(4 * c4 + 0) * VT_LD + r] = vv.x;
            Vt[(4 * c4 + 1) * VT_LD + r] = vv.y;
            Vt[(4 * c4 + 2) * VT_LD + r] = vv.z;
            Vt[(4 * c4 + 3) * VT_LD + r] = vv.w;
        } else {
            *reinterpret_cast<float4*>(&Ksm[r * SA_KLD + c4 * 4]) = make_float4(0.f,0.f,0.f,0.f);
        }
    }
    // zero Vt pad columns and Sc pad columns (once; never overwritten)
    for (int i = tid; i < 64 * 16; i += 256) {
        int rr = i >> 4, p = 196 + (i & 15);
        Vt[rr * VT_LD + p] = 0.f;
        Sc[rr * SC_LD + p] = 0.f;
    }

    // ---- Q prefetch helper (cp.async, 16B, zero-fill OOB rows) ----
    const uint32_t smbase = smem_u32(sm);
    auto issue_q = [&](int it, int buf) {
        const int q0 = (qt0 + it) * 64;
#pragma unroll
        for (int k = 0; k < 4; k++) {
            int i = tid + k * 256;
            int r = i >> 4, c4 = i & 15;
            int sq = q0 + r;
            int valid = (sq < SS);
            int sqc = valid ? sq : (SS - 1);
            const float* gp = qkv + (size_t)(b * NN + 1 + sqc) * N_QKV + h * DD + c4 * 4;
            uint32_t sa = smbase + (SA_QOFF + buf * SA_QBUF + r * SA_QLD + c4 * 4) * 4;
            cp_async16(sa, gp, valid ? 16 : 0);
        }
        CP_COMMIT();
    };

    issue_q(0, 0);

    for (int it = 0; it < niters; it++) {
        const int buf = it & 1;
        const int q0 = (qt0 + it) * 64;
        const float* Qsm = Qb + buf * SA_QBUF;

        CP_WAIT0();
        __syncthreads();   // Q visible to all; prev iter phase-3 done (Sc safe to overwrite)

        if (it + 1 < niters) issue_q(it + 1, buf ^ 1);

        // ---- phase 1: S[64][208] = Q @ K^T; warp tile 16m x 104n ----
        const int mrow1  = (w >> 1) * 16;
        const int nbase1 = (w & 1) * 104;
        float acc[13][4];
#pragma unroll
        for (int nt = 0; nt < 13; nt++)
#pragma unroll
            for (int r = 0; r < 4; r++) acc[nt][r] = 0.f;

#pragma unroll
        for (int kb = 0; kb < 64; kb += 8) {
            uint32_t af[4];
            const float* ab = &Qsm[(mrow1 + (lane >> 2)) * SA_QLD + kb + (lane & 3)];
            af[0] = __float_as_uint(ab[0]);
            af[1] = __float_as_uint(ab[8 * SA_QLD]);
            af[2] = __float_as_uint(ab[4]);
            af[3] = __float_as_uint(ab[8 * SA_QLD + 4]);
#pragma unroll
            for (int nt = 0; nt < 13; nt++) {
                uint32_t bfr[2];
                const float* bb = &Ksm[(nbase1 + nt * 8 + (lane >> 2)) * SA_KLD + kb + (lane & 3)];
                bfr[0] = __float_as_uint(bb[0]);
                bfr[1] = __float_as_uint(bb[4]);
                mma_tf32(acc[nt], af, bfr);
            }
        }

        // scores -> Sc (cols<196 only; pads stay zero)
        {
            const int r0 = mrow1 + (lane >> 2);
#pragma unroll
            for (int nt = 0; nt < 13; nt++) {
                int col = nbase1 + nt * 8 + (lane & 3) * 2;
                if (col < 196) {
                    Sc[r0 * SC_LD + col]       = acc[nt][0] * SCALE;
                    Sc[r0 * SC_LD + col + 1]   = acc[nt][1] * SCALE;
                    Sc[(r0 + 8) * SC_LD + col]     = acc[nt][2] * SCALE;
                    Sc[(r0 + 8) * SC_LD + col + 1] = acc[nt][3] * SCALE;
                }
            }
        }
        __syncthreads();

        // ---- phase 2: softmax over p; 8 rows per warp ----
#pragma unroll
        for (int qi = 0; qi < 8; qi++) {
            const int q = w * 8 + qi;
            float v[7];
            float mx = -1e30f;
#pragma unroll
            for (int j = 0; j < 7; j++) {
                int p = lane + 32 * j;
                v[j] = (p < 196) ? Sc[q * SC_LD + p] : -1e30f;
                mx = fmaxf(mx, v[j]);
            }
#pragma unroll
            for (int o = 16; o > 0; o >>= 1) mx = fmaxf(mx, __shfl_xor_sync(0xffffffffu, mx, o));
            float sum = 0.f;
#pragma unroll
            for (int j = 0; j < 7; j++) {
                int p = lane + 32 * j;
                float e = (p < 196) ? __expf(v[j] - mx) : 0.f;
                v[j] = e; sum += e;
            }
#pragma unroll
            for (int o = 16; o > 0; o >>= 1) sum += __shfl_xor_sync(0xffffffffu, sum, o);
            float inv = 1.f / sum;
#pragma unroll
            for (int j = 0; j < 7; j++) {
                int p = lane + 32 * j;
                if (p < 196) Sc[q * SC_LD + p] = f2tf(v[j] * inv);
            }
        }
        __syncthreads();

        // ---- phase 3: out[64][64] = Sc @ Vt^T; warp tile 16m x 32n ----
        {
            const int m3  = (w >> 1) * 16;
            const int nb3 = (w & 1) * 32;
            float o2[4][4];
#pragma unroll
            for (int j = 0; j < 4; j++)
#pragma unroll
                for (int r = 0; r < 4; r++) o2[j][r] = 0.f;

#pragma unroll
            for (int kb = 0; kb < 208; kb += 8) {
                uint32_t af[4];
                const float* ab = &Sc[(m3 + (lane >> 2)) * SC_LD + kb + (lane & 3)];
                af[0] = __float_as_uint(ab[0]);
                af[1] = __float_as_uint(ab[8 * SC_LD]);
                af[2] = __float_as_uint(ab[4]);
                af[3] = __float_as_uint(ab[8 * SC_LD + 4]);
#pragma unroll
                for (int j = 0; j < 4; j++) {
                    uint32_t bfr[2];
                    const float* bb = &Vt[(nb3 + j * 8 + (lane >> 2)) * VT_LD + kb + (lane & 3)];
                    bfr[0] = __float_as_uint(bb[0]);
                    bfr[1] = __float_as_uint(bb[4]);
                    mma_tf32(o2[j], af, bfr);
                }
            }

            // epilogue: write xt (+ x_diag rows when f == sq/P)
            const int r0 = m3 + (lane >> 2);
#pragma unroll
            for (int hh2 = 0; hh2 < 2; hh2++) {
                const int sq = q0 + r0 + hh2 * 8;
                if (sq < SS) {
                    float* xp = xt + ((size_t)(b * SS + sq) * FF + f) * CC + h * DD;
                    const bool diag = (sq / PP == f);
                    float* dp = xd + (size_t)(b * SS + sq) * CC + h * DD;
#pragma unroll
                    for (int j = 0; j < 4; j++) {
                        const int dv = nb3 + j * 8 + (lane & 3) * 2;
                        float2 r;
                        r.x = o2[j][hh2 * 2 + 0];
                        r.y = o2[j][hh2 * 2 + 1];
                        *reinterpret_cast<float2*>(xp + dv) = r;
                        if (diag) *reinterpret_cast<float2*>(dp + dv) = r;
                    }
                }
            }
        }
        __syncthreads();   // phase-3 Sc reads done before next iter's score store
    }
}

// =============================================================
// gemm_G tf32: per head h, G[m,c] = sum_k q2[m,h64+k]*wkv[c,h64+k]
// =============================================================
__global__ __launch_bounds__(256)
void gemm_G_tf32(const float* __restrict__ q2, const float* __restrict__ wkv,
                 float* __restrict__ G)
{
    __shared__ float As[128 * 68];
    __shared__ float Bs[128 * 68];

    const int mt = blockIdx.x, ct = blockIdx.y, h = blockIdx.z;
    const int tid = threadIdx.x;
    const int lane = tid & 31;
    const int w = tid >> 5;

    for (int i = tid; i < 128 * 16; i += 256) {
        int r = i >> 4, c4 = i & 15;
        *reinterpret_cast<float4*>(&As[r * 68 + 4 * c4]) =
            *reinterpret_cast<const float4*>(q2 + (size_t)(mt * 128 + r) * CC + h * DD + 4 * c4);
        float4 bv = *reinterpret_cast<const float4*>(wkv + (size_t)(ct * 128 + r) * (2 * CC) + h * DD + 4 * c4);
        float* pb = &Bs[r * 68 + 4 * c4];
        pb[0] = f2tf(bv.x); pb[1] = f2tf(bv.y); pb[2] = f2tf(bv.z); pb[3] = f2tf(bv.w);
    }
    __syncthreads();

    const int wm = (w >> 2) * 64;
    const int wn = (w & 3) * 32;

    float acc[4][4][4];
#pragma unroll
    for (int i = 0; i < 4; i++)
#pragma unroll
        for (int j = 0; j < 4; j++)
#pragma unroll
            for (int r = 0; r < 4; r++) acc[i][j][r] = 0.f;

#pragma unroll
    for (int kb = 0; kb < 64; kb += 8) {
        uint32_t af[4][4], bf[4][2];
#pragma unroll
        for (int i = 0; i < 4; i++) {
            const float* base = &As[(wm + i * 16 + (lane >> 2)) * 68 + kb + (lane & 3)];
            af[i][0] = __float_as_uint(base[0]);
            af[i][1] = __float_as_uint(base[8 * 68]);
            af[i][2] = __float_as_uint(base[4]);
            af[i][3] = __float_as_uint(base[8 * 68 + 4]);
        }
#pragma unroll
        for (int j = 0; j < 4; j++) {
            const float* base = &Bs[(wn + j * 8 + (lane >> 2)) * 68 + kb + (lane & 3)];
            bf[j][0] = __float_as_uint(base[0]);
            bf[j][1] = __float_as_uint(base[4]);
        }
#pragma unroll
        for (int i = 0; i < 4; i++)
#pragma unroll
            for (int j = 0; j < 4; j++)
                mma_tf32(acc[i][j], af[i], bf[j]);
    }

#pragma unroll
    for (int i = 0; i < 4; i++) {
        const int rbase = mt * 128 + wm + i * 16 + (lane >> 2);
#pragma unroll
        for (int hh2 = 0; hh2 < 2; hh2++) {
            const size_t row = rbase + hh2 * 8;
            float* gp = G + (row * HH + h) * CC + ct * 128;
#pragma unroll
            for (int j = 0; j < 4; j++) {
                const int col = wn + j * 8 + (lane & 3) * 2;
                float2 r;
                r.x = acc[i][j][hh2 * 2 + 0];
                r.y = acc[i][j][hh2 * 2 + 1];
                *reinterpret_cast<float2*>(gp + col) = r;
            }
        }
    }
}

// =============================================================
// Per (b,s): scores(12x8), softmax over f, weighted sum.
// =============================================================
#define SO_SMEM ((FF*CC + HH*CC + 96 + 96) * 4)

__global__ __launch_bounds__(256)
void score_out_kernel(const float* __restrict__ xt, const float* __restrict__ G,
                      float* __restrict__ preout, float* __restrict__ attn2)
{
    extern __shared__ float sm[];
    float* xts = sm;
    float* Gs  = xts + FF * CC;
    float* sc  = Gs + HH * CC;
    float* pr  = sc + 96;

    const int bs = blockIdx.x;
    const int b = bs / SS, s = bs % SS;
    const int tid = threadIdx.x;

    for (int i = tid; i < FF * CC / 4; i += 256)
        reinterpret_cast<float4*>(xts)[i] = reinterpret_cast<const float4*>(xt)[(size_t)bs * (FF * CC / 4) + i];
    for (int i = tid; i < HH * CC / 4; i += 256)
        reinterpret_cast<float4*>(Gs)[i] = reinterpret_cast<const float4*>(G)[(size_t)bs * (HH * CC / 4) + i];
    __syncthreads();

    const int w = tid >> 5, l = tid & 31;
    for (int idx = w; idx < 96; idx += 8) {
        int h = idx >> 3, f = idx & 7;
        const float4* gp = reinterpret_cast<const float4*>(Gs + h * CC);
        const float4* xp = reinterpret_cast<const float4*>(xts + f * CC);
        float part = 0.f;
#pragma unroll
        for (int c4 = l; c4 < CC / 4; c4 += 32) {
            float4 g = gp[c4], x = xp[c4];
            part += g.x*x.x + g.y*x.y + g.z*x.z + g.w*x.w;
        }
#pragma unroll
        for (int o = 16; o > 0; o >>= 1) part += __shfl_xor_sync(0xffffffffu, part, o);
        if (l == 0) sc[idx] = part;
    }
    __syncthreads();

    if (tid < HH) {
        int h = tid;
        float mx = -1e30f;
#pragma unroll
        for (int f = 0; f < FF; f++) mx = fmaxf(mx, sc[h * 8 + f]);
        float sum = 0.f;
        float e[FF];
#pragma unroll
        for (int f = 0; f < FF; f++) { e[f] = __expf(sc[h * 8 + f] - mx); sum += e[f]; }
        float inv = 1.f / sum;
#pragma unroll
        for (int f = 0; f < FF; f++) {
            float p = e[f] * inv;
            pr[h * 8 + f] = p;
            attn2[((size_t)(b * HH + h) * SS + s) * FF + f] = p;
        }
    }
    __syncthreads();

    for (int c = tid; c < CC; c += 256) {
        int h = c >> 6;
        float v = 0.f;
#pragma unroll
        for (int f = 0; f < FF; f++) v += pr[h * 8 + f] * xts[f * CC + c];
        preout[(size_t)(b * NN + 1 + s) * CC + c] = v;
    }
}

// =============================================================
// host launch
// =============================================================
extern "C" void kernel_launch(void* const* d_in, const int* in_sizes, int n_in,
                              void* d_out, int out_size)
{
    const float* x      = (const float*)d_in[0];
    const float* w_qkv  = (const float*)d_in[1];
    const float* w_q    = (const float*)d_in[2];
    const float* w_kv   = (const float*)d_in[3];
    const float* w_proj = (const float*)d_in[4];
    const float* b_proj = (const float*)d_in[5];

    float *p_qkv, *p_xt, *p_xd, *p_q2, *p_G, *p_pre;
    cudaGetSymbolAddress((void**)&p_qkv, g_qkv);
    cudaGetSymbolAddress((void**)&p_xt,  g_xt);
    cudaGetSymbolAddress((void**)&p_xd,  g_xd);
    cudaGetSymbolAddress((void**)&p_q2,  g_q2);
    cudaGetSymbolAddress((void**)&p_G,   g_G);
    cudaGetSymbolAddress((void**)&p_pre, g_pre);

    cudaFuncSetAttribute((const void*)gemm_tf32<false, true>,  cudaFuncAttributeMaxDynamicSharedMemorySize, GT_SMEM);
    cudaFuncSetAttribute((const void*)gemm_tf32<true,  false>, cudaFuncAttributeMaxDynamicSharedMemorySize, GT_SMEM);
    cudaFuncSetAttribute(space_attn_kernel, cudaFuncAttributeMaxDynamicSharedMemorySize, SA_SMEM);
    cudaFuncSetAttribute(score_out_kernel,  cudaFuncAttributeMaxDynamicSharedMemorySize, SO_SMEM);

    float* outp  = (float*)d_out;
    float* attn2 = outp + OUT_ELEMS;

    // 1) qkv = x @ w_qkv (tf32, output rounded to tf32)
    gemm_tf32<false, true><<<dim3(N_QKV/256, (M_QKV+127)/128), 256, GT_SMEM>>>(
        x, w_qkv, p_qkv, nullptr, M_QKV, N_QKV, CC, CC, N_QKV, N_QKV, 1.f);

    // 2) cls attention -> preout rows n=0
    cls_attn_kernel<<<BATCH*HH, 256>>>(p_qkv, p_pre);

    // 3) fused space attention (K/V resident, cp.async Q pipeline)
    space_attn_kernel<<<dim3(2, FF, BATCH*HH), 256, SA_SMEM>>>(p_qkv, p_xt, p_xd);

    // 4) q2 = scale * x_diag @ w_q (tf32, output rounded)
    gemm_tf32<false, true><<<dim3(CC/256, M_S/128), 256, GT_SMEM>>>(
        p_xd, w_q, p_q2, nullptr, M_S, CC, CC, CC, CC, CC, SCALE);

    // 5) G = per-head q2 @ Wk_h^T (tf32 MMA)
    gemm_G_tf32<<<dim3(M_S/128, CC/128, HH), 256>>>(p_q2, w_kv, p_G);

    // 6) scores + softmax(F) -> attn2; weighted xt -> preout rows 1+s
    score_out_kernel<<<M_S, 256, SO_SMEM>>>(p_xt, p_G, p_pre, attn2);

    // 7) out = preout @ w_proj + b_proj (tf32, full-precision output)
    gemm_tf32<true, false><<<dim3(CC/256, (M_QKV+127)/128), 256, GT_SMEM>>>(
        p_pre, w_proj, outp, b_proj, M_QKV, CC, CC, CC, CC, CC, 1.f);
}

// round 9
// speedup vs baseline: 2.2784x; 1.0144x over previous
#include <cuda_runtime.h>
#include <cuda_bf16.h>
#include <math.h>
#include <stdint.h>

// ---------------- problem constants ----------------
#define BATCH 4
#define PP    196
#define FF    8
#define CC    768
#define NN    1569          // 1 + F*P
#define SS    1568          // F*P
#define HH    12
#define DD    64
#define SCALE 0.125f        // d^-0.5

#define M_QKV   (BATCH*NN)          // 6276
#define N_QKV   (3*CC)              // 2304
#define M_S     (BATCH*SS)          // 6272
#define OUT_ELEMS ((size_t)BATCH*NN*CC)   // 4,819,968

// ---------------- scratch ----------------
__device__ float g_qkv[(size_t)M_QKV * N_QKV];        // (B,N,3C) tf32-rounded
__device__ float g_xt [(size_t)M_S * FF * CC];        // (B,S,F,C)
__device__ float g_xd [(size_t)M_S * CC];             // x_diag, tf32-rounded
__device__ float g_q2 [(size_t)M_S * CC];             // tf32-rounded
__device__ float g_G  [(size_t)M_S * HH * CC];        // (B,S,h,C)
__device__ float g_pre[(size_t)M_QKV * CC];           // pre-proj, tf32-rounded
// tf32-rounded input copies
__device__ float g_xr    [(size_t)M_QKV * CC];
__device__ float g_wqkvr [(size_t)CC * 3 * CC];
__device__ float g_wqr   [(size_t)CC * CC];
__device__ float g_wkvr  [(size_t)CC * 2 * CC];
__device__ float g_wprojr[(size_t)CC * CC];

// ---------------- helpers ----------------
__device__ __forceinline__ float f2tf(float x) {
    uint32_t u;
    asm("cvt.rna.tf32.f32 %0, %1;" : "=r"(u) : "f"(x));
    return __uint_as_float(u);
}

__device__ __forceinline__ void mma_tf32(float* c, const uint32_t* a, const uint32_t* b) {
    asm volatile("mma.sync.aligned.m16n8k8.row.col.f32.tf32.tf32.f32 "
        "{%0,%1,%2,%3}, {%4,%5,%6,%7}, {%8,%9}, {%0,%1,%2,%3};"
        : "+f"(c[0]), "+f"(c[1]), "+f"(c[2]), "+f"(c[3])
        : "r"(a[0]), "r"(a[1]), "r"(a[2]), "r"(a[3]), "r"(b[0]), "r"(b[1]));
}

__device__ __forceinline__ uint32_t smem_u32(const void* p) {
    return (uint32_t)__cvta_generic_to_shared(p);
}

__device__ __forceinline__ void cp_async16(uint32_t saddr, const void* gptr, int src_bytes) {
    asm volatile("cp.async.cg.shared.global [%0], [%1], 16, %2;\n"
                 :: "r"(saddr), "l"(gptr), "r"(src_bytes));
}
#define CP_COMMIT() asm volatile("cp.async.commit_group;\n" ::: "memory")
#define CP_WAIT(n)  asm volatile("cp.async.wait_group %0;\n" :: "n"(n) : "memory")

// =============================================================
// round_copy: dst = tf32_round(src), float4 grid-stride
// =============================================================
__global__ __launch_bounds__(256)
void round_copy(const float* __restrict__ src, float* __restrict__ dst, int n4)
{
    int i = blockIdx.x * 256 + threadIdx.x;
    if (i < n4) {
        float4 v = reinterpret_cast<const float4*>(src)[i];
        v.x = f2tf(v.x); v.y = f2tf(v.y); v.z = f2tf(v.z); v.w = f2tf(v.w);
        reinterpret_cast<float4*>(dst)[i] = v;
    }
}

// =============================================================
// TF32 GEMM v3: inputs pre-rounded; cp.async 3-stage pipeline.
// block 128x128x16, 8 warps, warp tile 64x32, 2 CTAs/SM.
// N%128==0, K%16==0.
// =============================================================
#define ALD3 20
#define BLD3 136
#define A_ST (128 * ALD3)       // 2560 floats
#define B_ST (16 * BLD3)        // 2176 floats
#define GT_SMEM ((3 * A_ST + 3 * B_ST) * 4)   // 56832 B

template<bool HAS_BIAS, bool ROUND_OUT>
__global__ __launch_bounds__(256, 2)
void gemm_tf32(const float* __restrict__ A, const float* __restrict__ Bm,
               float* __restrict__ Cm, const float* __restrict__ bias,
               int M, int N, int K, int lda, int ldb, int ldc, float alpha)
{
    extern __shared__ float smg[];
    const uint32_t smbase = smem_u32(smg);

    const int tid  = threadIdx.x;
    const int lane = tid & 31;
    const int warp = tid >> 5;
    const int wm   = (warp >> 2) * 64;
    const int wn   = (warp & 3) * 32;
    const int m0   = blockIdx.y * 128;
    const int n0   = blockIdx.x * 128;

    // A chunks: i in [0,512): r=i>>2, c4=i&3 (2 per thread)
    // B chunks: i in [0,512): r=i>>5, c4=i&31 (2 per thread)
    auto issue = [&](int t, int s) {
        const int k0 = t * 16;
        const uint32_t abase = smbase + (s * A_ST) * 4;
        const uint32_t bbase = smbase + (3 * A_ST + s * B_ST) * 4;
#pragma unroll
        for (int u = 0; u < 2; u++) {
            int i = tid + u * 256;
            int r = i >> 2, c4 = i & 3;
            int row = m0 + r;
            int valid = (row < M);
            int rowc = valid ? row : (M - 1);
            cp_async16(abase + (r * ALD3 + c4 * 4) * 4,
                       A + (size_t)rowc * lda + k0 + c4 * 4, valid ? 16 : 0);
        }
#pragma unroll
        for (int u = 0; u < 2; u++) {
            int i = tid + u * 256;
            int r = i >> 5, c4 = i & 31;
            cp_async16(bbase + (r * BLD3 + c4 * 4) * 4,
                       Bm + (size_t)(k0 + r) * ldb + n0 + c4 * 4, 16);
        }
        CP_COMMIT();
    };

    const int ntiles = K / 16;
    issue(0, 0);
    issue(1, 1);

    float acc[4][4][4];
#pragma unroll
    for (int i = 0; i < 4; i++)
#pragma unroll
        for (int j = 0; j < 4; j++)
#pragma unroll
            for (int r = 0; r < 4; r++) acc[i][j][r] = 0.f;

    for (int t = 0; t < ntiles; t++) {
        const int s = t % 3;
        CP_WAIT(1);
        __syncthreads();
        if (t + 2 < ntiles) issue(t + 2, (t + 2) % 3);

        const float* As = smg + s * A_ST;
        const float* Bs = smg + 3 * A_ST + s * B_ST;

#pragma unroll
        for (int ks = 0; ks < 2; ks++) {
            const int kb = ks * 8;
            uint32_t af[4][4];
#pragma unroll
            for (int i = 0; i < 4; i++) {
                const float* base = &As[(wm + i * 16 + (lane >> 2)) * ALD3 + kb + (lane & 3)];
                af[i][0] = __float_as_uint(base[0]);
                af[i][1] = __float_as_uint(base[8 * ALD3]);
                af[i][2] = __float_as_uint(base[4]);
                af[i][3] = __float_as_uint(base[8 * ALD3 + 4]);
            }
#pragma unroll
            for (int j = 0; j < 4; j++) {
                uint32_t bf[2];
                const float* base = &Bs[(kb + (lane & 3)) * BLD3 + wn + j * 8 + (lane >> 2)];
                bf[0] = __float_as_uint(base[0]);
                bf[1] = __float_as_uint(base[4 * BLD3]);
#pragma unroll
                for (int i = 0; i < 4; i++)
                    mma_tf32(acc[i][j], af[i], bf);
            }
        }
        __syncthreads();
    }

    // ---- epilogue ----
#pragma unroll
    for (int i = 0; i < 4; i++) {
        const int rbase = m0 + wm + i * 16 + (lane >> 2);
#pragma unroll
        for (int h = 0; h < 2; h++) {
            const int row = rbase + h * 8;
            if (row < M) {
#pragma unroll
                for (int j = 0; j < 4; j++) {
                    const int col = n0 + wn + j * 8 + (lane & 3) * 2;
                    float2 r;
                    r.x = acc[i][j][h * 2 + 0] * alpha;
                    r.y = acc[i][j][h * 2 + 1] * alpha;
                    if (HAS_BIAS) { r.x += bias[col]; r.y += bias[col + 1]; }
                    if (ROUND_OUT) { r.x = f2tf(r.x); r.y = f2tf(r.y); }
                    *(float2*)(Cm + (size_t)row * ldc + col) = r;
                }
            }
        }
    }
}

// =============================================================
// CLS attention: 48 blocks (b,h).
// =============================================================
__global__ __launch_bounds__(256)
void cls_attn_kernel(const float* __restrict__ qkv, float* __restrict__ preout)
{
    __shared__ float sim[NN];
    __shared__ float qv[DD];
    __shared__ float red[256];
    __shared__ float accred[4 * DD];

    const int b = blockIdx.x / HH;
    const int h = blockIdx.x % HH;
    const int tid = threadIdx.x;

    if (tid < DD)
        qv[tid] = qkv[(size_t)(b * NN) * N_QKV + h * DD + tid] * SCALE;
    __syncthreads();

    for (int n = tid; n < NN; n += 256) {
        const float* kp = qkv + (size_t)(b * NN + n) * N_QKV + CC + h * DD;
        float d = 0.f;
#pragma unroll
        for (int c4 = 0; c4 < DD / 4; c4++) {
            float4 k4 = *reinterpret_cast<const float4*>(kp + c4 * 4);
            d += qv[c4*4+0]*k4.x + qv[c4*4+1]*k4.y + qv[c4*4+2]*k4.z + qv[c4*4+3]*k4.w;
        }
        sim[n] = d;
    }
    __syncthreads();

    float m = -1e30f;
    for (int n = tid; n < NN; n += 256) m = fmaxf(m, sim[n]);
    red[tid] = m; __syncthreads();
    for (int o = 128; o > 0; o >>= 1) { if (tid < o) red[tid] = fmaxf(red[tid], red[tid+o]); __syncthreads(); }
    const float mx = red[0];
    __syncthreads();

    float s = 0.f;
    for (int n = tid; n < NN; n += 256) { float e = __expf(sim[n] - mx); sim[n] = e; s += e; }
    red[tid] = s; __syncthreads();
    for (int o = 128; o > 0; o >>= 1) { if (tid < o) red[tid] += red[tid+o]; __syncthreads(); }
    const float inv = 1.f / red[0];
    __syncthreads();

    const int g = tid >> 6, dd = tid & 63;
    float a = 0.f;
    for (int n = g; n < NN; n += 4)
        a += sim[n] * qkv[(size_t)(b * NN + n) * N_QKV + 2 * CC + h * DD + dd];
    accred[g * DD + dd] = a;
    __syncthreads();
    if (tid < DD)
        preout[(size_t)(b * NN) * CC + h * DD + tid] =
            f2tf((accred[tid] + accred[DD + tid] + accred[2*DD + tid] + accred[3*DD + tid]) * inv);
}

// =============================================================
// Space attention v5: K/V-resident blocks + cp.async Q pipeline.
// xd writes tf32-rounded (feeds q2 GEMM A).
// =============================================================
#define SA_KLD 68
#define SA_QLD 68
#define VT_LD  212
#define SC_LD  212
#define SA_KOFF  0
#define SA_VTOFF 14144
#define SA_QOFF  27712
#define SA_QBUF  4352
#define SA_SCOFF 36416
#define SA_FLOATS 49984
#define SA_SMEM (SA_FLOATS * 4)          // 199936 B

__global__ __launch_bounds__(256)
void space_attn_kernel(const float* __restrict__ qkv, float* __restrict__ xt,
                       float* __restrict__ xd)
{
    extern __shared__ float sm[];
    float* Ksm = sm + SA_KOFF;
    float* Vt  = sm + SA_VTOFF;
    float* Qb  = sm + SA_QOFF;
    float* Sc  = sm + SA_SCOFF;

    const int qhalf = blockIdx.x;
    const int f  = blockIdx.y;
    const int bh = blockIdx.z;
    const int b  = bh / HH, h = bh % HH;
    const int tid = threadIdx.x;
    const int w = tid >> 5, lane = tid & 31;
    const int niters = qhalf ? 12 : 13;
    const int qt0 = qhalf * 13;

    for (int i = tid; i < 208 * 16; i += 256) {
        int r = i >> 4, c4 = i & 15;
        if (r < 196) {
            size_t base = (size_t)(b * NN + 1 + f * PP + r) * N_QKV + h * DD + c4 * 4;
            *reinterpret_cast<float4*>(&Ksm[r * SA_KLD + c4 * 4]) =
                *reinterpret_cast<const float4*>(qkv + base + CC);
            float4 vv = *reinterpret_cast<const float4*>(qkv + base + 2 * CC);
            Vt[(4 * c4 + 0) * VT_LD + r] = vv.x;
            Vt[(4 * c4 + 1) * VT_LD + r] = vv.y;
            Vt[(4 * c4 + 2) * VT_LD + r] = vv.z;
            Vt[(4 * c4 + 3) * VT_LD + r] = vv.w;
        } else {
            *reinterpret_cast<float4*>(&Ksm[r * SA_KLD + c4 * 4]) = make_float4(0.f,0.f,0.f,0.f);
        }
    }
    for (int i = tid; i < 64 * 16; i += 256) {
        int rr = i >> 4, p = 196 + (i & 15);
        Vt[rr * VT_LD + p] = 0.f;
        Sc[rr * SC_LD + p] = 0.f;
    }

    const uint32_t smbase = smem_u32(sm);
    auto issue_q = [&](int it, int buf) {
        const int q0 = (qt0 + it) * 64;
#pragma unroll
        for (int k = 0; k < 4; k++) {
            int i = tid + k * 256;
            int r = i >> 4, c4 = i & 15;
            int sq = q0 + r;
            int valid = (sq < SS);
            int sqc = valid ? sq : (SS - 1);
            const float* gp = qkv + (size_t)(b * NN + 1 + sqc) * N_QKV + h * DD + c4 * 4;
            uint32_t sa = smbase + (SA_QOFF + buf * SA_QBUF + r * SA_QLD + c4 * 4) * 4;
            cp_async16(sa, gp, valid ? 16 : 0);
        }
        CP_COMMIT();
    };

    issue_q(0, 0);

    for (int it = 0; it < niters; it++) {
        const int buf = it & 1;
        const int q0 = (qt0 + it) * 64;
        const float* Qsm = Qb + buf * SA_QBUF;

        CP_WAIT(0);
        __syncthreads();

        if (it + 1 < niters) issue_q(it + 1, buf ^ 1);

        // phase 1: S = Q @ K^T; warp tile 16m x 104n
        const int mrow1  = (w >> 1) * 16;
        const int nbase1 = (w & 1) * 104;
        float acc[13][4];
#pragma unroll
        for (int nt = 0; nt < 13; nt++)
#pragma unroll
            for (int r = 0; r < 4; r++) acc[nt][r] = 0.f;

#pragma unroll
        for (int kb = 0; kb < 64; kb += 8) {
            uint32_t af[4];
            const float* ab = &Qsm[(mrow1 + (lane >> 2)) * SA_QLD + kb + (lane & 3)];
            af[0] = __float_as_uint(ab[0]);
            af[1] = __float_as_uint(ab[8 * SA_QLD]);
            af[2] = __float_as_uint(ab[4]);
            af[3] = __float_as_uint(ab[8 * SA_QLD + 4]);
#pragma unroll
            for (int nt = 0; nt < 13; nt++) {
                uint32_t bfr[2];
                const float* bb = &Ksm[(nbase1 + nt * 8 + (lane >> 2)) * SA_KLD + kb + (lane & 3)];
                bfr[0] = __float_as_uint(bb[0]);
                bfr[1] = __float_as_uint(bb[4]);
                mma_tf32(acc[nt], af, bfr);
            }
        }

        {
            const int r0 = mrow1 + (lane >> 2);
#pragma unroll
            for (int nt = 0; nt < 13; nt++) {
                int col = nbase1 + nt * 8 + (lane & 3) * 2;
                if (col < 196) {
                    Sc[r0 * SC_LD + col]       = acc[nt][0] * SCALE;
                    Sc[r0 * SC_LD + col + 1]   = acc[nt][1] * SCALE;
                    Sc[(r0 + 8) * SC_LD + col]     = acc[nt][2] * SCALE;
                    Sc[(r0 + 8) * SC_LD + col + 1] = acc[nt][3] * SCALE;
                }
            }
        }
        __syncthreads();

        // phase 2: softmax
#pragma unroll
        for (int qi = 0; qi < 8; qi++) {
            const int q = w * 8 + qi;
            float v[7];
            float mx = -1e30f;
#pragma unroll
            for (int j = 0; j < 7; j++) {
                int p = lane + 32 * j;
                v[j] = (p < 196) ? Sc[q * SC_LD + p] : -1e30f;
                mx = fmaxf(mx, v[j]);
            }
#pragma unroll
            for (int o = 16; o > 0; o >>= 1) mx = fmaxf(mx, __shfl_xor_sync(0xffffffffu, mx, o));
            float sum = 0.f;
#pragma unroll
            for (int j = 0; j < 7; j++) {
                int p = lane + 32 * j;
                float e = (p < 196) ? __expf(v[j] - mx) : 0.f;
                v[j] = e; sum += e;
            }
#pragma unroll
            for (int o = 16; o > 0; o >>= 1) sum += __shfl_xor_sync(0xffffffffu, sum, o);
            float inv = 1.f / sum;
#pragma unroll
            for (int j = 0; j < 7; j++) {
                int p = lane + 32 * j;
                if (p < 196) Sc[q * SC_LD + p] = f2tf(v[j] * inv);
            }
        }
        __syncthreads();

        // phase 3: out = Sc @ Vt^T; warp tile 16m x 32n
        {
            const int m3  = (w >> 1) * 16;
            const int nb3 = (w & 1) * 32;
            float o2[4][4];
#pragma unroll
            for (int j = 0; j < 4; j++)
#pragma unroll
                for (int r = 0; r < 4; r++) o2[j][r] = 0.f;

#pragma unroll
            for (int kb = 0; kb < 208; kb += 8) {
                uint32_t af[4];
                const float* ab = &Sc[(m3 + (lane >> 2)) * SC_LD + kb + (lane & 3)];
                af[0] = __float_as_uint(ab[0]);
                af[1] = __float_as_uint(ab[8 * SC_LD]);
                af[2] = __float_as_uint(ab[4]);
                af[3] = __float_as_uint(ab[8 * SC_LD + 4]);
#pragma unroll
                for (int j = 0; j < 4; j++) {
                    uint32_t bfr[2];
                    const float* bb = &Vt[(nb3 + j * 8 + (lane >> 2)) * VT_LD + kb + (lane & 3)];
                    bfr[0] = __float_as_uint(bb[0]);
                    bfr[1] = __float_as_uint(bb[4]);
                    mma_tf32(o2[j], af, bfr);
                }
            }

            const int r0 = m3 + (lane >> 2);
#pragma unroll
            for (int hh2 = 0; hh2 < 2; hh2++) {
                const int sq = q0 + r0 + hh2 * 8;
                if (sq < SS) {
                    float* xp = xt + ((size_t)(b * SS + sq) * FF + f) * CC + h * DD;
                    const bool diag = (sq / PP == f);
                    float* dp = xd + (size_t)(b * SS + sq) * CC + h * DD;
#pragma unroll
                    for (int j = 0; j < 4; j++) {
                        const int dv = nb3 + j * 8 + (lane & 3) * 2;
                        float2 r;
                        r.x = o2[j][hh2 * 2 + 0];
                        r.y = o2[j][hh2 * 2 + 1];
                        *reinterpret_cast<float2*>(xp + dv) = r;
                        if (diag) {
                            float2 rr = make_float2(f2tf(r.x), f2tf(r.y));
                            *reinterpret_cast<float2*>(dp + dv) = rr;
                        }
                    }
                }
            }
        }
        __syncthreads();
    }
}

// =============================================================
// gemm_G tf32: per head h, G[m,c] = sum_k q2[m,h64+k]*wkv[c,h64+k]
// q2 & w_kv pre-rounded -> plain vector fills.
// =============================================================
__global__ __launch_bounds__(256)
void gemm_G_tf32(const float* __restrict__ q2, const float* __restrict__ wkv,
                 float* __restrict__ G)
{
    __shared__ float As[128 * 68];
    __shared__ float Bs[128 * 68];

    const int mt = blockIdx.x, ct = blockIdx.y, h = blockIdx.z;
    const int tid = threadIdx.x;
    const int lane = tid & 31;
    const int w = tid >> 5;

    for (int i = tid; i < 128 * 16; i += 256) {
        int r = i >> 4, c4 = i & 15;
        *reinterpret_cast<float4*>(&As[r * 68 + 4 * c4]) =
            *reinterpret_cast<const float4*>(q2 + (size_t)(mt * 128 + r) * CC + h * DD + 4 * c4);
        *reinterpret_cast<float4*>(&Bs[r * 68 + 4 * c4]) =
            *reinterpret_cast<const float4*>(wkv + (size_t)(ct * 128 + r) * (2 * CC) + h * DD + 4 * c4);
    }
    __syncthreads();

    const int wm = (w >> 2) * 64;
    const int wn = (w & 3) * 32;

    float acc[4][4][4];
#pragma unroll
    for (int i = 0; i < 4; i++)
#pragma unroll
        for (int j = 0; j < 4; j++)
#pragma unroll
            for (int r = 0; r < 4; r++) acc[i][j][r] = 0.f;

#pragma unroll
    for (int kb = 0; kb < 64; kb += 8) {
        uint32_t af[4][4], bf[4][2];
#pragma unroll
        for (int i = 0; i < 4; i++) {
            const float* base = &As[(wm + i * 16 + (lane >> 2)) * 68 + kb + (lane & 3)];
            af[i][0] = __float_as_uint(base[0]);
            af[i][1] = __float_as_uint(base[8 * 68]);
            af[i][2] = __float_as_uint(base[4]);
            af[i][3] = __float_as_uint(base[8 * 68 + 4]);
        }
#pragma unroll
        for (int j = 0; j < 4; j++) {
            const float* base = &Bs[(wn + j * 8 + (lane >> 2)) * 68 + kb + (lane & 3)];
            bf[j][0] = __float_as_uint(base[0]);
            bf[j][1] = __float_as_uint(base[4]);
        }
#pragma unroll
        for (int i = 0; i < 4; i++)
#pragma unroll
            for (int j = 0; j < 4; j++)
                mma_tf32(acc[i][j], af[i], bf[j]);
    }

#pragma unroll
    for (int i = 0; i < 4; i++) {
        const int rbase = mt * 128 + wm + i * 16 + (lane >> 2);
#pragma unroll
        for (int hh2 = 0; hh2 < 2; hh2++) {
            const size_t row = rbase + hh2 * 8;
            float* gp = G + (row * HH + h) * CC + ct * 128;
#pragma unroll
            for (int j = 0; j < 4; j++) {
                const int col = wn + j * 8 + (lane & 3) * 2;
                float2 r;
                r.x = acc[i][j][hh2 * 2 + 0];
                r.y = acc[i][j][hh2 * 2 + 1];
                *reinterpret_cast<float2*>(gp + col) = r;
            }
        }
    }
}

// =============================================================
// Per (b,s): scores(12x8), softmax over f, weighted sum.
// preout writes tf32-rounded (feeds proj GEMM A).
// =============================================================
#define SO_SMEM ((FF*CC + HH*CC + 96 + 96) * 4)

__global__ __launch_bounds__(256)
void score_out_kernel(const float* __restrict__ xt, const float* __restrict__ G,
                      float* __restrict__ preout, float* __restrict__ attn2)
{
    extern __shared__ float sm[];
    float* xts = sm;
    float* Gs  = xts + FF * CC;
    float* sc  = Gs + HH * CC;
    float* pr  = sc + 96;

    const int bs = blockIdx.x;
    const int b = bs / SS, s = bs % SS;
    const int tid = threadIdx.x;

    for (int i = tid; i < FF * CC / 4; i += 256)
        reinterpret_cast<float4*>(xts)[i] = reinterpret_cast<const float4*>(xt)[(size_t)bs * (FF * CC / 4) + i];
    for (int i = tid; i < HH * CC / 4; i += 256)
        reinterpret_cast<float4*>(Gs)[i] = reinterpret_cast<const float4*>(G)[(size_t)bs * (HH * CC / 4) + i];
    __syncthreads();

    const int w = tid >> 5, l = tid & 31;
    for (int idx = w; idx < 96; idx += 8) {
        int h = idx >> 3, f = idx & 7;
        const float4* gp = reinterpret_cast<const float4*>(Gs + h * CC);
        const float4* xp = reinterpret_cast<const float4*>(xts + f * CC);
        float part = 0.f;
#pragma unroll
        for (int c4 = l; c4 < CC / 4; c4 += 32) {
            float4 g = gp[c4], x = xp[c4];
            part += g.x*x.x + g.y*x.y + g.z*x.z + g.w*x.w;
        }
#pragma unroll
        for (int o = 16; o > 0; o >>= 1) part += __shfl_xor_sync(0xffffffffu, part, o);
        if (l == 0) sc[idx] = part;
    }
    __syncthreads();

    if (tid < HH) {
        int h = tid;
        float mx = -1e30f;
#pragma unroll
        for (int f = 0; f < FF; f++) mx = fmaxf(mx, sc[h * 8 + f]);
        float sum = 0.f;
        float e[FF];
#pragma unroll
        for (int f = 0; f < FF; f++) { e[f] = __expf(sc[h * 8 + f] - mx); sum += e[f]; }
        float inv = 1.f / sum;
#pragma unroll
        for (int f = 0; f < FF; f++) {
            float p = e[f] * inv;
            pr[h * 8 + f] = p;
            attn2[((size_t)(b * HH + h) * SS + s) * FF + f] = p;
        }
    }
    __syncthreads();

    for (int c = tid; c < CC; c += 256) {
        int h = c >> 6;
        float v = 0.f;
#pragma unroll
        for (int f = 0; f < FF; f++) v += pr[h * 8 + f] * xts[f * CC + c];
        preout[(size_t)(b * NN + 1 + s) * CC + c] = f2tf(v);
    }
}

// =============================================================
// host launch
// =============================================================
extern "C" void kernel_launch(void* const* d_in, const int* in_sizes, int n_in,
                              void* d_out, int out_size)
{
    const float* x      = (const float*)d_in[0];
    const float* w_qkv  = (const float*)d_in[1];
    const float* w_q    = (const float*)d_in[2];
    const float* w_kv   = (const float*)d_in[3];
    const float* w_proj = (const float*)d_in[4];
    const float* b_proj = (const float*)d_in[5];

    float *p_qkv, *p_xt, *p_xd, *p_q2, *p_G, *p_pre;
    float *p_xr, *p_wqkvr, *p_wqr, *p_wkvr, *p_wprojr;
    cudaGetSymbolAddress((void**)&p_qkv, g_qkv);
    cudaGetSymbolAddress((void**)&p_xt,  g_xt);
    cudaGetSymbolAddress((void**)&p_xd,  g_xd);
    cudaGetSymbolAddress((void**)&p_q2,  g_q2);
    cudaGetSymbolAddress((void**)&p_G,   g_G);
    cudaGetSymbolAddress((void**)&p_pre, g_pre);
    cudaGetSymbolAddress((void**)&p_xr,     g_xr);
    cudaGetSymbolAddress((void**)&p_wqkvr,  g_wqkvr);
    cudaGetSymbolAddress((void**)&p_wqr,    g_wqr);
    cudaGetSymbolAddress((void**)&p_wkvr,   g_wkvr);
    cudaGetSymbolAddress((void**)&p_wprojr, g_wprojr);

    cudaFuncSetAttribute((const void*)gemm_tf32<false, true>,  cudaFuncAttributeMaxDynamicSharedMemorySize, GT_SMEM);
    cudaFuncSetAttribute((const void*)gemm_tf32<true,  false>, cudaFuncAttributeMaxDynamicSharedMemorySize, GT_SMEM);
    cudaFuncSetAttribute(space_attn_kernel, cudaFuncAttributeMaxDynamicSharedMemorySize, SA_SMEM);
    cudaFuncSetAttribute(score_out_kernel,  cudaFuncAttributeMaxDynamicSharedMemorySize, SO_SMEM);

    float* outp  = (float*)d_out;
    float* attn2 = outp + OUT_ELEMS;

    // 0) tf32-round all GEMM inputs once
    {
        int n;
        n = (M_QKV * CC) / 4;      round_copy<<<(n+255)/256, 256>>>(x,      p_xr,     n);
        n = (CC * 3 * CC) / 4;     round_copy<<<(n+255)/256, 256>>>(w_qkv,  p_wqkvr,  n);
        n = (CC * CC) / 4;         round_copy<<<(n+255)/256, 256>>>(w_q,    p_wqr,    n);
        n = (CC * 2 * CC) / 4;     round_copy<<<(n+255)/256, 256>>>(w_kv,   p_wkvr,   n);
        n = (CC * CC) / 4;         round_copy<<<(n+255)/256, 256>>>(w_proj, p_wprojr, n);
    }

    // 1) qkv = x @ w_qkv (tf32, output rounded)
    gemm_tf32<false, true><<<dim3(N_QKV/128, (M_QKV+127)/128), 256, GT_SMEM>>>(
        p_xr, p_wqkvr, p_qkv, nullptr, M_QKV, N_QKV, CC, CC, N_QKV, N_QKV, 1.f);

    // 2) cls attention -> preout row n=0 (rounded)
    cls_attn_kernel<<<BATCH*HH, 256>>>(p_qkv, p_pre);

    // 3) fused space attention (K/V resident) -> xt, xd(rounded)
    space_attn_kernel<<<dim3(2, FF, BATCH*HH), 256, SA_SMEM>>>(p_qkv, p_xt, p_xd);

    // 4) q2 = scale * x_diag @ w_q (tf32, output rounded)
    gemm_tf32<false, true><<<dim3(CC/128, M_S/128), 256, GT_SMEM>>>(
        p_xd, p_wqr, p_q2, nullptr, M_S, CC, CC, CC, CC, CC, SCALE);

    // 5) G = per-head q2 @ Wk_h^T
    gemm_G_tf32<<<dim3(M_S/128, CC/128, HH), 256>>>(p_q2, p_wkvr, p_G);

    // 6) scores + softmax(F) -> attn2; weighted xt -> preout (rounded)
    score_out_kernel<<<M_S, 256, SO_SMEM>>>(p_xt, p_G, p_pre, attn2);

    // 7) out = preout @ w_proj + b_proj (full-precision output)
    gemm_tf32<true, false><<<dim3(CC/128, (M_QKV+127)/128), 256, GT_SMEM>>>(
        p_pre, p_wprojr, outp, b_proj, M_QKV, CC, CC, CC, CC, CC, 1.f);
}